// round 1
// baseline (speedup 1.0000x reference)
#include <cuda_runtime.h>
#include <cuda_bf16.h>
#include <cstddef>

// Problem constants
#define BB   16
#define CC   512
#define NN   4096
#define NH   8
#define HD   64
#define EPS  1e-6f

// Scratch (device globals: allocation-free rule)
__device__ float g_qk[(size_t)BB * 2 * CC * NN];   // [B][1024][4096] relu(qk)
__device__ float g_v [(size_t)BB * CC * NN];       // [B][512][4096] v, later reused as attn
__device__ float g_kvp[(size_t)8 * 128 * 65 * 64]; // split-K partials for kv
__device__ float g_kv [(size_t)128 * 65 * 64];     // [B*nh][65][64]

// ---------------------------------------------------------------------------
// Projection GEMM: Y[O,N] = W[O,C] @ X[C,N] per batch (blockIdx.z)
// 128x128 block tile, BK=8, 256 threads, 8x8 per thread.
// ADD_POS: X := x + pos ; RELU: applied at store.
// ---------------------------------------------------------------------------
template<bool ADD_POS, bool RELU>
__global__ __launch_bounds__(256) void proj_kernel(
    const float* __restrict__ W, const float* __restrict__ X,
    const float* __restrict__ P, float* __restrict__ Y, int O)
{
    __shared__ float As[8][128];   // W tile, transposed: As[k][o]
    __shared__ float Bs[8][132];   // X tile: Bs[k][n], padded (132*4B = 16B mult)

    const int tid = threadIdx.x;
    const int bz  = blockIdx.z;
    const int n0  = blockIdx.x * 128;
    const int o0  = blockIdx.y * 128;

    const float* Xb = X + (size_t)bz * CC * NN;
    const float* Pb = ADD_POS ? (P + (size_t)bz * CC * NN) : nullptr;
    float*       Yb = Y + (size_t)bz * O * NN;

    const int tx = tid & 15;       // n dimension
    const int ty = tid >> 4;       // o dimension

    float acc[8][8];
    #pragma unroll
    for (int i = 0; i < 8; i++)
        #pragma unroll
        for (int j = 0; j < 8; j++) acc[i][j] = 0.f;

    const int wlo = tid >> 1;            // 0..127 (o within tile)
    const int wlk = (tid & 1) * 4;       // 0 or 4 (k within tile)
    const int xlk = tid >> 5;            // 0..7  (k within tile)
    const int xln = (tid & 31) * 4;      // 0..124 (n within tile)

    for (int kt = 0; kt < CC; kt += 8) {
        float4 w4 = *(const float4*)&W[(size_t)(o0 + wlo) * CC + kt + wlk];
        float4 x4 = *(const float4*)&Xb[(size_t)(kt + xlk) * NN + n0 + xln];
        if (ADD_POS) {
            float4 p4 = *(const float4*)&Pb[(size_t)(kt + xlk) * NN + n0 + xln];
            x4.x += p4.x; x4.y += p4.y; x4.z += p4.z; x4.w += p4.w;
        }
        As[wlk + 0][wlo] = w4.x;
        As[wlk + 1][wlo] = w4.y;
        As[wlk + 2][wlo] = w4.z;
        As[wlk + 3][wlo] = w4.w;
        *(float4*)&Bs[xlk][xln] = x4;
        __syncthreads();

        #pragma unroll
        for (int k = 0; k < 8; k++) {
            float a[8], b[8];
            *(float4*)&a[0] = *(const float4*)&As[k][ty * 8];
            *(float4*)&a[4] = *(const float4*)&As[k][ty * 8 + 4];
            *(float4*)&b[0] = *(const float4*)&Bs[k][tx * 8];
            *(float4*)&b[4] = *(const float4*)&Bs[k][tx * 8 + 4];
            #pragma unroll
            for (int i = 0; i < 8; i++)
                #pragma unroll
                for (int j = 0; j < 8; j++)
                    acc[i][j] = fmaf(a[i], b[j], acc[i][j]);
        }
        __syncthreads();
    }

    #pragma unroll
    for (int i = 0; i < 8; i++) {
        size_t row = (size_t)(o0 + ty * 8 + i) * NN + n0 + tx * 8;
        if (RELU) {
            #pragma unroll
            for (int j = 0; j < 8; j++) acc[i][j] = fmaxf(acc[i][j], 0.f);
        }
        *(float4*)&Yb[row]     = *(float4*)&acc[i][0];
        *(float4*)&Yb[row + 4] = *(float4*)&acc[i][4];
    }
}

// ---------------------------------------------------------------------------
// kv[e,d] = sum_n v_pad[e,n] * k[d,n]  per (b,h); split-K over 8 chunks of 512
// grid (8, 128), 256 threads. Writes deterministic partials (no atomics).
// ---------------------------------------------------------------------------
__global__ __launch_bounds__(256) void kv_kernel(
    const float* __restrict__ qk, const float* __restrict__ v,
    float* __restrict__ kvp)
{
    __shared__ float ks[64][68];
    __shared__ float vs[64][68];

    const int tid   = threadIdx.x;
    const int chunk = blockIdx.x;           // 0..7
    const int bh    = blockIdx.y;           // 0..127
    const int b = bh >> 3, h = bh & 7;

    const float* kbase = qk + (size_t)b * 2 * CC * NN + (size_t)(CC + h * HD) * NN;
    const float* vbase = v  + (size_t)b * CC * NN     + (size_t)(h * HD) * NN;

    const int d  = tid & 63;
    const int eg = tid >> 6;                // 0..3, covers e = eg*16 .. +15

    float acc[16];
    #pragma unroll
    for (int i = 0; i < 16; i++) acc[i] = 0.f;
    float ksum = 0.f;

    for (int sub = 0; sub < 8; sub++) {
        const int n0 = chunk * 512 + sub * 64;
        #pragma unroll
        for (int r = 0; r < 4; r++) {
            int idx = tid + r * 256;
            int row = idx >> 4;
            int col = (idx & 15) * 4;
            *(float4*)&ks[row][col] = *(const float4*)&kbase[(size_t)row * NN + n0 + col];
            *(float4*)&vs[row][col] = *(const float4*)&vbase[(size_t)row * NN + n0 + col];
        }
        __syncthreads();

        const float4* krow = (const float4*)&ks[d][0];
        #pragma unroll
        for (int n4 = 0; n4 < 16; n4++) {
            float4 kk = krow[n4];
            if (eg == 0) ksum += kk.x + kk.y + kk.z + kk.w;
            #pragma unroll
            for (int i = 0; i < 16; i++) {
                float4 vv = *(const float4*)&vs[eg * 16 + i][n4 * 4];
                acc[i] = fmaf(kk.x, vv.x, acc[i]);
                acc[i] = fmaf(kk.y, vv.y, acc[i]);
                acc[i] = fmaf(kk.z, vv.z, acc[i]);
                acc[i] = fmaf(kk.w, vv.w, acc[i]);
            }
        }
        __syncthreads();
    }

    float* outb = kvp + (size_t)chunk * (128 * 4160) + (size_t)bh * 4160;
    #pragma unroll
    for (int i = 0; i < 16; i++)
        outb[(eg * 16 + i) * 64 + d] = acc[i];
    if (eg == 0)
        outb[64 * 64 + d] = ksum;           // e = 64 row: sum of k (ones row of v_pad)
}

__global__ void kv_reduce(const float* __restrict__ kvp, float* __restrict__ kvout)
{
    int i = blockIdx.x * 256 + threadIdx.x;
    if (i < 128 * 4160) {
        float s = 0.f;
        #pragma unroll
        for (int c = 0; c < 8; c++) s += kvp[(size_t)c * (128 * 4160) + i];
        kvout[i] = s;
    }
}

// ---------------------------------------------------------------------------
// out[e,n] = sum_d kv[e,d]*q[d,n]; attn[e,n] = out[e,n]/(out[64,n]+EPS)
// grid (N/64, 128), 256 threads (16x16), 4x4 micro-tile (e x n).
// ---------------------------------------------------------------------------
__global__ __launch_bounds__(256) void attn_kernel(
    const float* __restrict__ qk, const float* __restrict__ kv,
    float* __restrict__ attn)
{
    __shared__ float kvs[65 * 64];
    __shared__ float qs[16][68];
    __shared__ float dens[64];

    const int tid = threadIdx.x;
    const int bh  = blockIdx.y;
    const int b = bh >> 3, h = bh & 7;
    const int n0 = blockIdx.x * 64;

    for (int i = tid; i < 65 * 64; i += 256)
        kvs[i] = kv[(size_t)bh * 4160 + i];

    const int tx = tid & 15;     // n
    const int ty = tid >> 4;     // e
    const int ld = tid >> 4;     // d for q staging
    const int ln = (tid & 15) * 4;

    float acc[4][4] = {};
    float dacc[4] = {0.f, 0.f, 0.f, 0.f};

    const float* qbase = qk + (size_t)b * 2 * CC * NN + (size_t)(h * HD) * NN + n0;

    __syncthreads();

    for (int dt = 0; dt < 64; dt += 16) {
        *(float4*)&qs[ld][ln] = *(const float4*)&qbase[(size_t)(dt + ld) * NN + ln];
        __syncthreads();
        #pragma unroll
        for (int dd = 0; dd < 16; dd++) {
            const int d = dt + dd;
            float4 qv = *(const float4*)&qs[dd][tx * 4];
            #pragma unroll
            for (int i = 0; i < 4; i++) {
                float a = kvs[(ty * 4 + i) * 64 + d];
                acc[i][0] = fmaf(a, qv.x, acc[i][0]);
                acc[i][1] = fmaf(a, qv.y, acc[i][1]);
                acc[i][2] = fmaf(a, qv.z, acc[i][2]);
                acc[i][3] = fmaf(a, qv.w, acc[i][3]);
            }
            if (ty == 0) {
                float a = kvs[64 * 64 + d];
                dacc[0] = fmaf(a, qv.x, dacc[0]);
                dacc[1] = fmaf(a, qv.y, dacc[1]);
                dacc[2] = fmaf(a, qv.z, dacc[2]);
                dacc[3] = fmaf(a, qv.w, dacc[3]);
            }
        }
        __syncthreads();
    }

    if (ty == 0) {
        dens[tx * 4 + 0] = dacc[0];
        dens[tx * 4 + 1] = dacc[1];
        dens[tx * 4 + 2] = dacc[2];
        dens[tx * 4 + 3] = dacc[3];
    }
    __syncthreads();

    float inv0 = 1.f / (dens[tx * 4 + 0] + EPS);
    float inv1 = 1.f / (dens[tx * 4 + 1] + EPS);
    float inv2 = 1.f / (dens[tx * 4 + 2] + EPS);
    float inv3 = 1.f / (dens[tx * 4 + 3] + EPS);

    float* ab = attn + (size_t)b * CC * NN + (size_t)(h * HD) * NN + n0 + tx * 4;
    #pragma unroll
    for (int i = 0; i < 4; i++) {
        float4 o;
        o.x = acc[i][0] * inv0;
        o.y = acc[i][1] * inv1;
        o.z = acc[i][2] * inv2;
        o.w = acc[i][3] * inv3;
        *(float4*)&ab[(size_t)(ty * 4 + i) * NN] = o;
    }
}

// ---------------------------------------------------------------------------
extern "C" void kernel_launch(void* const* d_in, const int* in_sizes, int n_in,
                              void* d_out, int out_size)
{
    const float* x    = (const float*)d_in[0];
    const float* pos  = (const float*)d_in[1];
    const float* w_qk = (const float*)d_in[2];
    const float* w_v  = (const float*)d_in[3];
    const float* w_o  = (const float*)d_in[4];
    float* out = (float*)d_out;

    float *qk, *v, *kvp, *kv;
    cudaGetSymbolAddress((void**)&qk,  g_qk);
    cudaGetSymbolAddress((void**)&v,   g_v);
    cudaGetSymbolAddress((void**)&kvp, g_kvp);
    cudaGetSymbolAddress((void**)&kv,  g_kv);

    // 1) qk = relu(w_qk @ (x + pos))   [B][1024][N]
    proj_kernel<true, true><<<dim3(NN / 128, 1024 / 128, BB), 256>>>(w_qk, x, pos, qk, 1024);
    // 2) v = w_v @ x                   [B][512][N]
    proj_kernel<false, false><<<dim3(NN / 128, 512 / 128, BB), 256>>>(w_v, x, nullptr, v, 512);
    // 3) kv partials + reduce          [128][65][64]
    kv_kernel<<<dim3(8, 128), 256>>>(qk, v, kvp);
    kv_reduce<<<(128 * 4160 + 255) / 256, 256>>>(kvp, kv);
    // 4) attn = normalize(kv @ q)      (reuses g_v as output)
    attn_kernel<<<dim3(NN / 64, 128), 256>>>(qk, kv, v);
    // 5) out = w_o @ attn
    proj_kernel<false, false><<<dim3(NN / 128, 512 / 128, BB), 256>>>(w_o, v, nullptr, out, 512);
}

// round 3
// speedup vs baseline: 2.3634x; 2.3634x over previous
#include <cuda_runtime.h>
#include <cuda_bf16.h>
#include <cstdint>
#include <cstddef>

// Problem constants
#define BB   16
#define CC   512
#define NN   4096
#define NH   8
#define HD   64
#define EPS  1e-6f

// ---------------------------------------------------------------------------
// Scratch (device globals: allocation-free rule)
// ---------------------------------------------------------------------------
__device__ float g_qk[(size_t)BB * 2 * CC * NN];   // [B][1024][4096] relu(qk) fp32
__device__ float g_v [(size_t)BB * CC * NN];       // [B][512][4096] v, later reused as attn out
__device__ float g_kvp[(size_t)8 * 128 * 65 * 64]; // split-K partials for kv
__device__ float g_kv [(size_t)128 * 65 * 64];     // [B*nh][65][64]

// bf16 hi/lo operands, B operand layout [B][N][C] (K-major rows of length C)
__device__ __nv_bfloat16 g_xq_hi[(size_t)BB * NN * CC];
__device__ __nv_bfloat16 g_xq_lo[(size_t)BB * NN * CC];
__device__ __nv_bfloat16 g_xv_hi[(size_t)BB * NN * CC];
__device__ __nv_bfloat16 g_xv_lo[(size_t)BB * NN * CC];
__device__ __nv_bfloat16 g_ao_hi[(size_t)BB * NN * CC];
__device__ __nv_bfloat16 g_ao_lo[(size_t)BB * NN * CC];
// weights hi/lo, [O][C] row-major (K-major)
__device__ __nv_bfloat16 g_wqk_hi[1024 * 512];
__device__ __nv_bfloat16 g_wqk_lo[1024 * 512];
__device__ __nv_bfloat16 g_wv_hi [512 * 512];
__device__ __nv_bfloat16 g_wv_lo [512 * 512];
__device__ __nv_bfloat16 g_wo_hi [512 * 512];
__device__ __nv_bfloat16 g_wo_lo [512 * 512];

// ---------------------------------------------------------------------------
// Helpers
// ---------------------------------------------------------------------------
__device__ __forceinline__ uint32_t smem_u32(const void* p) {
    uint32_t a;
    asm("{ .reg .u64 t; cvta.to.shared.u64 t, %1; cvt.u32.u64 %0, t; }" : "=r"(a) : "l"(p));
    return a;
}
#define SWZ128(off) ((off) ^ (((off) >> 3) & 0x70))

__device__ __forceinline__ void cp_async16(uint32_t s, const void* g) {
    asm volatile("cp.async.cg.shared.global [%0], [%1], 16;" :: "r"(s), "l"(g));
}
#define CP_COMMIT() asm volatile("cp.async.commit_group;" ::: "memory")
#define CP_WAIT(n)  asm volatile("cp.async.wait_group %0;" :: "n"(n) : "memory")

__device__ __forceinline__ void ldmatrix_x4(uint32_t* r, uint32_t addr) {
    asm volatile("ldmatrix.sync.aligned.m8n8.x4.shared.b16 {%0,%1,%2,%3}, [%4];"
                 : "=r"(r[0]), "=r"(r[1]), "=r"(r[2]), "=r"(r[3]) : "r"(addr));
}
__device__ __forceinline__ void mma_bf16(float* d, const uint32_t* a, const uint32_t* b) {
    asm volatile(
        "mma.sync.aligned.m16n8k16.row.col.f32.bf16.bf16.f32 "
        "{%0,%1,%2,%3}, {%4,%5,%6,%7}, {%8,%9}, {%0,%1,%2,%3};"
        : "+f"(d[0]), "+f"(d[1]), "+f"(d[2]), "+f"(d[3])
        : "r"(a[0]), "r"(a[1]), "r"(a[2]), "r"(a[3]), "r"(b[0]), "r"(b[1]));
}

// ---------------------------------------------------------------------------
// Tensor-core projection GEMM:  Y[O,N] = W[O,C] @ X[C,N] per batch.
// A = W hi/lo [O][C] bf16 K-major; B = Xt hi/lo [N][C] bf16 K-major.
// 3-term split as virtual K=1536 (segments: hi*hi, hi*lo, lo*hi).
// BM=128, BN=256, BK=64, 512 threads (16 warps, warp tile 64x32), 3 stages.
// ---------------------------------------------------------------------------
#define BKB 128          // bytes per smem row (64 bf16)
#define A_STG 16384      // A tile bytes per stage
#define B_STG 32768      // B tile bytes per stage
#define STG   49152      // stage bytes
#define GEMM_SMEM (3 * STG)
#define NIT 24

template<bool RELU>
__global__ __launch_bounds__(512, 1) void gemm_tc(
    const __nv_bfloat16* __restrict__ Ahi, const __nv_bfloat16* __restrict__ Alo,
    const __nv_bfloat16* __restrict__ Bhi, const __nv_bfloat16* __restrict__ Blo,
    float* __restrict__ Y, int O)
{
    extern __shared__ __align__(1024) char smem[];
    const uint32_t sbase = smem_u32(smem);
    const int tid  = threadIdx.x;
    const int wid  = tid >> 5;
    const int lane = tid & 31;
    const int wm   = wid & 1;        // 2 m-warps
    const int wn   = wid >> 1;       // 8 n-warps

    const int n0 = blockIdx.x * 256;
    const int o0 = blockIdx.y * 128;
    const int bz = blockIdx.z;

    const __nv_bfloat16* Bhib = Bhi + (size_t)bz * NN * CC;
    const __nv_bfloat16* Blob = Blo + (size_t)bz * NN * CC;
    float* Yb = Y + (size_t)bz * O * NN;

    auto load_stage = [&](int it, int st) {
        const int seg = it >> 3;
        const __nv_bfloat16* Ap = (seg == 2) ? Alo : Ahi;
        const __nv_bfloat16* Bp = (seg == 1) ? Blob : Bhib;
        const int k0 = (it & 7) * 64;
        const uint32_t sb = sbase + st * STG;
        #pragma unroll
        for (int i = 0; i < 2; i++) {            // A: 128 rows x 128B
            int c = tid + i * 512;
            int row = c >> 3, cc = c & 7;
            cp_async16(sb + SWZ128(row * BKB + cc * 16),
                       Ap + (size_t)(o0 + row) * CC + k0 + cc * 8);
        }
        #pragma unroll
        for (int i = 0; i < 4; i++) {            // B: 256 rows x 128B
            int c = tid + i * 512;
            int row = c >> 3, cc = c & 7;
            cp_async16(sb + A_STG + SWZ128(row * BKB + cc * 16),
                       Bp + (size_t)(n0 + row) * CC + k0 + cc * 8);
        }
        CP_COMMIT();
    };

    float acc[4][4][4];
    #pragma unroll
    for (int mf = 0; mf < 4; mf++)
        #pragma unroll
        for (int nf = 0; nf < 4; nf++)
            #pragma unroll
            for (int e = 0; e < 4; e++) acc[mf][nf][e] = 0.f;

    load_stage(0, 0);
    load_stage(1, 1);
    CP_WAIT(1);
    __syncthreads();

    // precomputed per-lane ldmatrix offsets (within tile, pre-swizzle inputs)
    const int a_row  = wm * 64 + (lane & 15);
    const int a_coff = (lane >> 4) * 16;
    const int b_row  = wn * 32 + ((lane >> 4) << 3) + (lane & 7);
    const int b_coff = ((lane >> 3) & 1) * 16;

    for (int it = 0; it < NIT; it++) {
        const uint32_t sb = sbase + (it % 3) * STG;
        #pragma unroll
        for (int kk = 0; kk < 4; kk++) {
            uint32_t a[4][4];
            #pragma unroll
            for (int mf = 0; mf < 4; mf++)
                ldmatrix_x4(a[mf], sb + SWZ128((a_row + mf * 16) * BKB + kk * 32 + a_coff));
            uint32_t b[4][2];
            #pragma unroll
            for (int np = 0; np < 2; np++) {
                uint32_t r[4];
                ldmatrix_x4(r, sb + A_STG +
                            SWZ128((b_row + np * 16) * BKB + kk * 32 + b_coff));
                b[np * 2][0] = r[0];  b[np * 2][1] = r[1];
                b[np * 2 + 1][0] = r[2];  b[np * 2 + 1][1] = r[3];
            }
            #pragma unroll
            for (int mf = 0; mf < 4; mf++)
                #pragma unroll
                for (int nf = 0; nf < 4; nf++)
                    mma_bf16(acc[mf][nf], a[mf], b[nf]);
        }
        if (it + 2 < NIT) {
            load_stage(it + 2, (it + 2) % 3);
            CP_WAIT(1);
        } else {
            CP_WAIT(0);
        }
        __syncthreads();
    }

    // Epilogue: float2 stores, optional relu
    const int er = lane >> 2;
    const int ec = (lane & 3) * 2;
    #pragma unroll
    for (int mf = 0; mf < 4; mf++) {
        #pragma unroll
        for (int nf = 0; nf < 4; nf++) {
            const int orow = o0 + wm * 64 + mf * 16 + er;
            const int ocol = n0 + wn * 32 + nf * 8 + ec;
            float2 v0, v1;
            v0.x = acc[mf][nf][0]; v0.y = acc[mf][nf][1];
            v1.x = acc[mf][nf][2]; v1.y = acc[mf][nf][3];
            if (RELU) {
                v0.x = fmaxf(v0.x, 0.f); v0.y = fmaxf(v0.y, 0.f);
                v1.x = fmaxf(v1.x, 0.f); v1.y = fmaxf(v1.y, 0.f);
            }
            *(float2*)&Yb[(size_t)orow * NN + ocol]       = v0;
            *(float2*)&Yb[(size_t)(orow + 8) * NN + ocol] = v1;
        }
    }
}

// ---------------------------------------------------------------------------
// Weight split: fp32 -> bf16 hi/lo, same layout
// ---------------------------------------------------------------------------
__global__ void conv_w_kernel(const float* __restrict__ in,
                              __nv_bfloat16* __restrict__ hi,
                              __nv_bfloat16* __restrict__ lo, int n)
{
    int i = blockIdx.x * 256 + threadIdx.x;
    if (i < n) {
        float f = in[i];
        __nv_bfloat16 h = __float2bfloat16(f);
        hi[i] = h;
        lo[i] = __float2bfloat16(f - __bfloat162float(h));
    }
}

// ---------------------------------------------------------------------------
// Transpose + bf16 split.
// MODE 0 (dual): in0=x, in1=pos -> outA=(x+pos) hi/lo, outB=x hi/lo
// MODE 1 (single): in0=attn     -> outA hi/lo
// Input [B][C][N] fp32; output [B][N][C] bf16. Tile 64c x 64n.
// ---------------------------------------------------------------------------
template<int MODE>
__global__ __launch_bounds__(256) void conv_t_kernel(
    const float* __restrict__ in0, const float* __restrict__ in1,
    __nv_bfloat16* __restrict__ Ahi, __nv_bfloat16* __restrict__ Alo,
    __nv_bfloat16* __restrict__ Bhi, __nv_bfloat16* __restrict__ Blo)
{
    __shared__ float sA[64][65];
    __shared__ float sB[64][65];

    const int tid = threadIdx.x;
    const int n0 = blockIdx.x * 64;
    const int c0 = blockIdx.y * 64;
    const int bz = blockIdx.z;

    const float* i0 = in0 + (size_t)bz * CC * NN;
    const float* i1 = (MODE == 0) ? in1 + (size_t)bz * CC * NN : nullptr;

    #pragma unroll
    for (int i = 0; i < 16; i++) {
        int idx = i * 256 + tid;
        int rc = idx >> 6, cn = idx & 63;
        float xv = i0[(size_t)(c0 + rc) * NN + n0 + cn];
        if (MODE == 0) {
            float pv = i1[(size_t)(c0 + rc) * NN + n0 + cn];
            sA[rc][cn] = xv + pv;
            sB[rc][cn] = xv;
        } else {
            sA[rc][cn] = xv;
        }
    }
    __syncthreads();

    const size_t obase = ((size_t)bz * NN + n0) * CC + c0;
    #pragma unroll
    for (int i = 0; i < 8; i++) {
        int idx = i * 256 + tid;
        int nr = idx >> 5, cp = idx & 31;
        size_t oa = obase + (size_t)nr * CC + cp * 2;

        float f0 = sA[cp * 2][nr], f1 = sA[cp * 2 + 1][nr];
        __nv_bfloat16 h0 = __float2bfloat16(f0), h1 = __float2bfloat16(f1);
        __nv_bfloat16 l0 = __float2bfloat16(f0 - __bfloat162float(h0));
        __nv_bfloat16 l1 = __float2bfloat16(f1 - __bfloat162float(h1));
        *(__nv_bfloat162*)(Ahi + oa) = __nv_bfloat162(h0, h1);
        *(__nv_bfloat162*)(Alo + oa) = __nv_bfloat162(l0, l1);

        if (MODE == 0) {
            float g0 = sB[cp * 2][nr], g1 = sB[cp * 2 + 1][nr];
            __nv_bfloat16 p0 = __float2bfloat16(g0), p1 = __float2bfloat16(g1);
            __nv_bfloat16 q0 = __float2bfloat16(g0 - __bfloat162float(p0));
            __nv_bfloat16 q1 = __float2bfloat16(g1 - __bfloat162float(p1));
            *(__nv_bfloat162*)(Bhi + oa) = __nv_bfloat162(p0, p1);
            *(__nv_bfloat162*)(Blo + oa) = __nv_bfloat162(q0, q1);
        }
    }
}

// ---------------------------------------------------------------------------
// kv[e,d] = sum_n v_pad[e,n]*k[d,n] per (b,h); split-K, deterministic partials.
// ---------------------------------------------------------------------------
__global__ __launch_bounds__(256) void kv_kernel(
    const float* __restrict__ qk, const float* __restrict__ v,
    float* __restrict__ kvp)
{
    __shared__ float ks[64][68];
    __shared__ float vs[64][68];

    const int tid   = threadIdx.x;
    const int chunk = blockIdx.x;
    const int bh    = blockIdx.y;
    const int b = bh >> 3, h = bh & 7;

    const float* kbase = qk + (size_t)b * 2 * CC * NN + (size_t)(CC + h * HD) * NN;
    const float* vbase = v  + (size_t)b * CC * NN     + (size_t)(h * HD) * NN;

    const int d  = tid & 63;
    const int eg = tid >> 6;

    float acc[16];
    #pragma unroll
    for (int i = 0; i < 16; i++) acc[i] = 0.f;
    float ksum = 0.f;

    for (int sub = 0; sub < 8; sub++) {
        const int n0 = chunk * 512 + sub * 64;
        #pragma unroll
        for (int r = 0; r < 4; r++) {
            int idx = tid + r * 256;
            int row = idx >> 4;
            int col = (idx & 15) * 4;
            *(float4*)&ks[row][col] = *(const float4*)&kbase[(size_t)row * NN + n0 + col];
            *(float4*)&vs[row][col] = *(const float4*)&vbase[(size_t)row * NN + n0 + col];
        }
        __syncthreads();

        const float4* krow = (const float4*)&ks[d][0];
        #pragma unroll
        for (int n4 = 0; n4 < 16; n4++) {
            float4 kk = krow[n4];
            if (eg == 0) ksum += kk.x + kk.y + kk.z + kk.w;
            #pragma unroll
            for (int i = 0; i < 16; i++) {
                float4 vv = *(const float4*)&vs[eg * 16 + i][n4 * 4];
                acc[i] = fmaf(kk.x, vv.x, acc[i]);
                acc[i] = fmaf(kk.y, vv.y, acc[i]);
                acc[i] = fmaf(kk.z, vv.z, acc[i]);
                acc[i] = fmaf(kk.w, vv.w, acc[i]);
            }
        }
        __syncthreads();
    }

    float* outb = kvp + (size_t)chunk * (128 * 4160) + (size_t)bh * 4160;
    #pragma unroll
    for (int i = 0; i < 16; i++)
        outb[(eg * 16 + i) * 64 + d] = acc[i];
    if (eg == 0)
        outb[64 * 64 + d] = ksum;
}

__global__ void kv_reduce(const float* __restrict__ kvp, float* __restrict__ kvout)
{
    int i = blockIdx.x * 256 + threadIdx.x;
    if (i < 128 * 4160) {
        float s = 0.f;
        #pragma unroll
        for (int c = 0; c < 8; c++) s += kvp[(size_t)c * (128 * 4160) + i];
        kvout[i] = s;
    }
}

// ---------------------------------------------------------------------------
// attn[e,n] = (kv @ q)[e,n] / ((ksum @ q)[n] + EPS)
// ---------------------------------------------------------------------------
__global__ __launch_bounds__(256) void attn_kernel(
    const float* __restrict__ qk, const float* __restrict__ kv,
    float* __restrict__ attn)
{
    __shared__ float kvs[65 * 64];
    __shared__ float qs[16][68];
    __shared__ float dens[64];

    const int tid = threadIdx.x;
    const int bh  = blockIdx.y;
    const int b = bh >> 3, h = bh & 7;
    const int n0 = blockIdx.x * 64;

    for (int i = tid; i < 65 * 64; i += 256)
        kvs[i] = kv[(size_t)bh * 4160 + i];

    const int tx = tid & 15;
    const int ty = tid >> 4;
    const int ld = tid >> 4;
    const int ln = (tid & 15) * 4;

    float acc[4][4] = {};
    float dacc[4] = {0.f, 0.f, 0.f, 0.f};

    const float* qbase = qk + (size_t)b * 2 * CC * NN + (size_t)(h * HD) * NN + n0;

    __syncthreads();

    for (int dt = 0; dt < 64; dt += 16) {
        *(float4*)&qs[ld][ln] = *(const float4*)&qbase[(size_t)(dt + ld) * NN + ln];
        __syncthreads();
        #pragma unroll
        for (int dd = 0; dd < 16; dd++) {
            const int d = dt + dd;
            float4 qv = *(const float4*)&qs[dd][tx * 4];
            #pragma unroll
            for (int i = 0; i < 4; i++) {
                float a = kvs[(ty * 4 + i) * 64 + d];
                acc[i][0] = fmaf(a, qv.x, acc[i][0]);
                acc[i][1] = fmaf(a, qv.y, acc[i][1]);
                acc[i][2] = fmaf(a, qv.z, acc[i][2]);
                acc[i][3] = fmaf(a, qv.w, acc[i][3]);
            }
            if (ty == 0) {
                float a = kvs[64 * 64 + d];
                dacc[0] = fmaf(a, qv.x, dacc[0]);
                dacc[1] = fmaf(a, qv.y, dacc[1]);
                dacc[2] = fmaf(a, qv.z, dacc[2]);
                dacc[3] = fmaf(a, qv.w, dacc[3]);
            }
        }
        __syncthreads();
    }

    if (ty == 0) {
        dens[tx * 4 + 0] = dacc[0];
        dens[tx * 4 + 1] = dacc[1];
        dens[tx * 4 + 2] = dacc[2];
        dens[tx * 4 + 3] = dacc[3];
    }
    __syncthreads();

    float inv0 = 1.f / (dens[tx * 4 + 0] + EPS);
    float inv1 = 1.f / (dens[tx * 4 + 1] + EPS);
    float inv2 = 1.f / (dens[tx * 4 + 2] + EPS);
    float inv3 = 1.f / (dens[tx * 4 + 3] + EPS);

    float* ab = attn + (size_t)b * CC * NN + (size_t)(h * HD) * NN + n0 + tx * 4;
    #pragma unroll
    for (int i = 0; i < 4; i++) {
        float4 o;
        o.x = acc[i][0] * inv0;
        o.y = acc[i][1] * inv1;
        o.z = acc[i][2] * inv2;
        o.w = acc[i][3] * inv3;
        *(float4*)&ab[(size_t)(ty * 4 + i) * NN] = o;
    }
}

// ---------------------------------------------------------------------------
extern "C" void kernel_launch(void* const* d_in, const int* in_sizes, int n_in,
                              void* d_out, int out_size)
{
    const float* x    = (const float*)d_in[0];
    const float* pos  = (const float*)d_in[1];
    const float* w_qk = (const float*)d_in[2];
    const float* w_v  = (const float*)d_in[3];
    const float* w_o  = (const float*)d_in[4];
    float* out = (float*)d_out;

    float *qk, *v, *kvp, *kv;
    cudaGetSymbolAddress((void**)&qk,  g_qk);
    cudaGetSymbolAddress((void**)&v,   g_v);
    cudaGetSymbolAddress((void**)&kvp, g_kvp);
    cudaGetSymbolAddress((void**)&kv,  g_kv);
    __nv_bfloat16 *xqh, *xql, *xvh, *xvl, *aoh, *aol;
    __nv_bfloat16 *wqh, *wql, *wvh, *wvl, *woh, *wol;
    cudaGetSymbolAddress((void**)&xqh, g_xq_hi); cudaGetSymbolAddress((void**)&xql, g_xq_lo);
    cudaGetSymbolAddress((void**)&xvh, g_xv_hi); cudaGetSymbolAddress((void**)&xvl, g_xv_lo);
    cudaGetSymbolAddress((void**)&aoh, g_ao_hi); cudaGetSymbolAddress((void**)&aol, g_ao_lo);
    cudaGetSymbolAddress((void**)&wqh, g_wqk_hi); cudaGetSymbolAddress((void**)&wql, g_wqk_lo);
    cudaGetSymbolAddress((void**)&wvh, g_wv_hi);  cudaGetSymbolAddress((void**)&wvl, g_wv_lo);
    cudaGetSymbolAddress((void**)&woh, g_wo_hi);  cudaGetSymbolAddress((void**)&wol, g_wo_lo);

    cudaFuncSetAttribute(gemm_tc<true>,
                         cudaFuncAttributeMaxDynamicSharedMemorySize, GEMM_SMEM);
    cudaFuncSetAttribute(gemm_tc<false>,
                         cudaFuncAttributeMaxDynamicSharedMemorySize, GEMM_SMEM);

    // 0) weight splits
    conv_w_kernel<<<(1024 * 512 + 255) / 256, 256>>>(w_qk, wqh, wql, 1024 * 512);
    conv_w_kernel<<<(512 * 512 + 255) / 256, 256>>>(w_v, wvh, wvl, 512 * 512);
    conv_w_kernel<<<(512 * 512 + 255) / 256, 256>>>(w_o, woh, wol, 512 * 512);

    // 1) x / x+pos -> transposed bf16 hi/lo
    conv_t_kernel<0><<<dim3(NN / 64, CC / 64, BB), 256>>>(x, pos, xqh, xql, xvh, xvl);

    // 2) qk = relu(w_qk @ (x+pos))   [tensor cores]
    gemm_tc<true><<<dim3(NN / 256, 1024 / 128, BB), 512, GEMM_SMEM>>>(
        wqh, wql, xqh, xql, qk, 1024);

    // 3) v = w_v @ x                 [tensor cores]
    gemm_tc<false><<<dim3(NN / 256, 512 / 128, BB), 512, GEMM_SMEM>>>(
        wvh, wvl, xvh, xvl, v, 512);

    // 4) kv partials + reduce
    kv_kernel<<<dim3(8, 128), 256>>>(qk, v, kvp);
    kv_reduce<<<(128 * 4160 + 255) / 256, 256>>>(kvp, kv);

    // 5) attn (reuses g_v as output)
    attn_kernel<<<dim3(NN / 64, 128), 256>>>(qk, kv, v);

    // 6) attn -> transposed bf16 hi/lo
    conv_t_kernel<1><<<dim3(NN / 64, CC / 64, BB), 256>>>(v, nullptr, aoh, aol, nullptr, nullptr);

    // 7) out = w_o @ attn            [tensor cores]
    gemm_tc<false><<<dim3(NN / 256, 512 / 128, BB), 512, GEMM_SMEM>>>(
        woh, wol, aoh, aol, out, 512);
}

// round 4
// speedup vs baseline: 3.0817x; 1.3039x over previous
#include <cuda_runtime.h>
#include <cuda_fp16.h>
#include <cstdint>
#include <cstddef>

// Problem constants
#define BB   16
#define CC   512
#define NN   4096
#define NH   8
#define HD   64
#define EPS  1e-6f
#define WSCL 512.0f
#define INV_WSCL (1.0f / 512.0f)

// ---------------------------------------------------------------------------
// Scratch (device globals: allocation-free rule)
// ---------------------------------------------------------------------------
__device__ float g_qk[(size_t)BB * 2 * CC * NN];   // [B][1024][4096] relu(qk) fp32
__device__ float g_v [(size_t)BB * CC * NN];       // [B][512][4096] v fp32
__device__ float g_kvp[(size_t)8 * 128 * 65 * 64]; // split-K partials for kv
__device__ float g_kv [(size_t)128 * 65 * 64];     // [B*nh][65][64]

// fp16 activations, [B][N][C] K-major
__device__ __half g_xq[(size_t)BB * NN * CC];      // x + pos
__device__ __half g_xv[(size_t)BB * NN * CC];      // x
__device__ __half g_ao[(size_t)BB * NN * CC];      // attn output
// weights (x512 scaled) hi/lo fp16, [O][C] K-major
__device__ __half g_wqk_hi[1024 * 512];
__device__ __half g_wqk_lo[1024 * 512];
__device__ __half g_wv_hi [512 * 512];
__device__ __half g_wv_lo [512 * 512];
__device__ __half g_wo_hi [512 * 512];
__device__ __half g_wo_lo [512 * 512];

// ---------------------------------------------------------------------------
// Helpers
// ---------------------------------------------------------------------------
__device__ __forceinline__ uint32_t smem_u32(const void* p) {
    uint32_t a;
    asm("{ .reg .u64 t; cvta.to.shared.u64 t, %1; cvt.u32.u64 %0, t; }" : "=r"(a) : "l"(p));
    return a;
}
#define SWZ128(off) ((off) ^ (((off) >> 3) & 0x70))

__device__ __forceinline__ void cp_async16(uint32_t s, const void* g) {
    asm volatile("cp.async.cg.shared.global [%0], [%1], 16;" :: "r"(s), "l"(g));
}
#define CP_COMMIT() asm volatile("cp.async.commit_group;" ::: "memory")
#define CP_WAIT(n)  asm volatile("cp.async.wait_group %0;" :: "n"(n) : "memory")

__device__ __forceinline__ void ldmatrix_x4(uint32_t* r, uint32_t addr) {
    asm volatile("ldmatrix.sync.aligned.m8n8.x4.shared.b16 {%0,%1,%2,%3}, [%4];"
                 : "=r"(r[0]), "=r"(r[1]), "=r"(r[2]), "=r"(r[3]) : "r"(addr));
}
__device__ __forceinline__ void mma_f16(float* d, const uint32_t* a, const uint32_t* b) {
    asm volatile(
        "mma.sync.aligned.m16n8k16.row.col.f32.f16.f16.f32 "
        "{%0,%1,%2,%3}, {%4,%5,%6,%7}, {%8,%9}, {%0,%1,%2,%3};"
        : "+f"(d[0]), "+f"(d[1]), "+f"(d[2]), "+f"(d[3])
        : "r"(a[0]), "r"(a[1]), "r"(a[2]), "r"(a[3]), "r"(b[0]), "r"(b[1]));
}

// ---------------------------------------------------------------------------
// Tensor-core projection GEMM:  Y[O,N] = (1/512) * (Whi + Wlo)[O,C] @ X[C,N]
//   A = W hi/lo [O][C] fp16 K-major (pre-scaled x512); B = Xt [N][C] fp16.
// BM=128, BN=256, BK=64, 512 threads (16 warps, warp tile 64x32), 3 stages.
// 8 K-chunks; per chunk two mma terms (hi, lo) sharing B fragments.
// ---------------------------------------------------------------------------
#define BKB 128          // bytes per smem row (64 fp16)
#define AH_OFF 0
#define AL_OFF 16384
#define B_OFF  32768
#define STG    65536
#define GEMM_SMEM (3 * STG)

template<bool RELU>
__global__ __launch_bounds__(512, 1) void gemm_tc(
    const __half* __restrict__ Ahi, const __half* __restrict__ Alo,
    const __half* __restrict__ Bx, float* __restrict__ Y, int O)
{
    extern __shared__ __align__(1024) char smem[];
    const uint32_t sbase = smem_u32(smem);
    const int tid  = threadIdx.x;
    const int wid  = tid >> 5;
    const int lane = tid & 31;
    const int wm   = wid & 1;        // 2 m-warps
    const int wn   = wid >> 1;       // 8 n-warps

    const int n0 = blockIdx.x * 256;
    const int o0 = blockIdx.y * 128;
    const int bz = blockIdx.z;

    const __half* Bb = Bx + (size_t)bz * NN * CC;
    float* Yb = Y + (size_t)bz * O * NN;

    auto load_stage = [&](int ck, int st) {
        const int k0 = ck * 64;
        const uint32_t sb = sbase + st * STG;
        #pragma unroll
        for (int i = 0; i < 2; i++) {            // A hi+lo: 128 rows x 128B each
            int c = tid + i * 512;
            int row = c >> 3, cc = c & 7;
            const uint32_t so = SWZ128((uint32_t)(row * BKB + cc * 16));
            const size_t ga = (size_t)(o0 + row) * CC + k0 + cc * 8;
            cp_async16(sb + AH_OFF + so, Ahi + ga);
            cp_async16(sb + AL_OFF + so, Alo + ga);
        }
        #pragma unroll
        for (int i = 0; i < 4; i++) {            // B: 256 rows x 128B
            int c = tid + i * 512;
            int row = c >> 3, cc = c & 7;
            cp_async16(sb + B_OFF + SWZ128((uint32_t)(row * BKB + cc * 16)),
                       Bb + (size_t)(n0 + row) * CC + k0 + cc * 8);
        }
        CP_COMMIT();
    };

    float acc[4][4][4];
    #pragma unroll
    for (int mf = 0; mf < 4; mf++)
        #pragma unroll
        for (int nf = 0; nf < 4; nf++)
            #pragma unroll
            for (int e = 0; e < 4; e++) acc[mf][nf][e] = 0.f;

    load_stage(0, 0);
    load_stage(1, 1);
    CP_WAIT(1);
    __syncthreads();

    const int a_row  = wm * 64 + (lane & 15);
    const int a_coff = (lane >> 4) * 16;
    const int b_row  = wn * 32 + ((lane >> 4) << 3) + (lane & 7);
    const int b_coff = ((lane >> 3) & 1) * 16;

    for (int it = 0; it < 8; it++) {
        const uint32_t sb = sbase + (it % 3) * STG;
        #pragma unroll
        for (int kk = 0; kk < 4; kk++) {
            uint32_t ah[4][4], al[4][4], b[4][2];
            #pragma unroll
            for (int mf = 0; mf < 4; mf++) {
                const uint32_t so = SWZ128((uint32_t)((a_row + mf * 16) * BKB + kk * 32 + a_coff));
                ldmatrix_x4(ah[mf], sb + AH_OFF + so);
                ldmatrix_x4(al[mf], sb + AL_OFF + so);
            }
            #pragma unroll
            for (int np = 0; np < 2; np++) {
                uint32_t r[4];
                ldmatrix_x4(r, sb + B_OFF +
                            SWZ128((uint32_t)((b_row + np * 16) * BKB + kk * 32 + b_coff)));
                b[np * 2][0] = r[0];  b[np * 2][1] = r[1];
                b[np * 2 + 1][0] = r[2];  b[np * 2 + 1][1] = r[3];
            }
            #pragma unroll
            for (int mf = 0; mf < 4; mf++)
                #pragma unroll
                for (int nf = 0; nf < 4; nf++) {
                    mma_f16(acc[mf][nf], ah[mf], b[nf]);
                    mma_f16(acc[mf][nf], al[mf], b[nf]);
                }
        }
        if (it + 2 < 8) {
            load_stage(it + 2, (it + 2) % 3);
            CP_WAIT(1);
        } else {
            CP_WAIT(0);
        }
        __syncthreads();
    }

    // Epilogue: scale by 1/512, optional relu, float2 stores
    const int er = lane >> 2;
    const int ec = (lane & 3) * 2;
    #pragma unroll
    for (int mf = 0; mf < 4; mf++) {
        #pragma unroll
        for (int nf = 0; nf < 4; nf++) {
            const int orow = o0 + wm * 64 + mf * 16 + er;
            const int ocol = n0 + wn * 32 + nf * 8 + ec;
            float2 v0, v1;
            v0.x = acc[mf][nf][0] * INV_WSCL; v0.y = acc[mf][nf][1] * INV_WSCL;
            v1.x = acc[mf][nf][2] * INV_WSCL; v1.y = acc[mf][nf][3] * INV_WSCL;
            if (RELU) {
                v0.x = fmaxf(v0.x, 0.f); v0.y = fmaxf(v0.y, 0.f);
                v1.x = fmaxf(v1.x, 0.f); v1.y = fmaxf(v1.y, 0.f);
            }
            *(float2*)&Yb[(size_t)orow * NN + ocol]       = v0;
            *(float2*)&Yb[(size_t)(orow + 8) * NN + ocol] = v1;
        }
    }
}

// ---------------------------------------------------------------------------
// Weight split: fp32 -> (x512) fp16 hi/lo
// ---------------------------------------------------------------------------
__global__ void conv_w_kernel(const float* __restrict__ in,
                              __half* __restrict__ hi,
                              __half* __restrict__ lo, int n)
{
    int i = blockIdx.x * 256 + threadIdx.x;
    if (i < n) {
        float f = in[i] * WSCL;
        __half h = __float2half_rn(f);
        hi[i] = h;
        lo[i] = __float2half_rn(f - __half2float(h));
    }
}

// ---------------------------------------------------------------------------
// Transpose + fp16 convert: x, pos [B][C][N] fp32 -> xq=(x+pos), xv=x
// as [B][N][C] fp16. Tile 64c x 64n.
// ---------------------------------------------------------------------------
__global__ __launch_bounds__(256) void conv_xt_kernel(
    const float* __restrict__ x, const float* __restrict__ pos,
    __half* __restrict__ xq, __half* __restrict__ xv)
{
    __shared__ float sA[64][65];
    __shared__ float sB[64][65];

    const int tid = threadIdx.x;
    const int n0 = blockIdx.x * 64;
    const int c0 = blockIdx.y * 64;
    const int bz = blockIdx.z;

    const float* i0 = x   + (size_t)bz * CC * NN;
    const float* i1 = pos + (size_t)bz * CC * NN;

    #pragma unroll
    for (int i = 0; i < 16; i++) {
        int idx = i * 256 + tid;
        int rc = idx >> 6, cn = idx & 63;
        float xv_ = i0[(size_t)(c0 + rc) * NN + n0 + cn];
        float pv  = i1[(size_t)(c0 + rc) * NN + n0 + cn];
        sA[rc][cn] = xv_ + pv;
        sB[rc][cn] = xv_;
    }
    __syncthreads();

    const size_t obase = ((size_t)bz * NN + n0) * CC + c0;
    #pragma unroll
    for (int i = 0; i < 8; i++) {
        int idx = i * 256 + tid;
        int nr = idx >> 5, cp = idx & 31;
        size_t oa = obase + (size_t)nr * CC + cp * 2;
        __half2 hq, hv;
        hq.x = __float2half_rn(sA[cp * 2][nr]);
        hq.y = __float2half_rn(sA[cp * 2 + 1][nr]);
        hv.x = __float2half_rn(sB[cp * 2][nr]);
        hv.y = __float2half_rn(sB[cp * 2 + 1][nr]);
        *(__half2*)(xq + oa) = hq;
        *(__half2*)(xv + oa) = hv;
    }
}

// ---------------------------------------------------------------------------
// kv[e,d] = sum_n v_pad[e,n]*k[d,n] per (b,h); split-K, deterministic partials.
// ---------------------------------------------------------------------------
__global__ __launch_bounds__(256) void kv_kernel(
    const float* __restrict__ qk, const float* __restrict__ v,
    float* __restrict__ kvp)
{
    __shared__ float ks[64][68];
    __shared__ float vs[64][68];

    const int tid   = threadIdx.x;
    const int chunk = blockIdx.x;
    const int bh    = blockIdx.y;
    const int b = bh >> 3, h = bh & 7;

    const float* kbase = qk + (size_t)b * 2 * CC * NN + (size_t)(CC + h * HD) * NN;
    const float* vbase = v  + (size_t)b * CC * NN     + (size_t)(h * HD) * NN;

    const int d  = tid & 63;
    const int eg = tid >> 6;

    float acc[16];
    #pragma unroll
    for (int i = 0; i < 16; i++) acc[i] = 0.f;
    float ksum = 0.f;

    for (int sub = 0; sub < 8; sub++) {
        const int n0 = chunk * 512 + sub * 64;
        #pragma unroll
        for (int r = 0; r < 4; r++) {
            int idx = tid + r * 256;
            int row = idx >> 4;
            int col = (idx & 15) * 4;
            *(float4*)&ks[row][col] = *(const float4*)&kbase[(size_t)row * NN + n0 + col];
            *(float4*)&vs[row][col] = *(const float4*)&vbase[(size_t)row * NN + n0 + col];
        }
        __syncthreads();

        const float4* krow = (const float4*)&ks[d][0];
        #pragma unroll
        for (int n4 = 0; n4 < 16; n4++) {
            float4 kk = krow[n4];
            if (eg == 0) ksum += kk.x + kk.y + kk.z + kk.w;
            #pragma unroll
            for (int i = 0; i < 16; i++) {
                float4 vv = *(const float4*)&vs[eg * 16 + i][n4 * 4];
                acc[i] = fmaf(kk.x, vv.x, acc[i]);
                acc[i] = fmaf(kk.y, vv.y, acc[i]);
                acc[i] = fmaf(kk.z, vv.z, acc[i]);
                acc[i] = fmaf(kk.w, vv.w, acc[i]);
            }
        }
        __syncthreads();
    }

    float* outb = kvp + (size_t)chunk * (128 * 4160) + (size_t)bh * 4160;
    #pragma unroll
    for (int i = 0; i < 16; i++)
        outb[(eg * 16 + i) * 64 + d] = acc[i];
    if (eg == 0)
        outb[64 * 64 + d] = ksum;
}

__global__ void kv_reduce(const float* __restrict__ kvp, float* __restrict__ kvout)
{
    int i = blockIdx.x * 256 + threadIdx.x;
    if (i < 128 * 4160) {
        float s = 0.f;
        #pragma unroll
        for (int c = 0; c < 8; c++) s += kvp[(size_t)c * (128 * 4160) + i];
        kvout[i] = s;
    }
}

// ---------------------------------------------------------------------------
// attn: out[e,n] = (kv @ q)[e,n] / ((ksum @ q)[n] + EPS)
// Output written DIRECTLY as fp16 transposed [B][N][C] (C idx = h*64+e).
// ---------------------------------------------------------------------------
__global__ __launch_bounds__(256) void attn_kernel(
    const float* __restrict__ qk, const float* __restrict__ kv,
    __half* __restrict__ ao)
{
    __shared__ float kvs[65 * 64];
    __shared__ float qs[16][68];
    __shared__ float dens[64];
    __shared__ float sOut[64][65];      // [n][e]

    const int tid = threadIdx.x;
    const int bh  = blockIdx.y;
    const int b = bh >> 3, h = bh & 7;
    const int n0 = blockIdx.x * 64;

    for (int i = tid; i < 65 * 64; i += 256)
        kvs[i] = kv[(size_t)bh * 4160 + i];

    const int tx = tid & 15;
    const int ty = tid >> 4;
    const int ld = tid >> 4;
    const int ln = (tid & 15) * 4;

    float acc[4][4] = {};
    float dacc[4] = {0.f, 0.f, 0.f, 0.f};

    const float* qbase = qk + (size_t)b * 2 * CC * NN + (size_t)(h * HD) * NN + n0;

    __syncthreads();

    for (int dt = 0; dt < 64; dt += 16) {
        *(float4*)&qs[ld][ln] = *(const float4*)&qbase[(size_t)(dt + ld) * NN + ln];
        __syncthreads();
        #pragma unroll
        for (int dd = 0; dd < 16; dd++) {
            const int d = dt + dd;
            float4 qv = *(const float4*)&qs[dd][tx * 4];
            #pragma unroll
            for (int i = 0; i < 4; i++) {
                float a = kvs[(ty * 4 + i) * 64 + d];
                acc[i][0] = fmaf(a, qv.x, acc[i][0]);
                acc[i][1] = fmaf(a, qv.y, acc[i][1]);
                acc[i][2] = fmaf(a, qv.z, acc[i][2]);
                acc[i][3] = fmaf(a, qv.w, acc[i][3]);
            }
            if (ty == 0) {
                float a = kvs[64 * 64 + d];
                dacc[0] = fmaf(a, qv.x, dacc[0]);
                dacc[1] = fmaf(a, qv.y, dacc[1]);
                dacc[2] = fmaf(a, qv.z, dacc[2]);
                dacc[3] = fmaf(a, qv.w, dacc[3]);
            }
        }
        __syncthreads();
    }

    if (ty == 0) {
        dens[tx * 4 + 0] = dacc[0];
        dens[tx * 4 + 1] = dacc[1];
        dens[tx * 4 + 2] = dacc[2];
        dens[tx * 4 + 3] = dacc[3];
    }
    __syncthreads();

    float inv[4];
    #pragma unroll
    for (int j = 0; j < 4; j++) inv[j] = 1.f / (dens[tx * 4 + j] + EPS);

    #pragma unroll
    for (int i = 0; i < 4; i++)
        #pragma unroll
        for (int j = 0; j < 4; j++)
            sOut[tx * 4 + j][ty * 4 + i] = acc[i][j] * inv[j];
    __syncthreads();

    // transposed coalesced write: thread -> (n, 16-wide e chunk)
    const int n  = tid & 63;
    const int eg = tid >> 6;       // 0..3
    __half tmp[16];
    #pragma unroll
    for (int c = 0; c < 16; c++)
        tmp[c] = __float2half_rn(sOut[n][eg * 16 + c]);
    __half* dst = ao + ((size_t)b * NN + n0 + n) * CC + h * HD + eg * 16;
    *(uint4*)(dst)     = *(uint4*)&tmp[0];
    *(uint4*)(dst + 8) = *(uint4*)&tmp[8];
}

// ---------------------------------------------------------------------------
extern "C" void kernel_launch(void* const* d_in, const int* in_sizes, int n_in,
                              void* d_out, int out_size)
{
    const float* x    = (const float*)d_in[0];
    const float* pos  = (const float*)d_in[1];
    const float* w_qk = (const float*)d_in[2];
    const float* w_v  = (const float*)d_in[3];
    const float* w_o  = (const float*)d_in[4];
    float* out = (float*)d_out;

    float *qk, *v, *kvp, *kv;
    cudaGetSymbolAddress((void**)&qk,  g_qk);
    cudaGetSymbolAddress((void**)&v,   g_v);
    cudaGetSymbolAddress((void**)&kvp, g_kvp);
    cudaGetSymbolAddress((void**)&kv,  g_kv);
    __half *xq, *xv, *ao;
    __half *wqh, *wql, *wvh, *wvl, *woh, *wol;
    cudaGetSymbolAddress((void**)&xq, g_xq);
    cudaGetSymbolAddress((void**)&xv, g_xv);
    cudaGetSymbolAddress((void**)&ao, g_ao);
    cudaGetSymbolAddress((void**)&wqh, g_wqk_hi); cudaGetSymbolAddress((void**)&wql, g_wqk_lo);
    cudaGetSymbolAddress((void**)&wvh, g_wv_hi);  cudaGetSymbolAddress((void**)&wvl, g_wv_lo);
    cudaGetSymbolAddress((void**)&woh, g_wo_hi);  cudaGetSymbolAddress((void**)&wol, g_wo_lo);

    cudaFuncSetAttribute(gemm_tc<true>,
                         cudaFuncAttributeMaxDynamicSharedMemorySize, GEMM_SMEM);
    cudaFuncSetAttribute(gemm_tc<false>,
                         cudaFuncAttributeMaxDynamicSharedMemorySize, GEMM_SMEM);

    // 0) weight splits (x512 scaled fp16 hi/lo)
    conv_w_kernel<<<(1024 * 512 + 255) / 256, 256>>>(w_qk, wqh, wql, 1024 * 512);
    conv_w_kernel<<<(512 * 512 + 255) / 256, 256>>>(w_v, wvh, wvl, 512 * 512);
    conv_w_kernel<<<(512 * 512 + 255) / 256, 256>>>(w_o, woh, wol, 512 * 512);

    // 1) x / x+pos -> transposed fp16
    conv_xt_kernel<<<dim3(NN / 64, CC / 64, BB), 256>>>(x, pos, xq, xv);

    // 2) qk = relu(w_qk @ (x+pos))   [tensor cores]
    gemm_tc<true><<<dim3(NN / 256, 1024 / 128, BB), 512, GEMM_SMEM>>>(
        wqh, wql, xq, qk, 1024);

    // 3) v = w_v @ x                 [tensor cores]
    gemm_tc<false><<<dim3(NN / 256, 512 / 128, BB), 512, GEMM_SMEM>>>(
        wvh, wvl, xv, v, 512);

    // 4) kv partials + reduce
    kv_kernel<<<dim3(8, 128), 256>>>(qk, v, kvp);
    kv_reduce<<<(128 * 4160 + 255) / 256, 256>>>(kvp, kv);

    // 5) attn -> fp16 transposed [B][N][C] directly
    attn_kernel<<<dim3(NN / 64, 128), 256>>>(qk, kv, ao);

    // 6) out = w_o @ attn            [tensor cores]
    gemm_tc<false><<<dim3(NN / 256, 512 / 128, BB), 512, GEMM_SMEM>>>(
        woh, wol, ao, out, 512);
}

// round 5
// speedup vs baseline: 3.9683x; 1.2877x over previous
#include <cuda_runtime.h>
#include <cuda_fp16.h>
#include <cstdint>
#include <cstddef>

// Problem constants
#define BB   16
#define CC   512
#define NN   4096
#define NH   8
#define HD   64
#define EPS  1e-6f
#define WSCL 512.0f
#define INV_WSCL (1.0f / 512.0f)

// ---------------------------------------------------------------------------
// Scratch (device globals: allocation-free rule)
// ---------------------------------------------------------------------------
__device__ __half g_qkh[(size_t)BB * 2 * CC * NN]; // [B][1024][4096] relu(qk) fp16
__device__ __half g_vh [(size_t)BB * CC * NN];     // [B][512][4096] v fp16
__device__ float g_kvp[(size_t)8 * 128 * 65 * 64]; // split-K partials for kv
__device__ float g_kv [(size_t)128 * 65 * 64];     // [B*nh][65][64] fp32

// fp16 activations, [B][N][C] K-major
__device__ __half g_xq[(size_t)BB * NN * CC];      // x + pos
__device__ __half g_xv[(size_t)BB * NN * CC];      // x
__device__ __half g_ao[(size_t)BB * NN * CC];      // attn output (transposed)
// weights (x512 scaled) hi/lo fp16, [O][C] K-major
__device__ __half g_wqk_hi[1024 * 512];
__device__ __half g_wqk_lo[1024 * 512];
__device__ __half g_wv_hi [512 * 512];
__device__ __half g_wv_lo [512 * 512];
__device__ __half g_wo_hi [512 * 512];
__device__ __half g_wo_lo [512 * 512];

// ---------------------------------------------------------------------------
// Helpers
// ---------------------------------------------------------------------------
__device__ __forceinline__ uint32_t smem_u32(const void* p) {
    uint32_t a;
    asm("{ .reg .u64 t; cvta.to.shared.u64 t, %1; cvt.u32.u64 %0, t; }" : "=r"(a) : "l"(p));
    return a;
}
#define SWZ128(off) ((off) ^ (((off) >> 3) & 0x70))
#define ONES2 0x3C003C00u

__device__ __forceinline__ void cp_async16(uint32_t s, const void* g) {
    asm volatile("cp.async.cg.shared.global [%0], [%1], 16;" :: "r"(s), "l"(g));
}
#define CP_COMMIT() asm volatile("cp.async.commit_group;" ::: "memory")
#define CP_WAIT(n)  asm volatile("cp.async.wait_group %0;" :: "n"(n) : "memory")

__device__ __forceinline__ void ldmatrix_x4(uint32_t* r, uint32_t addr) {
    asm volatile("ldmatrix.sync.aligned.m8n8.x4.shared.b16 {%0,%1,%2,%3}, [%4];"
                 : "=r"(r[0]), "=r"(r[1]), "=r"(r[2]), "=r"(r[3]) : "r"(addr));
}
__device__ __forceinline__ void mma_f16(float* d, const uint32_t* a, const uint32_t* b) {
    asm volatile(
        "mma.sync.aligned.m16n8k16.row.col.f32.f16.f16.f32 "
        "{%0,%1,%2,%3}, {%4,%5,%6,%7}, {%8,%9}, {%0,%1,%2,%3};"
        : "+f"(d[0]), "+f"(d[1]), "+f"(d[2]), "+f"(d[3])
        : "r"(a[0]), "r"(a[1]), "r"(a[2]), "r"(a[3]), "r"(b[0]), "r"(b[1]));
}

// ---------------------------------------------------------------------------
// Tensor-core projection GEMM:  Y[O,N] = (1/512) * (Whi + Wlo)[O,C] @ X[C,N]
// BM=128, BN=256, BK=64, 512 threads, 3 stages. HOUT: fp16 output.
// ---------------------------------------------------------------------------
#define BKB 128
#define AH_OFF 0
#define AL_OFF 16384
#define B_OFF  32768
#define STG    65536
#define GEMM_SMEM (3 * STG)

template<bool RELU, bool HOUT>
__global__ __launch_bounds__(512, 1) void gemm_tc(
    const __half* __restrict__ Ahi, const __half* __restrict__ Alo,
    const __half* __restrict__ Bx, void* __restrict__ Yv, int O)
{
    extern __shared__ __align__(1024) char smem[];
    const uint32_t sbase = smem_u32(smem);
    const int tid  = threadIdx.x;
    const int wid  = tid >> 5;
    const int lane = tid & 31;
    const int wm   = wid & 1;
    const int wn   = wid >> 1;

    const int n0 = blockIdx.x * 256;
    const int o0 = blockIdx.y * 128;
    const int bz = blockIdx.z;

    const __half* Bb = Bx + (size_t)bz * NN * CC;

    auto load_stage = [&](int ck, int st) {
        const int k0 = ck * 64;
        const uint32_t sb = sbase + st * STG;
        #pragma unroll
        for (int i = 0; i < 2; i++) {
            int c = tid + i * 512;
            int row = c >> 3, cc = c & 7;
            const uint32_t so = SWZ128((uint32_t)(row * BKB + cc * 16));
            const size_t ga = (size_t)(o0 + row) * CC + k0 + cc * 8;
            cp_async16(sb + AH_OFF + so, Ahi + ga);
            cp_async16(sb + AL_OFF + so, Alo + ga);
        }
        #pragma unroll
        for (int i = 0; i < 4; i++) {
            int c = tid + i * 512;
            int row = c >> 3, cc = c & 7;
            cp_async16(sb + B_OFF + SWZ128((uint32_t)(row * BKB + cc * 16)),
                       Bb + (size_t)(n0 + row) * CC + k0 + cc * 8);
        }
        CP_COMMIT();
    };

    float acc[4][4][4];
    #pragma unroll
    for (int mf = 0; mf < 4; mf++)
        #pragma unroll
        for (int nf = 0; nf < 4; nf++)
            #pragma unroll
            for (int e = 0; e < 4; e++) acc[mf][nf][e] = 0.f;

    load_stage(0, 0);
    load_stage(1, 1);
    CP_WAIT(1);
    __syncthreads();

    const int a_row  = wm * 64 + (lane & 15);
    const int a_coff = (lane >> 4) * 16;
    const int b_row  = wn * 32 + ((lane >> 4) << 3) + (lane & 7);
    const int b_coff = ((lane >> 3) & 1) * 16;

    for (int it = 0; it < 8; it++) {
        const uint32_t sb = sbase + (it % 3) * STG;
        #pragma unroll
        for (int kk = 0; kk < 4; kk++) {
            uint32_t ah[4][4], al[4][4], b[4][2];
            #pragma unroll
            for (int mf = 0; mf < 4; mf++) {
                const uint32_t so = SWZ128((uint32_t)((a_row + mf * 16) * BKB + kk * 32 + a_coff));
                ldmatrix_x4(ah[mf], sb + AH_OFF + so);
                ldmatrix_x4(al[mf], sb + AL_OFF + so);
            }
            #pragma unroll
            for (int np = 0; np < 2; np++) {
                uint32_t r[4];
                ldmatrix_x4(r, sb + B_OFF +
                            SWZ128((uint32_t)((b_row + np * 16) * BKB + kk * 32 + b_coff)));
                b[np * 2][0] = r[0];  b[np * 2][1] = r[1];
                b[np * 2 + 1][0] = r[2];  b[np * 2 + 1][1] = r[3];
            }
            #pragma unroll
            for (int mf = 0; mf < 4; mf++)
                #pragma unroll
                for (int nf = 0; nf < 4; nf++) {
                    mma_f16(acc[mf][nf], ah[mf], b[nf]);
                    mma_f16(acc[mf][nf], al[mf], b[nf]);
                }
        }
        if (it + 2 < 8) {
            load_stage(it + 2, (it + 2) % 3);
            CP_WAIT(1);
        } else {
            CP_WAIT(0);
        }
        __syncthreads();
    }

    const int er = lane >> 2;
    const int ec = (lane & 3) * 2;
    #pragma unroll
    for (int mf = 0; mf < 4; mf++) {
        #pragma unroll
        for (int nf = 0; nf < 4; nf++) {
            const int orow = o0 + wm * 64 + mf * 16 + er;
            const int ocol = n0 + wn * 32 + nf * 8 + ec;
            float v0x = acc[mf][nf][0] * INV_WSCL, v0y = acc[mf][nf][1] * INV_WSCL;
            float v1x = acc[mf][nf][2] * INV_WSCL, v1y = acc[mf][nf][3] * INV_WSCL;
            if (RELU) {
                v0x = fmaxf(v0x, 0.f); v0y = fmaxf(v0y, 0.f);
                v1x = fmaxf(v1x, 0.f); v1y = fmaxf(v1y, 0.f);
            }
            if (HOUT) {
                __half* Yb = (__half*)Yv + (size_t)bz * O * NN;
                *(__half2*)&Yb[(size_t)orow * NN + ocol] =
                    __floats2half2_rn(v0x, v0y);
                *(__half2*)&Yb[(size_t)(orow + 8) * NN + ocol] =
                    __floats2half2_rn(v1x, v1y);
            } else {
                float* Yb = (float*)Yv + (size_t)bz * O * NN;
                *(float2*)&Yb[(size_t)orow * NN + ocol]       = make_float2(v0x, v0y);
                *(float2*)&Yb[(size_t)(orow + 8) * NN + ocol] = make_float2(v1x, v1y);
            }
        }
    }
}

// ---------------------------------------------------------------------------
// Weight split: fp32 -> (x512) fp16 hi/lo
// ---------------------------------------------------------------------------
__global__ void conv_w_kernel(const float* __restrict__ in,
                              __half* __restrict__ hi,
                              __half* __restrict__ lo, int n)
{
    int i = blockIdx.x * 256 + threadIdx.x;
    if (i < n) {
        float f = in[i] * WSCL;
        __half h = __float2half_rn(f);
        hi[i] = h;
        lo[i] = __float2half_rn(f - __half2float(h));
    }
}

// ---------------------------------------------------------------------------
// Transpose + fp16 convert: x, pos [B][C][N] fp32 -> xq=(x+pos), xv=x  [B][N][C]
// ---------------------------------------------------------------------------
__global__ __launch_bounds__(256) void conv_xt_kernel(
    const float* __restrict__ x, const float* __restrict__ pos,
    __half* __restrict__ xq, __half* __restrict__ xv)
{
    __shared__ float sA[64][65];
    __shared__ float sB[64][65];

    const int tid = threadIdx.x;
    const int n0 = blockIdx.x * 64;
    const int c0 = blockIdx.y * 64;
    const int bz = blockIdx.z;

    const float* i0 = x   + (size_t)bz * CC * NN;
    const float* i1 = pos + (size_t)bz * CC * NN;

    #pragma unroll
    for (int i = 0; i < 16; i++) {
        int idx = i * 256 + tid;
        int rc = idx >> 6, cn = idx & 63;
        float xv_ = i0[(size_t)(c0 + rc) * NN + n0 + cn];
        float pv  = i1[(size_t)(c0 + rc) * NN + n0 + cn];
        sA[rc][cn] = xv_ + pv;
        sB[rc][cn] = xv_;
    }
    __syncthreads();

    const size_t obase = ((size_t)bz * NN + n0) * CC + c0;
    #pragma unroll
    for (int i = 0; i < 8; i++) {
        int idx = i * 256 + tid;
        int nr = idx >> 5, cp = idx & 31;
        size_t oa = obase + (size_t)nr * CC + cp * 2;
        __half2 hq, hv;
        hq.x = __float2half_rn(sA[cp * 2][nr]);
        hq.y = __float2half_rn(sA[cp * 2 + 1][nr]);
        hv.x = __float2half_rn(sB[cp * 2][nr]);
        hv.y = __float2half_rn(sB[cp * 2 + 1][nr]);
        *(__half2*)(xq + oa) = hq;
        *(__half2*)(xv + oa) = hv;
    }
}

// ---------------------------------------------------------------------------
// kv (tensor cores): kv[e,d] = sum_n v[e,n]*k[d,n] (+ ksum row via ones-A).
// grid (8 chunks, 128 bh), 128 threads (4 warps). K-range 512 per block.
// ---------------------------------------------------------------------------
__global__ __launch_bounds__(128) void kv_tc_kernel(
    const __half* __restrict__ qk, const __half* __restrict__ v,
    float* __restrict__ kvp)
{
    __shared__ __align__(1024) char smem[32768];   // 2 stages x (v 8KB + k 8KB)
    const uint32_t sbase = smem_u32(smem);

    const int tid   = threadIdx.x;
    const int wid   = tid >> 5;
    const int lane  = tid & 31;
    const int chunk = blockIdx.x;
    const int bh    = blockIdx.y;
    const int b = bh >> 3, h = bh & 7;

    const __half* kbase = qk + ((size_t)b * 2 * CC + CC + h * HD) * NN;
    const __half* vbase = v  + ((size_t)b * CC + h * HD) * NN;

    auto load_sub = [&](int sub, int st) {
        const int n0 = chunk * 512 + sub * 64;
        const uint32_t sb = sbase + st * 16384;
        #pragma unroll
        for (int i = 0; i < 4; i++) {
            int idx = tid + i * 128;
            int row = idx >> 3, c = idx & 7;
            const uint32_t so = SWZ128((uint32_t)(row * 128 + c * 16));
            cp_async16(sb +        so, vbase + (size_t)row * NN + n0 + c * 8);
            cp_async16(sb + 8192 + so, kbase + (size_t)row * NN + n0 + c * 8);
        }
        CP_COMMIT();
    };

    float acc[5][2][4];
    #pragma unroll
    for (int m = 0; m < 5; m++)
        #pragma unroll
        for (int nt = 0; nt < 2; nt++)
            #pragma unroll
            for (int e = 0; e < 4; e++) acc[m][nt][e] = 0.f;

    const int a_row  = lane & 15;
    const int a_coff = (lane >> 4) * 16;
    const int b_row  = wid * 16 + ((lane >> 4) << 3) + (lane & 7);
    const int b_coff = ((lane >> 3) & 1) * 16;
    const uint32_t ones[4] = {ONES2, ONES2, ONES2, ONES2};

    load_sub(0, 0);
    for (int sub = 0; sub < 8; sub++) {
        if (sub + 1 < 8) { load_sub(sub + 1, (sub + 1) & 1); CP_WAIT(1); }
        else             { CP_WAIT(0); }
        __syncthreads();
        const uint32_t sv = sbase + (sub & 1) * 16384;
        const uint32_t sk = sv + 8192;
        #pragma unroll
        for (int ks = 0; ks < 4; ks++) {
            uint32_t a[4][4];
            #pragma unroll
            for (int m = 0; m < 4; m++)
                ldmatrix_x4(a[m], sv + SWZ128((uint32_t)((m * 16 + a_row) * 128 + ks * 32 + a_coff)));
            uint32_t bf[4];
            ldmatrix_x4(bf, sk + SWZ128((uint32_t)(b_row * 128 + ks * 32 + b_coff)));
            uint32_t b0[2] = {bf[0], bf[1]}, b1[2] = {bf[2], bf[3]};
            #pragma unroll
            for (int m = 0; m < 4; m++) {
                mma_f16(acc[m][0], a[m], b0);
                mma_f16(acc[m][1], a[m], b1);
            }
            mma_f16(acc[4][0], ones, b0);
            mma_f16(acc[4][1], ones, b1);
        }
        __syncthreads();
    }

    float* outb = kvp + (size_t)chunk * (128 * 4160) + (size_t)bh * 4160;
    #pragma unroll
    for (int m = 0; m < 4; m++)
        #pragma unroll
        for (int nt = 0; nt < 2; nt++) {
            const int e = m * 16 + (lane >> 2);
            const int d = wid * 16 + nt * 8 + 2 * (lane & 3);
            *(float2*)&outb[e * 64 + d]       = make_float2(acc[m][nt][0], acc[m][nt][1]);
            *(float2*)&outb[(e + 8) * 64 + d] = make_float2(acc[m][nt][2], acc[m][nt][3]);
        }
    if (lane < 4) {
        #pragma unroll
        for (int nt = 0; nt < 2; nt++) {
            const int d = wid * 16 + nt * 8 + 2 * lane;
            *(float2*)&outb[4096 + d] = make_float2(acc[4][nt][0], acc[4][nt][1]);
        }
    }
}

__global__ void kv_reduce(const float* __restrict__ kvp, float* __restrict__ kvout)
{
    int i = blockIdx.x * 256 + threadIdx.x;
    if (i < 128 * 4160) {
        float s = 0.f;
        #pragma unroll
        for (int c = 0; c < 8; c++) s += kvp[(size_t)c * (128 * 4160) + i];
        kvout[i] = s;
    }
}

// ---------------------------------------------------------------------------
// attn (tensor cores): out[e,n] = (kv @ q)[e,n] / (ksum@q[n] + EPS)
// A = kv hi/lo fp16 [80][64] (row64 = ksum), B = q^T [128 n][64 d].
// grid (NN/128, 128 bh), 128 threads. Output fp16 transposed [B][N][C].
// ---------------------------------------------------------------------------
#define AT_AH 0
#define AT_AL 10240
#define AT_B  20480
#define AT_SCR 36864           // q stage [64][144]h then sOut [128][72]h
#define ATTN_SMEM 55296

__global__ __launch_bounds__(128) void attn_tc_kernel(
    const __half* __restrict__ qk, const float* __restrict__ kv,
    __half* __restrict__ ao)
{
    extern __shared__ __align__(1024) char smem[];
    const uint32_t sbase = smem_u32(smem);
    __half* S1   = (__half*)(smem + AT_SCR);
    __half* sOut = (__half*)(smem + AT_SCR);

    const int tid  = threadIdx.x;
    const int wid  = tid >> 5;
    const int lane = tid & 31;
    const int bh   = blockIdx.y;
    const int b = bh >> 3, h = bh & 7;
    const int n0 = blockIdx.x * 128;

    // async load q tile [64 d][128 n] -> S1 (pitch 144 halves)
    const __half* qbase = qk + ((size_t)b * 2 * CC + h * HD) * NN + n0;
    #pragma unroll
    for (int i = 0; i < 8; i++) {
        int idx = tid + i * 128;
        int d = idx >> 4, j = idx & 15;
        cp_async16(sbase + AT_SCR + (uint32_t)(d * 288 + j * 16),
                   qbase + (size_t)d * NN + j * 8);
    }
    CP_COMMIT();

    // zero A hi/lo (80 rows incl. pad), then fill rows 0..64 from kv fp32
    {
        uint4 z = {0, 0, 0, 0};
        for (int i = tid; i < 1280; i += 128) {
            *(uint4*)(smem + AT_AH + i * 16) = z;   // covers AH+AL (20480 B)
        }
    }
    __syncthreads();
    const float* kvb = kv + (size_t)bh * 4160;
    for (int i = tid; i < 4160; i += 128) {
        int e = i >> 6, d = i & 63;
        float f = kvb[i];
        __half hi = __float2half_rn(f);
        __half lo = __float2half_rn(f - __half2float(hi));
        uint32_t off = SWZ128((uint32_t)(e * 128 + d * 2));
        *(__half*)(smem + AT_AH + off) = hi;
        *(__half*)(smem + AT_AL + off) = lo;
    }
    CP_WAIT(0);
    __syncthreads();

    // build B [128 n][64 d] swizzled from S1
    {
        union { __half hh[8]; uint4 u; } pk;
        const int n = tid;
        #pragma unroll
        for (int j = 0; j < 8; j++) {
            #pragma unroll
            for (int d2 = 0; d2 < 8; d2++)
                pk.hh[d2] = S1[(j * 8 + d2) * 144 + n];
            *(uint4*)(smem + AT_B + SWZ128((uint32_t)(n * 128 + j * 16))) = pk.u;
        }
    }
    __syncthreads();

    // mma: M=80 (5 tiles), N=32 per warp (4 n8-tiles), K=64 (4 steps)
    float acc[5][4][4];
    #pragma unroll
    for (int m = 0; m < 5; m++)
        #pragma unroll
        for (int nt = 0; nt < 4; nt++)
            #pragma unroll
            for (int e = 0; e < 4; e++) acc[m][nt][e] = 0.f;

    const int a_row  = lane & 15;
    const int a_coff = (lane >> 4) * 16;
    const int b_coff = ((lane >> 3) & 1) * 16;

    #pragma unroll
    for (int ks = 0; ks < 4; ks++) {
        uint32_t ah[5][4], al[5][4], bfr[4][2];
        #pragma unroll
        for (int m = 0; m < 5; m++) {
            const uint32_t so = SWZ128((uint32_t)((m * 16 + a_row) * 128 + ks * 32 + a_coff));
            ldmatrix_x4(ah[m], sbase + AT_AH + so);
            ldmatrix_x4(al[m], sbase + AT_AL + so);
        }
        #pragma unroll
        for (int g = 0; g < 2; g++) {
            const int brow = wid * 32 + g * 16 + ((lane >> 4) << 3) + (lane & 7);
            uint32_t r[4];
            ldmatrix_x4(r, sbase + AT_B + SWZ128((uint32_t)(brow * 128 + ks * 32 + b_coff)));
            bfr[g * 2][0] = r[0];  bfr[g * 2][1] = r[1];
            bfr[g * 2 + 1][0] = r[2];  bfr[g * 2 + 1][1] = r[3];
        }
        #pragma unroll
        for (int m = 0; m < 5; m++)
            #pragma unroll
            for (int nt = 0; nt < 4; nt++) {
                mma_f16(acc[m][nt], ah[m], bfr[nt]);
                mma_f16(acc[m][nt], al[m], bfr[nt]);
            }
    }

    // normalize + stage to sOut [n][e] (pitch 72 halves)
    #pragma unroll
    for (int nt = 0; nt < 4; nt++) {
        float den0 = __shfl_sync(0xffffffffu, acc[4][nt][0], lane & 3);
        float den1 = __shfl_sync(0xffffffffu, acc[4][nt][1], lane & 3);
        float inv0 = 1.f / (den0 + EPS);
        float inv1 = 1.f / (den1 + EPS);
        const int n = wid * 32 + nt * 8 + 2 * (lane & 3);
        #pragma unroll
        for (int m = 0; m < 4; m++) {
            const int e = m * 16 + (lane >> 2);
            sOut[n * 72 + e]           = __float2half_rn(acc[m][nt][0] * inv0);
            sOut[(n + 1) * 72 + e]     = __float2half_rn(acc[m][nt][1] * inv1);
            sOut[n * 72 + e + 8]       = __float2half_rn(acc[m][nt][2] * inv0);
            sOut[(n + 1) * 72 + e + 8] = __float2half_rn(acc[m][nt][3] * inv1);
        }
    }
    __syncthreads();

    // coalesced store: thread = n row, 64 halves (128 B)
    {
        const int n = tid;
        __half* dst = ao + ((size_t)b * NN + n0 + n) * CC + h * HD;
        #pragma unroll
        for (int j = 0; j < 8; j++)
            *(uint4*)(dst + j * 8) = *(uint4*)(sOut + n * 72 + j * 8);
    }
}

// ---------------------------------------------------------------------------
extern "C" void kernel_launch(void* const* d_in, const int* in_sizes, int n_in,
                              void* d_out, int out_size)
{
    const float* x    = (const float*)d_in[0];
    const float* pos  = (const float*)d_in[1];
    const float* w_qk = (const float*)d_in[2];
    const float* w_v  = (const float*)d_in[3];
    const float* w_o  = (const float*)d_in[4];
    float* out = (float*)d_out;

    __half *qk, *v;
    float *kvp, *kvr;
    cudaGetSymbolAddress((void**)&qk,  g_qkh);
    cudaGetSymbolAddress((void**)&v,   g_vh);
    cudaGetSymbolAddress((void**)&kvp, g_kvp);
    cudaGetSymbolAddress((void**)&kvr, g_kv);
    __half *xq, *xv, *ao;
    __half *wqh, *wql, *wvh, *wvl, *woh, *wol;
    cudaGetSymbolAddress((void**)&xq, g_xq);
    cudaGetSymbolAddress((void**)&xv, g_xv);
    cudaGetSymbolAddress((void**)&ao, g_ao);
    cudaGetSymbolAddress((void**)&wqh, g_wqk_hi); cudaGetSymbolAddress((void**)&wql, g_wqk_lo);
    cudaGetSymbolAddress((void**)&wvh, g_wv_hi);  cudaGetSymbolAddress((void**)&wvl, g_wv_lo);
    cudaGetSymbolAddress((void**)&woh, g_wo_hi);  cudaGetSymbolAddress((void**)&wol, g_wo_lo);

    cudaFuncSetAttribute(gemm_tc<true, true>,
                         cudaFuncAttributeMaxDynamicSharedMemorySize, GEMM_SMEM);
    cudaFuncSetAttribute(gemm_tc<false, true>,
                         cudaFuncAttributeMaxDynamicSharedMemorySize, GEMM_SMEM);
    cudaFuncSetAttribute(gemm_tc<false, false>,
                         cudaFuncAttributeMaxDynamicSharedMemorySize, GEMM_SMEM);
    cudaFuncSetAttribute(attn_tc_kernel,
                         cudaFuncAttributeMaxDynamicSharedMemorySize, ATTN_SMEM);

    // 0) weight splits (x512 scaled fp16 hi/lo)
    conv_w_kernel<<<(1024 * 512 + 255) / 256, 256>>>(w_qk, wqh, wql, 1024 * 512);
    conv_w_kernel<<<(512 * 512 + 255) / 256, 256>>>(w_v, wvh, wvl, 512 * 512);
    conv_w_kernel<<<(512 * 512 + 255) / 256, 256>>>(w_o, woh, wol, 512 * 512);

    // 1) x / x+pos -> transposed fp16
    conv_xt_kernel<<<dim3(NN / 64, CC / 64, BB), 256>>>(x, pos, xq, xv);

    // 2) qk = relu(w_qk @ (x+pos)) -> fp16
    gemm_tc<true, true><<<dim3(NN / 256, 1024 / 128, BB), 512, GEMM_SMEM>>>(
        wqh, wql, xq, qk, 1024);

    // 3) v = w_v @ x -> fp16
    gemm_tc<false, true><<<dim3(NN / 256, 512 / 128, BB), 512, GEMM_SMEM>>>(
        wvh, wvl, xv, v, 512);

    // 4) kv (tensor) + reduce
    kv_tc_kernel<<<dim3(8, 128), 128>>>(qk, v, kvp);
    kv_reduce<<<(128 * 4160 + 255) / 256, 256>>>(kvp, kvr);

    // 5) attn (tensor) -> fp16 transposed [B][N][C]
    attn_tc_kernel<<<dim3(NN / 128, 128), 128, ATTN_SMEM>>>(qk, kvr, ao);

    // 6) out = w_o @ attn -> fp32 (d_out)
    gemm_tc<false, false><<<dim3(NN / 256, 512 / 128, BB), 512, GEMM_SMEM>>>(
        woh, wol, ao, out, 512);
}

// round 6
// speedup vs baseline: 5.9315x; 1.4947x over previous
#include <cuda_runtime.h>
#include <cuda_fp16.h>
#include <cstdint>
#include <cstddef>

// Problem constants
#define BB   16
#define CC   512
#define NN   4096
#define NH   8
#define HD   64
#define EPS  1e-6f

// ---------------------------------------------------------------------------
// Scratch (device globals: allocation-free rule)
// ---------------------------------------------------------------------------
__device__ __half g_qkh[(size_t)BB * 2 * CC * NN]; // [B][1024][4096] relu(qk) fp16
__device__ __half g_vh [(size_t)BB * CC * NN];     // [B][512][4096] v fp16
__device__ float g_kvp[(size_t)8 * 128 * 65 * 64]; // split-K partials for kv
__device__ float g_kv [(size_t)128 * 65 * 64];     // [B*nh][65][64] fp32

// fp16 activations, [B][N][C] K-major
__device__ __half g_xq[(size_t)BB * NN * CC];      // x + pos
__device__ __half g_xv[(size_t)BB * NN * CC];      // x
__device__ __half g_ao[(size_t)BB * NN * CC];      // attn output (transposed)
// weights fp16, [O][C] K-major
__device__ __half g_wqk[1024 * 512];
__device__ __half g_wv [512 * 512];
__device__ __half g_wo [512 * 512];

// ---------------------------------------------------------------------------
// Helpers
// ---------------------------------------------------------------------------
__device__ __forceinline__ uint32_t smem_u32(const void* p) {
    uint32_t a;
    asm("{ .reg .u64 t; cvta.to.shared.u64 t, %1; cvt.u32.u64 %0, t; }" : "=r"(a) : "l"(p));
    return a;
}
#define SWZ128(off) ((off) ^ (((off) >> 3) & 0x70))
#define ONES2 0x3C003C00u

__device__ __forceinline__ void cp_async16(uint32_t s, const void* g) {
    asm volatile("cp.async.cg.shared.global [%0], [%1], 16;" :: "r"(s), "l"(g));
}
#define CP_COMMIT() asm volatile("cp.async.commit_group;" ::: "memory")
#define CP_WAIT(n)  asm volatile("cp.async.wait_group %0;" :: "n"(n) : "memory")

__device__ __forceinline__ void ldmatrix_x4(uint32_t* r, uint32_t addr) {
    asm volatile("ldmatrix.sync.aligned.m8n8.x4.shared.b16 {%0,%1,%2,%3}, [%4];"
                 : "=r"(r[0]), "=r"(r[1]), "=r"(r[2]), "=r"(r[3]) : "r"(addr));
}
__device__ __forceinline__ void mma_f16(float* d, const uint32_t* a, const uint32_t* b) {
    asm volatile(
        "mma.sync.aligned.m16n8k16.row.col.f32.f16.f16.f32 "
        "{%0,%1,%2,%3}, {%4,%5,%6,%7}, {%8,%9}, {%0,%1,%2,%3};"
        : "+f"(d[0]), "+f"(d[1]), "+f"(d[2]), "+f"(d[3])
        : "r"(a[0]), "r"(a[1]), "r"(a[2]), "r"(a[3]), "r"(b[0]), "r"(b[1]));
}

// ---------------------------------------------------------------------------
// Tensor-core projection GEMM:  Y[O,N] = W[O,C] @ X[C,N]
//   A = W [O][C] fp16 K-major; B = Xt [N][C] fp16 K-major.
// BM=128, BN=256, BK=64, 512 threads, 3 stages. HOUT: fp16 output.
// ---------------------------------------------------------------------------
#define BKB 128
#define B_OFF  16384
#define STG    49152
#define GEMM_SMEM (3 * STG)

template<bool RELU, bool HOUT>
__global__ __launch_bounds__(512, 1) void gemm_tc(
    const __half* __restrict__ A, const __half* __restrict__ Bx,
    void* __restrict__ Yv, int O)
{
    extern __shared__ __align__(1024) char smem[];
    const uint32_t sbase = smem_u32(smem);
    const int tid  = threadIdx.x;
    const int wid  = tid >> 5;
    const int lane = tid & 31;
    const int wm   = wid & 1;
    const int wn   = wid >> 1;

    const int n0 = blockIdx.x * 256;
    const int o0 = blockIdx.y * 128;
    const int bz = blockIdx.z;

    const __half* Bb = Bx + (size_t)bz * NN * CC;

    auto load_stage = [&](int ck, int st) {
        const int k0 = ck * 64;
        const uint32_t sb = sbase + st * STG;
        #pragma unroll
        for (int i = 0; i < 2; i++) {            // A: 128 rows x 128B
            int c = tid + i * 512;
            int row = c >> 3, cc = c & 7;
            cp_async16(sb + SWZ128((uint32_t)(row * BKB + cc * 16)),
                       A + (size_t)(o0 + row) * CC + k0 + cc * 8);
        }
        #pragma unroll
        for (int i = 0; i < 4; i++) {            // B: 256 rows x 128B
            int c = tid + i * 512;
            int row = c >> 3, cc = c & 7;
            cp_async16(sb + B_OFF + SWZ128((uint32_t)(row * BKB + cc * 16)),
                       Bb + (size_t)(n0 + row) * CC + k0 + cc * 8);
        }
        CP_COMMIT();
    };

    float acc[4][4][4];
    #pragma unroll
    for (int mf = 0; mf < 4; mf++)
        #pragma unroll
        for (int nf = 0; nf < 4; nf++)
            #pragma unroll
            for (int e = 0; e < 4; e++) acc[mf][nf][e] = 0.f;

    load_stage(0, 0);
    load_stage(1, 1);
    CP_WAIT(1);
    __syncthreads();

    const int a_row  = wm * 64 + (lane & 15);
    const int a_coff = (lane >> 4) * 16;
    const int b_row  = wn * 32 + ((lane >> 4) << 3) + (lane & 7);
    const int b_coff = ((lane >> 3) & 1) * 16;

    for (int it = 0; it < 8; it++) {
        const uint32_t sb = sbase + (it % 3) * STG;
        #pragma unroll
        for (int kk = 0; kk < 4; kk++) {
            uint32_t a[4][4], b[4][2];
            #pragma unroll
            for (int mf = 0; mf < 4; mf++)
                ldmatrix_x4(a[mf], sb +
                            SWZ128((uint32_t)((a_row + mf * 16) * BKB + kk * 32 + a_coff)));
            #pragma unroll
            for (int np = 0; np < 2; np++) {
                uint32_t r[4];
                ldmatrix_x4(r, sb + B_OFF +
                            SWZ128((uint32_t)((b_row + np * 16) * BKB + kk * 32 + b_coff)));
                b[np * 2][0] = r[0];  b[np * 2][1] = r[1];
                b[np * 2 + 1][0] = r[2];  b[np * 2 + 1][1] = r[3];
            }
            #pragma unroll
            for (int mf = 0; mf < 4; mf++)
                #pragma unroll
                for (int nf = 0; nf < 4; nf++)
                    mma_f16(acc[mf][nf], a[mf], b[nf]);
        }
        if (it + 2 < 8) {
            load_stage(it + 2, (it + 2) % 3);
            CP_WAIT(1);
        } else {
            CP_WAIT(0);
        }
        __syncthreads();
    }

    const int er = lane >> 2;
    const int ec = (lane & 3) * 2;
    #pragma unroll
    for (int mf = 0; mf < 4; mf++) {
        #pragma unroll
        for (int nf = 0; nf < 4; nf++) {
            const int orow = o0 + wm * 64 + mf * 16 + er;
            const int ocol = n0 + wn * 32 + nf * 8 + ec;
            float v0x = acc[mf][nf][0], v0y = acc[mf][nf][1];
            float v1x = acc[mf][nf][2], v1y = acc[mf][nf][3];
            if (RELU) {
                v0x = fmaxf(v0x, 0.f); v0y = fmaxf(v0y, 0.f);
                v1x = fmaxf(v1x, 0.f); v1y = fmaxf(v1y, 0.f);
            }
            if (HOUT) {
                __half* Yb = (__half*)Yv + (size_t)bz * O * NN;
                *(__half2*)&Yb[(size_t)orow * NN + ocol] =
                    __floats2half2_rn(v0x, v0y);
                *(__half2*)&Yb[(size_t)(orow + 8) * NN + ocol] =
                    __floats2half2_rn(v1x, v1y);
            } else {
                float* Yb = (float*)Yv + (size_t)bz * O * NN;
                *(float2*)&Yb[(size_t)orow * NN + ocol]       = make_float2(v0x, v0y);
                *(float2*)&Yb[(size_t)(orow + 8) * NN + ocol] = make_float2(v1x, v1y);
            }
        }
    }
}

// ---------------------------------------------------------------------------
// Weight convert: fp32 -> fp16
// ---------------------------------------------------------------------------
__global__ void conv_w_kernel(const float* __restrict__ in,
                              __half* __restrict__ w, int n)
{
    int i = blockIdx.x * 256 + threadIdx.x;
    if (i < n) w[i] = __float2half_rn(in[i]);
}

// ---------------------------------------------------------------------------
// Transpose + fp16 convert: x, pos [B][C][N] fp32 -> xq=(x+pos), xv=x  [B][N][C]
// ---------------------------------------------------------------------------
__global__ __launch_bounds__(256) void conv_xt_kernel(
    const float* __restrict__ x, const float* __restrict__ pos,
    __half* __restrict__ xq, __half* __restrict__ xv)
{
    __shared__ float sA[64][65];
    __shared__ float sB[64][65];

    const int tid = threadIdx.x;
    const int n0 = blockIdx.x * 64;
    const int c0 = blockIdx.y * 64;
    const int bz = blockIdx.z;

    const float* i0 = x   + (size_t)bz * CC * NN;
    const float* i1 = pos + (size_t)bz * CC * NN;

    #pragma unroll
    for (int i = 0; i < 16; i++) {
        int idx = i * 256 + tid;
        int rc = idx >> 6, cn = idx & 63;
        float xv_ = i0[(size_t)(c0 + rc) * NN + n0 + cn];
        float pv  = i1[(size_t)(c0 + rc) * NN + n0 + cn];
        sA[rc][cn] = xv_ + pv;
        sB[rc][cn] = xv_;
    }
    __syncthreads();

    const size_t obase = ((size_t)bz * NN + n0) * CC + c0;
    #pragma unroll
    for (int i = 0; i < 8; i++) {
        int idx = i * 256 + tid;
        int nr = idx >> 5, cp = idx & 31;
        size_t oa = obase + (size_t)nr * CC + cp * 2;
        __half2 hq, hv;
        hq.x = __float2half_rn(sA[cp * 2][nr]);
        hq.y = __float2half_rn(sA[cp * 2 + 1][nr]);
        hv.x = __float2half_rn(sB[cp * 2][nr]);
        hv.y = __float2half_rn(sB[cp * 2 + 1][nr]);
        *(__half2*)(xq + oa) = hq;
        *(__half2*)(xv + oa) = hv;
    }
}

// ---------------------------------------------------------------------------
// kv (tensor cores): kv[e,d] = sum_n v[e,n]*k[d,n] (+ ksum row via ones-A).
// grid (8 chunks, 128 bh), 128 threads (4 warps). K-range 512 per block.
// ---------------------------------------------------------------------------
__global__ __launch_bounds__(128) void kv_tc_kernel(
    const __half* __restrict__ qk, const __half* __restrict__ v,
    float* __restrict__ kvp)
{
    __shared__ __align__(1024) char smem[32768];   // 2 stages x (v 8KB + k 8KB)
    const uint32_t sbase = smem_u32(smem);

    const int tid   = threadIdx.x;
    const int wid   = tid >> 5;
    const int lane  = tid & 31;
    const int chunk = blockIdx.x;
    const int bh    = blockIdx.y;
    const int b = bh >> 3, h = bh & 7;

    const __half* kbase = qk + ((size_t)b * 2 * CC + CC + h * HD) * NN;
    const __half* vbase = v  + ((size_t)b * CC + h * HD) * NN;

    auto load_sub = [&](int sub, int st) {
        const int n0 = chunk * 512 + sub * 64;
        const uint32_t sb = sbase + st * 16384;
        #pragma unroll
        for (int i = 0; i < 4; i++) {
            int idx = tid + i * 128;
            int row = idx >> 3, c = idx & 7;
            const uint32_t so = SWZ128((uint32_t)(row * 128 + c * 16));
            cp_async16(sb +        so, vbase + (size_t)row * NN + n0 + c * 8);
            cp_async16(sb + 8192 + so, kbase + (size_t)row * NN + n0 + c * 8);
        }
        CP_COMMIT();
    };

    float acc[5][2][4];
    #pragma unroll
    for (int m = 0; m < 5; m++)
        #pragma unroll
        for (int nt = 0; nt < 2; nt++)
            #pragma unroll
            for (int e = 0; e < 4; e++) acc[m][nt][e] = 0.f;

    const int a_row  = lane & 15;
    const int a_coff = (lane >> 4) * 16;
    const int b_row  = wid * 16 + ((lane >> 4) << 3) + (lane & 7);
    const int b_coff = ((lane >> 3) & 1) * 16;
    const uint32_t ones[4] = {ONES2, ONES2, ONES2, ONES2};

    load_sub(0, 0);
    for (int sub = 0; sub < 8; sub++) {
        if (sub + 1 < 8) { load_sub(sub + 1, (sub + 1) & 1); CP_WAIT(1); }
        else             { CP_WAIT(0); }
        __syncthreads();
        const uint32_t sv = sbase + (sub & 1) * 16384;
        const uint32_t sk = sv + 8192;
        #pragma unroll
        for (int ks = 0; ks < 4; ks++) {
            uint32_t a[4][4];
            #pragma unroll
            for (int m = 0; m < 4; m++)
                ldmatrix_x4(a[m], sv + SWZ128((uint32_t)((m * 16 + a_row) * 128 + ks * 32 + a_coff)));
            uint32_t bf[4];
            ldmatrix_x4(bf, sk + SWZ128((uint32_t)(b_row * 128 + ks * 32 + b_coff)));
            uint32_t b0[2] = {bf[0], bf[1]}, b1[2] = {bf[2], bf[3]};
            #pragma unroll
            for (int m = 0; m < 4; m++) {
                mma_f16(acc[m][0], a[m], b0);
                mma_f16(acc[m][1], a[m], b1);
            }
            mma_f16(acc[4][0], ones, b0);
            mma_f16(acc[4][1], ones, b1);
        }
        __syncthreads();
    }

    float* outb = kvp + (size_t)chunk * (128 * 4160) + (size_t)bh * 4160;
    #pragma unroll
    for (int m = 0; m < 4; m++)
        #pragma unroll
        for (int nt = 0; nt < 2; nt++) {
            const int e = m * 16 + (lane >> 2);
            const int d = wid * 16 + nt * 8 + 2 * (lane & 3);
            *(float2*)&outb[e * 64 + d]       = make_float2(acc[m][nt][0], acc[m][nt][1]);
            *(float2*)&outb[(e + 8) * 64 + d] = make_float2(acc[m][nt][2], acc[m][nt][3]);
        }
    if (lane < 4) {
        #pragma unroll
        for (int nt = 0; nt < 2; nt++) {
            const int d = wid * 16 + nt * 8 + 2 * lane;
            *(float2*)&outb[4096 + d] = make_float2(acc[4][nt][0], acc[4][nt][1]);
        }
    }
}

__global__ void kv_reduce(const float* __restrict__ kvp, float* __restrict__ kvout)
{
    int i = blockIdx.x * 256 + threadIdx.x;
    if (i < 128 * 4160) {
        float s = 0.f;
        #pragma unroll
        for (int c = 0; c < 8; c++) s += kvp[(size_t)c * (128 * 4160) + i];
        kvout[i] = s;
    }
}

// ---------------------------------------------------------------------------
// attn (tensor cores): out[e,n] = (kv @ q)[e,n] / (ksum@q[n] + EPS)
// A = kv hi/lo fp16 [80][64] (row64 = ksum), B = q^T [128 n][64 d].
// grid (NN/128, 128 bh), 128 threads. Output fp16 transposed [B][N][C].
// ---------------------------------------------------------------------------
#define AT_AH 0
#define AT_AL 10240
#define AT_B  20480
#define AT_SCR 36864           // q stage [64][144]h then sOut [128][72]h
#define ATTN_SMEM 55296

__global__ __launch_bounds__(128) void attn_tc_kernel(
    const __half* __restrict__ qk, const float* __restrict__ kv,
    __half* __restrict__ ao)
{
    extern __shared__ __align__(1024) char smem[];
    const uint32_t sbase = smem_u32(smem);
    __half* S1   = (__half*)(smem + AT_SCR);
    __half* sOut = (__half*)(smem + AT_SCR);

    const int tid  = threadIdx.x;
    const int wid  = tid >> 5;
    const int lane = tid & 31;
    const int bh   = blockIdx.y;
    const int b = bh >> 3, h = bh & 7;
    const int n0 = blockIdx.x * 128;

    // async load q tile [64 d][128 n] -> S1 (pitch 144 halves)
    const __half* qbase = qk + ((size_t)b * 2 * CC + h * HD) * NN + n0;
    #pragma unroll
    for (int i = 0; i < 8; i++) {
        int idx = tid + i * 128;
        int d = idx >> 4, j = idx & 15;
        cp_async16(sbase + AT_SCR + (uint32_t)(d * 288 + j * 16),
                   qbase + (size_t)d * NN + j * 8);
    }
    CP_COMMIT();

    // zero A hi/lo (80 rows incl. pad), then fill rows 0..64 from kv fp32
    {
        uint4 z = {0, 0, 0, 0};
        for (int i = tid; i < 1280; i += 128) {
            *(uint4*)(smem + AT_AH + i * 16) = z;
        }
    }
    __syncthreads();
    const float* kvb = kv + (size_t)bh * 4160;
    for (int i = tid; i < 4160; i += 128) {
        int e = i >> 6, d = i & 63;
        float f = kvb[i];
        __half hi = __float2half_rn(f);
        __half lo = __float2half_rn(f - __half2float(hi));
        uint32_t off = SWZ128((uint32_t)(e * 128 + d * 2));
        *(__half*)(smem + AT_AH + off) = hi;
        *(__half*)(smem + AT_AL + off) = lo;
    }
    CP_WAIT(0);
    __syncthreads();

    // build B [128 n][64 d] swizzled from S1
    {
        union { __half hh[8]; uint4 u; } pk;
        const int n = tid;
        #pragma unroll
        for (int j = 0; j < 8; j++) {
            #pragma unroll
            for (int d2 = 0; d2 < 8; d2++)
                pk.hh[d2] = S1[(j * 8 + d2) * 144 + n];
            *(uint4*)(smem + AT_B + SWZ128((uint32_t)(n * 128 + j * 16))) = pk.u;
        }
    }
    __syncthreads();

    // mma: M=80 (5 tiles), N=32 per warp (4 n8-tiles), K=64 (4 steps)
    float acc[5][4][4];
    #pragma unroll
    for (int m = 0; m < 5; m++)
        #pragma unroll
        for (int nt = 0; nt < 4; nt++)
            #pragma unroll
            for (int e = 0; e < 4; e++) acc[m][nt][e] = 0.f;

    const int a_row  = lane & 15;
    const int a_coff = (lane >> 4) * 16;
    const int b_coff = ((lane >> 3) & 1) * 16;

    #pragma unroll
    for (int ks = 0; ks < 4; ks++) {
        uint32_t ah[5][4], al[5][4], bfr[4][2];
        #pragma unroll
        for (int m = 0; m < 5; m++) {
            const uint32_t so = SWZ128((uint32_t)((m * 16 + a_row) * 128 + ks * 32 + a_coff));
            ldmatrix_x4(ah[m], sbase + AT_AH + so);
            ldmatrix_x4(al[m], sbase + AT_AL + so);
        }
        #pragma unroll
        for (int g = 0; g < 2; g++) {
            const int brow = wid * 32 + g * 16 + ((lane >> 4) << 3) + (lane & 7);
            uint32_t r[4];
            ldmatrix_x4(r, sbase + AT_B + SWZ128((uint32_t)(brow * 128 + ks * 32 + b_coff)));
            bfr[g * 2][0] = r[0];  bfr[g * 2][1] = r[1];
            bfr[g * 2 + 1][0] = r[2];  bfr[g * 2 + 1][1] = r[3];
        }
        #pragma unroll
        for (int m = 0; m < 5; m++)
            #pragma unroll
            for (int nt = 0; nt < 4; nt++) {
                mma_f16(acc[m][nt], ah[m], bfr[nt]);
                mma_f16(acc[m][nt], al[m], bfr[nt]);
            }
    }

    // normalize + stage to sOut [n][e] (pitch 72 halves)
    #pragma unroll
    for (int nt = 0; nt < 4; nt++) {
        float den0 = __shfl_sync(0xffffffffu, acc[4][nt][0], lane & 3);
        float den1 = __shfl_sync(0xffffffffu, acc[4][nt][1], lane & 3);
        float inv0 = 1.f / (den0 + EPS);
        float inv1 = 1.f / (den1 + EPS);
        const int n = wid * 32 + nt * 8 + 2 * (lane & 3);
        #pragma unroll
        for (int m = 0; m < 4; m++) {
            const int e = m * 16 + (lane >> 2);
            sOut[n * 72 + e]           = __float2half_rn(acc[m][nt][0] * inv0);
            sOut[(n + 1) * 72 + e]     = __float2half_rn(acc[m][nt][1] * inv1);
            sOut[n * 72 + e + 8]       = __float2half_rn(acc[m][nt][2] * inv0);
            sOut[(n + 1) * 72 + e + 8] = __float2half_rn(acc[m][nt][3] * inv1);
        }
    }
    __syncthreads();

    // coalesced store: thread = n row, 64 halves (128 B)
    {
        const int n = tid;
        __half* dst = ao + ((size_t)b * NN + n0 + n) * CC + h * HD;
        #pragma unroll
        for (int j = 0; j < 8; j++)
            *(uint4*)(dst + j * 8) = *(uint4*)(sOut + n * 72 + j * 8);
    }
}

// ---------------------------------------------------------------------------
extern "C" void kernel_launch(void* const* d_in, const int* in_sizes, int n_in,
                              void* d_out, int out_size)
{
    const float* x    = (const float*)d_in[0];
    const float* pos  = (const float*)d_in[1];
    const float* w_qk = (const float*)d_in[2];
    const float* w_v  = (const float*)d_in[3];
    const float* w_o  = (const float*)d_in[4];
    float* out = (float*)d_out;

    __half *qk, *v;
    float *kvp, *kvr;
    cudaGetSymbolAddress((void**)&qk,  g_qkh);
    cudaGetSymbolAddress((void**)&v,   g_vh);
    cudaGetSymbolAddress((void**)&kvp, g_kvp);
    cudaGetSymbolAddress((void**)&kvr, g_kv);
    __half *xq, *xv, *ao, *wq, *wv, *wo;
    cudaGetSymbolAddress((void**)&xq, g_xq);
    cudaGetSymbolAddress((void**)&xv, g_xv);
    cudaGetSymbolAddress((void**)&ao, g_ao);
    cudaGetSymbolAddress((void**)&wq, g_wqk);
    cudaGetSymbolAddress((void**)&wv, g_wv);
    cudaGetSymbolAddress((void**)&wo, g_wo);

    cudaFuncSetAttribute(gemm_tc<true, true>,
                         cudaFuncAttributeMaxDynamicSharedMemorySize, GEMM_SMEM);
    cudaFuncSetAttribute(gemm_tc<false, true>,
                         cudaFuncAttributeMaxDynamicSharedMemorySize, GEMM_SMEM);
    cudaFuncSetAttribute(gemm_tc<false, false>,
                         cudaFuncAttributeMaxDynamicSharedMemorySize, GEMM_SMEM);
    cudaFuncSetAttribute(attn_tc_kernel,
                         cudaFuncAttributeMaxDynamicSharedMemorySize, ATTN_SMEM);

    // 0) weight converts (fp16)
    conv_w_kernel<<<(1024 * 512 + 255) / 256, 256>>>(w_qk, wq, 1024 * 512);
    conv_w_kernel<<<(512 * 512 + 255) / 256, 256>>>(w_v, wv, 512 * 512);
    conv_w_kernel<<<(512 * 512 + 255) / 256, 256>>>(w_o, wo, 512 * 512);

    // 1) x / x+pos -> transposed fp16
    conv_xt_kernel<<<dim3(NN / 64, CC / 64, BB), 256>>>(x, pos, xq, xv);

    // 2) qk = relu(w_qk @ (x+pos)) -> fp16
    gemm_tc<true, true><<<dim3(NN / 256, 1024 / 128, BB), 512, GEMM_SMEM>>>(
        wq, xq, qk, 1024);

    // 3) v = w_v @ x -> fp16
    gemm_tc<false, true><<<dim3(NN / 256, 512 / 128, BB), 512, GEMM_SMEM>>>(
        wv, xv, v, 512);

    // 4) kv (tensor) + reduce
    kv_tc_kernel<<<dim3(8, 128), 128>>>(qk, v, kvp);
    kv_reduce<<<(128 * 4160 + 255) / 256, 256>>>(kvp, kvr);

    // 5) attn (tensor) -> fp16 transposed [B][N][C]
    attn_tc_kernel<<<dim3(NN / 128, 128), 128, ATTN_SMEM>>>(qk, kvr, ao);

    // 6) out = w_o @ attn -> fp32 (d_out)
    gemm_tc<false, false><<<dim3(NN / 256, 512 / 128, BB), 512, GEMM_SMEM>>>(
        wo, ao, out, 512);
}

// round 7
// speedup vs baseline: 5.9928x; 1.0103x over previous
#include <cuda_runtime.h>
#include <cuda_fp16.h>
#include <cstdint>
#include <cstddef>

// Problem constants
#define BB   16
#define CC   512
#define NN   4096
#define NH   8
#define HD   64
#define EPS  1e-6f

// ---------------------------------------------------------------------------
// Scratch (device globals: allocation-free rule)
// ---------------------------------------------------------------------------
__device__ __half g_qkh[(size_t)BB * 2 * CC * NN]; // [B][1024][4096] relu(qk) fp16
__device__ float g_kvp[(size_t)32 * 128 * 65 * 64];// split-K partials (32 chunks)
__device__ float g_kv [(size_t)128 * 65 * 64];     // [B*nh][65][64] fp32

// fp16 activations, [B][N][C] K-major
__device__ __half g_xq[(size_t)BB * NN * CC];      // x + pos
__device__ __half g_xv[(size_t)BB * NN * CC];      // x
__device__ __half g_ao[(size_t)BB * NN * CC];      // attn output (transposed)
// weights fp16, [O][C] K-major
__device__ __half g_wqk[1024 * 512];
__device__ __half g_wv [512 * 512];
__device__ __half g_wo [512 * 512];

// ---------------------------------------------------------------------------
// Helpers
// ---------------------------------------------------------------------------
__device__ __forceinline__ uint32_t smem_u32(const void* p) {
    uint32_t a;
    asm("{ .reg .u64 t; cvta.to.shared.u64 t, %1; cvt.u32.u64 %0, t; }" : "=r"(a) : "l"(p));
    return a;
}
#define SWZ128(off) ((off) ^ (((off) >> 3) & 0x70))
#define ONES2 0x3C003C00u

__device__ __forceinline__ void cp_async16(uint32_t s, const void* g) {
    asm volatile("cp.async.cg.shared.global [%0], [%1], 16;" :: "r"(s), "l"(g));
}
#define CP_COMMIT() asm volatile("cp.async.commit_group;" ::: "memory")
#define CP_WAIT(n)  asm volatile("cp.async.wait_group %0;" :: "n"(n) : "memory")

__device__ __forceinline__ void ldmatrix_x4(uint32_t* r, uint32_t addr) {
    asm volatile("ldmatrix.sync.aligned.m8n8.x4.shared.b16 {%0,%1,%2,%3}, [%4];"
                 : "=r"(r[0]), "=r"(r[1]), "=r"(r[2]), "=r"(r[3]) : "r"(addr));
}
__device__ __forceinline__ void mma_f16(float* d, const uint32_t* a, const uint32_t* b) {
    asm volatile(
        "mma.sync.aligned.m16n8k16.row.col.f32.f16.f16.f32 "
        "{%0,%1,%2,%3}, {%4,%5,%6,%7}, {%8,%9}, {%0,%1,%2,%3};"
        : "+f"(d[0]), "+f"(d[1]), "+f"(d[2]), "+f"(d[3])
        : "r"(a[0]), "r"(a[1]), "r"(a[2]), "r"(a[3]), "r"(b[0]), "r"(b[1]));
}

#define BKB 128
#define B_OFF  16384
#define STG    49152
#define GEMM_SMEM (3 * STG)

// ---------------------------------------------------------------------------
// qk / o projection GEMM (as R6): Y[O,N] = W[O,C] @ X[C,N]
// ---------------------------------------------------------------------------
template<bool RELU, bool HOUT>
__global__ __launch_bounds__(512, 1) void gemm_tc(
    const __half* __restrict__ A, const __half* __restrict__ Bx,
    void* __restrict__ Yv, int O)
{
    extern __shared__ __align__(1024) char smem[];
    const uint32_t sbase = smem_u32(smem);
    const int tid  = threadIdx.x;
    const int wid  = tid >> 5;
    const int lane = tid & 31;
    const int wm   = wid & 1;
    const int wn   = wid >> 1;

    const int n0 = blockIdx.x * 256;
    const int o0 = blockIdx.y * 128;
    const int bz = blockIdx.z;

    const __half* Bb = Bx + (size_t)bz * NN * CC;

    auto load_stage = [&](int ck, int st) {
        const int k0 = ck * 64;
        const uint32_t sb = sbase + st * STG;
        #pragma unroll
        for (int i = 0; i < 2; i++) {
            int c = tid + i * 512;
            int row = c >> 3, cc = c & 7;
            cp_async16(sb + SWZ128((uint32_t)(row * BKB + cc * 16)),
                       A + (size_t)(o0 + row) * CC + k0 + cc * 8);
        }
        #pragma unroll
        for (int i = 0; i < 4; i++) {
            int c = tid + i * 512;
            int row = c >> 3, cc = c & 7;
            cp_async16(sb + B_OFF + SWZ128((uint32_t)(row * BKB + cc * 16)),
                       Bb + (size_t)(n0 + row) * CC + k0 + cc * 8);
        }
        CP_COMMIT();
    };

    float acc[4][4][4];
    #pragma unroll
    for (int mf = 0; mf < 4; mf++)
        #pragma unroll
        for (int nf = 0; nf < 4; nf++)
            #pragma unroll
            for (int e = 0; e < 4; e++) acc[mf][nf][e] = 0.f;

    load_stage(0, 0);
    load_stage(1, 1);
    CP_WAIT(1);
    __syncthreads();

    const int a_row  = wm * 64 + (lane & 15);
    const int a_coff = (lane >> 4) * 16;
    const int b_row  = wn * 32 + ((lane >> 4) << 3) + (lane & 7);
    const int b_coff = ((lane >> 3) & 1) * 16;

    for (int it = 0; it < 8; it++) {
        const uint32_t sb = sbase + (it % 3) * STG;
        #pragma unroll
        for (int kk = 0; kk < 4; kk++) {
            uint32_t a[4][4], b[4][2];
            #pragma unroll
            for (int mf = 0; mf < 4; mf++)
                ldmatrix_x4(a[mf], sb +
                            SWZ128((uint32_t)((a_row + mf * 16) * BKB + kk * 32 + a_coff)));
            #pragma unroll
            for (int np = 0; np < 2; np++) {
                uint32_t r[4];
                ldmatrix_x4(r, sb + B_OFF +
                            SWZ128((uint32_t)((b_row + np * 16) * BKB + kk * 32 + b_coff)));
                b[np * 2][0] = r[0];  b[np * 2][1] = r[1];
                b[np * 2 + 1][0] = r[2];  b[np * 2 + 1][1] = r[3];
            }
            #pragma unroll
            for (int mf = 0; mf < 4; mf++)
                #pragma unroll
                for (int nf = 0; nf < 4; nf++)
                    mma_f16(acc[mf][nf], a[mf], b[nf]);
        }
        if (it + 2 < 8) {
            load_stage(it + 2, (it + 2) % 3);
            CP_WAIT(1);
        } else {
            CP_WAIT(0);
        }
        __syncthreads();
    }

    const int er = lane >> 2;
    const int ec = (lane & 3) * 2;
    #pragma unroll
    for (int mf = 0; mf < 4; mf++) {
        #pragma unroll
        for (int nf = 0; nf < 4; nf++) {
            const int orow = o0 + wm * 64 + mf * 16 + er;
            const int ocol = n0 + wn * 32 + nf * 8 + ec;
            float v0x = acc[mf][nf][0], v0y = acc[mf][nf][1];
            float v1x = acc[mf][nf][2], v1y = acc[mf][nf][3];
            if (RELU) {
                v0x = fmaxf(v0x, 0.f); v0y = fmaxf(v0y, 0.f);
                v1x = fmaxf(v1x, 0.f); v1y = fmaxf(v1y, 0.f);
            }
            if (HOUT) {
                __half* Yb = (__half*)Yv + (size_t)bz * O * NN;
                *(__half2*)&Yb[(size_t)orow * NN + ocol] = __floats2half2_rn(v0x, v0y);
                *(__half2*)&Yb[(size_t)(orow + 8) * NN + ocol] = __floats2half2_rn(v1x, v1y);
            } else {
                float* Yb = (float*)Yv + (size_t)bz * O * NN;
                *(float2*)&Yb[(size_t)orow * NN + ocol]       = make_float2(v0x, v0y);
                *(float2*)&Yb[(size_t)(orow + 8) * NN + ocol] = make_float2(v1x, v1y);
            }
        }
    }
}

// ---------------------------------------------------------------------------
// Fused v-GEMM + kv: computes v = Wv @ X for its [128 o][256 n] tile, keeps it
// in SMEM (fp16, the exact rounding the old path stored to global), loads the
// matching k tile, and emits kv split-K partials. No v global round trip.
// grid (16 n-chunks, 4 o-tiles, 16 b). Partial chunks = 16 x 2 K-halves = 32.
// ---------------------------------------------------------------------------
#define VP 264                 // v/k smem pitch in halves (528 B, pad 16B)
#define KV_KOFF 67584          // k tile base (128*528)

__global__ __launch_bounds__(512, 1) void gemm_v_kv(
    const __half* __restrict__ A, const __half* __restrict__ Bx,
    const __half* __restrict__ qk, float* __restrict__ kvp)
{
    extern __shared__ __align__(1024) char smem[];
    const uint32_t sbase = smem_u32(smem);
    const int tid  = threadIdx.x;
    const int wid  = tid >> 5;
    const int lane = tid & 31;
    const int wm   = wid & 1;
    const int wn   = wid >> 1;

    const int n0 = blockIdx.x * 256;
    const int o0 = blockIdx.y * 128;
    const int bz = blockIdx.z;

    const __half* Bb = Bx + (size_t)bz * NN * CC;

    auto load_stage = [&](int ck, int st) {
        const int k0 = ck * 64;
        const uint32_t sb = sbase + st * STG;
        #pragma unroll
        for (int i = 0; i < 2; i++) {
            int c = tid + i * 512;
            int row = c >> 3, cc = c & 7;
            cp_async16(sb + SWZ128((uint32_t)(row * BKB + cc * 16)),
                       A + (size_t)(o0 + row) * CC + k0 + cc * 8);
        }
        #pragma unroll
        for (int i = 0; i < 4; i++) {
            int c = tid + i * 512;
            int row = c >> 3, cc = c & 7;
            cp_async16(sb + B_OFF + SWZ128((uint32_t)(row * BKB + cc * 16)),
                       Bb + (size_t)(n0 + row) * CC + k0 + cc * 8);
        }
        CP_COMMIT();
    };

    float acc[4][4][4];
    #pragma unroll
    for (int mf = 0; mf < 4; mf++)
        #pragma unroll
        for (int nf = 0; nf < 4; nf++)
            #pragma unroll
            for (int e = 0; e < 4; e++) acc[mf][nf][e] = 0.f;

    load_stage(0, 0);
    load_stage(1, 1);
    CP_WAIT(1);
    __syncthreads();

    const int a_row  = wm * 64 + (lane & 15);
    const int a_coff = (lane >> 4) * 16;
    const int b_row  = wn * 32 + ((lane >> 4) << 3) + (lane & 7);
    const int b_coff = ((lane >> 3) & 1) * 16;

    for (int it = 0; it < 8; it++) {
        const uint32_t sb = sbase + (it % 3) * STG;
        #pragma unroll
        for (int kk = 0; kk < 4; kk++) {
            uint32_t a[4][4], b[4][2];
            #pragma unroll
            for (int mf = 0; mf < 4; mf++)
                ldmatrix_x4(a[mf], sb +
                            SWZ128((uint32_t)((a_row + mf * 16) * BKB + kk * 32 + a_coff)));
            #pragma unroll
            for (int np = 0; np < 2; np++) {
                uint32_t r[4];
                ldmatrix_x4(r, sb + B_OFF +
                            SWZ128((uint32_t)((b_row + np * 16) * BKB + kk * 32 + b_coff)));
                b[np * 2][0] = r[0];  b[np * 2][1] = r[1];
                b[np * 2 + 1][0] = r[2];  b[np * 2 + 1][1] = r[3];
            }
            #pragma unroll
            for (int mf = 0; mf < 4; mf++)
                #pragma unroll
                for (int nf = 0; nf < 4; nf++)
                    mma_f16(acc[mf][nf], a[mf], b[nf]);
        }
        if (it + 2 < 8) {
            load_stage(it + 2, (it + 2) % 3);
            CP_WAIT(1);
        } else {
            CP_WAIT(0);
        }
        __syncthreads();
    }

    // ---- epilogue: v tile (fp16) -> smem [128][VP]; k tile -> smem ----
    __half* sv = (__half*)smem;
    const int er = lane >> 2;
    const int ec = (lane & 3) * 2;
    #pragma unroll
    for (int mf = 0; mf < 4; mf++) {
        #pragma unroll
        for (int nf = 0; nf < 4; nf++) {
            const int lr = wm * 64 + mf * 16 + er;
            const int lc = wn * 32 + nf * 8 + ec;
            *(__half2*)&sv[lr * VP + lc] =
                __floats2half2_rn(acc[mf][nf][0], acc[mf][nf][1]);
            *(__half2*)&sv[(lr + 8) * VP + lc] =
                __floats2half2_rn(acc[mf][nf][2], acc[mf][nf][3]);
        }
    }
    // k tile: rows r = local channel (CC + o0 + r), 512B per row
    const __half* kb = qk + ((size_t)bz * 2 * CC + CC + o0) * NN + n0;
    #pragma unroll
    for (int i = 0; i < 8; i++) {
        int idx = tid + i * 512;
        int r = idx >> 5, c = idx & 31;
        cp_async16(sbase + KV_KOFF + (uint32_t)(r * 528 + c * 16),
                   kb + (size_t)r * NN + c * 8);
    }
    CP_COMMIT();
    CP_WAIT(0);
    __syncthreads();

    // ---- kv mma: per head (2), per warp: 16 d cols, half of K=256 ----
    const int head   = wid >> 3;        // 0..1
    const int rem    = wid & 7;
    const int dgrp   = rem >> 1;        // 0..3 (16 d each)
    const int khalf  = rem & 1;         // 0..1 (128 n each)

    float kacc[5][2][4];
    #pragma unroll
    for (int m = 0; m < 5; m++)
        #pragma unroll
        for (int nt = 0; nt < 2; nt++)
            #pragma unroll
            for (int e = 0; e < 4; e++) kacc[m][nt][e] = 0.f;

    const uint32_t sva = sbase;
    const uint32_t ska = sbase + KV_KOFF;
    const int arow2 = lane & 15;
    const int acoff2 = (lane >> 4) * 16;
    const int brow2 = head * 64 + dgrp * 16 + ((lane >> 4) << 3) + (lane & 7);
    const int bcoff2 = ((lane >> 3) & 1) * 16;
    const uint32_t ones[4] = {ONES2, ONES2, ONES2, ONES2};

    #pragma unroll
    for (int ks = 0; ks < 8; ks++) {
        const int kstep = khalf * 8 + ks;
        uint32_t bf[4];
        ldmatrix_x4(bf, ska + (uint32_t)(brow2 * 528 + kstep * 32 + bcoff2));
        uint32_t b0[2] = {bf[0], bf[1]}, b1[2] = {bf[2], bf[3]};
        #pragma unroll
        for (int m = 0; m < 4; m++) {
            uint32_t a[4];
            ldmatrix_x4(a, sva +
                        (uint32_t)((head * 64 + m * 16 + arow2) * 528 + kstep * 32 + acoff2));
            mma_f16(kacc[m][0], a, b0);
            mma_f16(kacc[m][1], a, b1);
        }
        mma_f16(kacc[4][0], ones, b0);
        mma_f16(kacc[4][1], ones, b1);
    }

    // write partials: chunk = x*2 + khalf, bh = bz*8 + 2*y + head
    const int chunk = blockIdx.x * 2 + khalf;
    const int bh    = bz * 8 + 2 * blockIdx.y + head;
    float* outb = kvp + (size_t)chunk * (128 * 4160) + (size_t)bh * 4160;
    #pragma unroll
    for (int m = 0; m < 4; m++)
        #pragma unroll
        for (int nt = 0; nt < 2; nt++) {
            const int e = m * 16 + (lane >> 2);
            const int d = dgrp * 16 + nt * 8 + 2 * (lane & 3);
            *(float2*)&outb[e * 64 + d]       = make_float2(kacc[m][nt][0], kacc[m][nt][1]);
            *(float2*)&outb[(e + 8) * 64 + d] = make_float2(kacc[m][nt][2], kacc[m][nt][3]);
        }
    if (lane < 4) {
        #pragma unroll
        for (int nt = 0; nt < 2; nt++) {
            const int d = dgrp * 16 + nt * 8 + 2 * lane;
            *(float2*)&outb[4096 + d] = make_float2(kacc[4][nt][0], kacc[4][nt][1]);
        }
    }
}

// ---------------------------------------------------------------------------
// Weight convert (all three in one launch)
// ---------------------------------------------------------------------------
__global__ void conv_w_all(const float* __restrict__ wqk, const float* __restrict__ wv,
                           const float* __restrict__ wo,
                           __half* __restrict__ oq, __half* __restrict__ ov,
                           __half* __restrict__ oo)
{
    int i = blockIdx.x * 256 + threadIdx.x;
    if (i < 524288) {
        oq[i] = __float2half_rn(wqk[i]);
    } else if (i < 786432) {
        int j = i - 524288; ov[j] = __float2half_rn(wv[j]);
    } else if (i < 1048576) {
        int j = i - 786432; oo[j] = __float2half_rn(wo[j]);
    }
}

// ---------------------------------------------------------------------------
// Transpose + fp16 convert: x, pos [B][C][N] fp32 -> xq=(x+pos), xv=x  [B][N][C]
// ---------------------------------------------------------------------------
__global__ __launch_bounds__(256) void conv_xt_kernel(
    const float* __restrict__ x, const float* __restrict__ pos,
    __half* __restrict__ xq, __half* __restrict__ xv)
{
    __shared__ float sA[64][65];
    __shared__ float sB[64][65];

    const int tid = threadIdx.x;
    const int n0 = blockIdx.x * 64;
    const int c0 = blockIdx.y * 64;
    const int bz = blockIdx.z;

    const float* i0 = x   + (size_t)bz * CC * NN;
    const float* i1 = pos + (size_t)bz * CC * NN;

    #pragma unroll
    for (int i = 0; i < 4; i++) {
        int idx = i * 256 + tid;
        int rc = idx >> 4, cn = (idx & 15) * 4;
        float4 xv4 = *(const float4*)&i0[(size_t)(c0 + rc) * NN + n0 + cn];
        float4 pv4 = *(const float4*)&i1[(size_t)(c0 + rc) * NN + n0 + cn];
        sA[rc][cn]     = xv4.x + pv4.x;
        sA[rc][cn + 1] = xv4.y + pv4.y;
        sA[rc][cn + 2] = xv4.z + pv4.z;
        sA[rc][cn + 3] = xv4.w + pv4.w;
        sB[rc][cn]     = xv4.x;
        sB[rc][cn + 1] = xv4.y;
        sB[rc][cn + 2] = xv4.z;
        sB[rc][cn + 3] = xv4.w;
    }
    __syncthreads();

    const size_t obase = ((size_t)bz * NN + n0) * CC + c0;
    #pragma unroll
    for (int i = 0; i < 8; i++) {
        int idx = i * 256 + tid;
        int nr = idx >> 5, cp = idx & 31;
        size_t oa = obase + (size_t)nr * CC + cp * 2;
        __half2 hq, hv;
        hq.x = __float2half_rn(sA[cp * 2][nr]);
        hq.y = __float2half_rn(sA[cp * 2 + 1][nr]);
        hv.x = __float2half_rn(sB[cp * 2][nr]);
        hv.y = __float2half_rn(sB[cp * 2 + 1][nr]);
        *(__half2*)(xq + oa) = hq;
        *(__half2*)(xv + oa) = hv;
    }
}

// ---------------------------------------------------------------------------
__global__ void kv_reduce(const float* __restrict__ kvp, float* __restrict__ kvout)
{
    int i = blockIdx.x * 256 + threadIdx.x;
    if (i < 128 * 4160) {
        float s = 0.f;
        #pragma unroll
        for (int c = 0; c < 32; c++) s += kvp[(size_t)c * (128 * 4160) + i];
        kvout[i] = s;
    }
}

// ---------------------------------------------------------------------------
// attn (tensor cores): out[e,n] = (kv @ q)[e,n] / (ksum@q[n] + EPS)
// ---------------------------------------------------------------------------
#define AT_AH 0
#define AT_AL 10240
#define AT_B  20480
#define AT_SCR 36864
#define ATTN_SMEM 55296

__global__ __launch_bounds__(128) void attn_tc_kernel(
    const __half* __restrict__ qk, const float* __restrict__ kv,
    __half* __restrict__ ao)
{
    extern __shared__ __align__(1024) char smem[];
    const uint32_t sbase = smem_u32(smem);
    __half* S1   = (__half*)(smem + AT_SCR);
    __half* sOut = (__half*)(smem + AT_SCR);

    const int tid  = threadIdx.x;
    const int wid  = tid >> 5;
    const int lane = tid & 31;
    const int bh   = blockIdx.y;
    const int b = bh >> 3, h = bh & 7;
    const int n0 = blockIdx.x * 128;

    const __half* qbase = qk + ((size_t)b * 2 * CC + h * HD) * NN + n0;
    #pragma unroll
    for (int i = 0; i < 8; i++) {
        int idx = tid + i * 128;
        int d = idx >> 4, j = idx & 15;
        cp_async16(sbase + AT_SCR + (uint32_t)(d * 288 + j * 16),
                   qbase + (size_t)d * NN + j * 8);
    }
    CP_COMMIT();

    {
        uint4 z = {0, 0, 0, 0};
        for (int i = tid; i < 1280; i += 128)
            *(uint4*)(smem + AT_AH + i * 16) = z;
    }
    __syncthreads();
    const float* kvb = kv + (size_t)bh * 4160;
    for (int i = tid; i < 4160; i += 128) {
        int e = i >> 6, d = i & 63;
        float f = kvb[i];
        __half hi = __float2half_rn(f);
        __half lo = __float2half_rn(f - __half2float(hi));
        uint32_t off = SWZ128((uint32_t)(e * 128 + d * 2));
        *(__half*)(smem + AT_AH + off) = hi;
        *(__half*)(smem + AT_AL + off) = lo;
    }
    CP_WAIT(0);
    __syncthreads();

    {
        union { __half hh[8]; uint4 u; } pk;
        const int n = tid;
        #pragma unroll
        for (int j = 0; j < 8; j++) {
            #pragma unroll
            for (int d2 = 0; d2 < 8; d2++)
                pk.hh[d2] = S1[(j * 8 + d2) * 144 + n];
            *(uint4*)(smem + AT_B + SWZ128((uint32_t)(n * 128 + j * 16))) = pk.u;
        }
    }
    __syncthreads();

    float acc[5][4][4];
    #pragma unroll
    for (int m = 0; m < 5; m++)
        #pragma unroll
        for (int nt = 0; nt < 4; nt++)
            #pragma unroll
            for (int e = 0; e < 4; e++) acc[m][nt][e] = 0.f;

    const int a_row  = lane & 15;
    const int a_coff = (lane >> 4) * 16;
    const int b_coff = ((lane >> 3) & 1) * 16;

    #pragma unroll
    for (int ks = 0; ks < 4; ks++) {
        uint32_t ah[5][4], al[5][4], bfr[4][2];
        #pragma unroll
        for (int m = 0; m < 5; m++) {
            const uint32_t so = SWZ128((uint32_t)((m * 16 + a_row) * 128 + ks * 32 + a_coff));
            ldmatrix_x4(ah[m], sbase + AT_AH + so);
            ldmatrix_x4(al[m], sbase + AT_AL + so);
        }
        #pragma unroll
        for (int g = 0; g < 2; g++) {
            const int brow = wid * 32 + g * 16 + ((lane >> 4) << 3) + (lane & 7);
            uint32_t r[4];
            ldmatrix_x4(r, sbase + AT_B + SWZ128((uint32_t)(brow * 128 + ks * 32 + b_coff)));
            bfr[g * 2][0] = r[0];  bfr[g * 2][1] = r[1];
            bfr[g * 2 + 1][0] = r[2];  bfr[g * 2 + 1][1] = r[3];
        }
        #pragma unroll
        for (int m = 0; m < 5; m++)
            #pragma unroll
            for (int nt = 0; nt < 4; nt++) {
                mma_f16(acc[m][nt], ah[m], bfr[nt]);
                mma_f16(acc[m][nt], al[m], bfr[nt]);
            }
    }

    #pragma unroll
    for (int nt = 0; nt < 4; nt++) {
        float den0 = __shfl_sync(0xffffffffu, acc[4][nt][0], lane & 3);
        float den1 = __shfl_sync(0xffffffffu, acc[4][nt][1], lane & 3);
        float inv0 = 1.f / (den0 + EPS);
        float inv1 = 1.f / (den1 + EPS);
        const int n = wid * 32 + nt * 8 + 2 * (lane & 3);
        #pragma unroll
        for (int m = 0; m < 4; m++) {
            const int e = m * 16 + (lane >> 2);
            sOut[n * 72 + e]           = __float2half_rn(acc[m][nt][0] * inv0);
            sOut[(n + 1) * 72 + e]     = __float2half_rn(acc[m][nt][1] * inv1);
            sOut[n * 72 + e + 8]       = __float2half_rn(acc[m][nt][2] * inv0);
            sOut[(n + 1) * 72 + e + 8] = __float2half_rn(acc[m][nt][3] * inv1);
        }
    }
    __syncthreads();

    {
        const int n = tid;
        __half* dst = ao + ((size_t)b * NN + n0 + n) * CC + h * HD;
        #pragma unroll
        for (int j = 0; j < 8; j++)
            *(uint4*)(dst + j * 8) = *(uint4*)(sOut + n * 72 + j * 8);
    }
}

// ---------------------------------------------------------------------------
extern "C" void kernel_launch(void* const* d_in, const int* in_sizes, int n_in,
                              void* d_out, int out_size)
{
    const float* x    = (const float*)d_in[0];
    const float* pos  = (const float*)d_in[1];
    const float* w_qk = (const float*)d_in[2];
    const float* w_v  = (const float*)d_in[3];
    const float* w_o  = (const float*)d_in[4];
    float* out = (float*)d_out;

    __half *qk;
    float *kvp, *kvr;
    cudaGetSymbolAddress((void**)&qk,  g_qkh);
    cudaGetSymbolAddress((void**)&kvp, g_kvp);
    cudaGetSymbolAddress((void**)&kvr, g_kv);
    __half *xq, *xv, *ao, *wq, *wv, *wo;
    cudaGetSymbolAddress((void**)&xq, g_xq);
    cudaGetSymbolAddress((void**)&xv, g_xv);
    cudaGetSymbolAddress((void**)&ao, g_ao);
    cudaGetSymbolAddress((void**)&wq, g_wqk);
    cudaGetSymbolAddress((void**)&wv, g_wv);
    cudaGetSymbolAddress((void**)&wo, g_wo);

    cudaFuncSetAttribute(gemm_tc<true, true>,
                         cudaFuncAttributeMaxDynamicSharedMemorySize, GEMM_SMEM);
    cudaFuncSetAttribute(gemm_tc<false, false>,
                         cudaFuncAttributeMaxDynamicSharedMemorySize, GEMM_SMEM);
    cudaFuncSetAttribute(gemm_v_kv,
                         cudaFuncAttributeMaxDynamicSharedMemorySize, GEMM_SMEM);
    cudaFuncSetAttribute(attn_tc_kernel,
                         cudaFuncAttributeMaxDynamicSharedMemorySize, ATTN_SMEM);

    // 0) weight converts (fp16), single launch
    conv_w_all<<<4096, 256>>>(w_qk, w_v, w_o, wq, wv, wo);

    // 1) x / x+pos -> transposed fp16
    conv_xt_kernel<<<dim3(NN / 64, CC / 64, BB), 256>>>(x, pos, xq, xv);

    // 2) qk = relu(w_qk @ (x+pos)) -> fp16
    gemm_tc<true, true><<<dim3(NN / 256, 1024 / 128, BB), 512, GEMM_SMEM>>>(
        wq, xq, qk, 1024);

    // 3+4) v GEMM fused with kv partials (no v global round trip)
    gemm_v_kv<<<dim3(NN / 256, 512 / 128, BB), 512, GEMM_SMEM>>>(
        wv, xv, qk, kvp);
    kv_reduce<<<(128 * 4160 + 255) / 256, 256>>>(kvp, kvr);

    // 5) attn (tensor) -> fp16 transposed [B][N][C]
    attn_tc_kernel<<<dim3(NN / 128, 128), 128, ATTN_SMEM>>>(qk, kvr, ao);

    // 6) out = w_o @ attn -> fp32 (d_out)
    gemm_tc<false, false><<<dim3(NN / 256, 512 / 128, BB), 512, GEMM_SMEM>>>(
        wo, ao, out, 512);
}

// round 8
// speedup vs baseline: 6.5862x; 1.0990x over previous
#include <cuda_runtime.h>
#include <cuda_fp16.h>
#include <cstdint>
#include <cstddef>

// Problem constants
#define BB   16
#define CC   512
#define NN   4096
#define NH   8
#define HD   64
#define EPS  1e-6f

// ---------------------------------------------------------------------------
// Scratch (device globals: allocation-free rule)
// ---------------------------------------------------------------------------
__device__ __half g_qkh[(size_t)BB * 2 * CC * NN]; // [B][1024][4096] relu(qk) fp16
__device__ float g_kvp[(size_t)32 * 128 * 65 * 64];// split-K partials (32 chunks)
__device__ float g_kv [(size_t)128 * 65 * 64];     // [B*nh][65][64] fp32

// fp16 activations, [B][N][C] K-major
__device__ __half g_xq[(size_t)BB * NN * CC];      // x + pos
__device__ __half g_xv[(size_t)BB * NN * CC];      // x
__device__ __half g_ao[(size_t)BB * NN * CC];      // attn output (transposed)
// weights fp16, [O][C] K-major
__device__ __half g_wqk[1024 * 512];
__device__ __half g_wv [512 * 512];
__device__ __half g_wo [512 * 512];

// ---------------------------------------------------------------------------
// Helpers
// ---------------------------------------------------------------------------
__device__ __forceinline__ uint32_t smem_u32(const void* p) {
    uint32_t a;
    asm("{ .reg .u64 t; cvta.to.shared.u64 t, %1; cvt.u32.u64 %0, t; }" : "=r"(a) : "l"(p));
    return a;
}
#define SWZ128(off) ((off) ^ (((off) >> 3) & 0x70))
#define ONES2 0x3C003C00u

__device__ __forceinline__ void cp_async16(uint32_t s, const void* g) {
    asm volatile("cp.async.cg.shared.global [%0], [%1], 16;" :: "r"(s), "l"(g));
}
#define CP_COMMIT() asm volatile("cp.async.commit_group;" ::: "memory")
#define CP_WAIT(n)  asm volatile("cp.async.wait_group %0;" :: "n"(n) : "memory")

__device__ __forceinline__ void ldmatrix_x4(uint32_t* r, uint32_t addr) {
    asm volatile("ldmatrix.sync.aligned.m8n8.x4.shared.b16 {%0,%1,%2,%3}, [%4];"
                 : "=r"(r[0]), "=r"(r[1]), "=r"(r[2]), "=r"(r[3]) : "r"(addr));
}
__device__ __forceinline__ void mma_f16(float* d, const uint32_t* a, const uint32_t* b) {
    asm volatile(
        "mma.sync.aligned.m16n8k16.row.col.f32.f16.f16.f32 "
        "{%0,%1,%2,%3}, {%4,%5,%6,%7}, {%8,%9}, {%0,%1,%2,%3};"
        : "+f"(d[0]), "+f"(d[1]), "+f"(d[2]), "+f"(d[3])
        : "r"(a[0]), "r"(a[1]), "r"(a[2]), "r"(a[3]), "r"(b[0]), "r"(b[1]));
}

// 256-thread GEMM config: BM=128, BN=128, BK=64, 3 stages, 2 CTAs/SM.
#define BKB 128
#define B_OFF  16384
#define STG    32768
#define GEMM_SMEM (3 * STG)

// ---------------------------------------------------------------------------
// qk / o projection GEMM:  Y[O,N] = W[O,C] @ X[C,N]
// ---------------------------------------------------------------------------
template<bool RELU, bool HOUT>
__global__ __launch_bounds__(256, 2) void gemm_tc(
    const __half* __restrict__ A, const __half* __restrict__ Bx,
    void* __restrict__ Yv, int O)
{
    extern __shared__ __align__(1024) char smem[];
    const uint32_t sbase = smem_u32(smem);
    const int tid  = threadIdx.x;
    const int wid  = tid >> 5;
    const int lane = tid & 31;
    const int wm   = wid & 1;        // 2 m-warps
    const int wn   = wid >> 1;       // 4 n-warps

    const int n0 = blockIdx.x * 128;
    const int o0 = blockIdx.y * 128;
    const int bz = blockIdx.z;

    const __half* Bb = Bx + (size_t)bz * NN * CC;

    auto load_stage = [&](int ck, int st) {
        const int k0 = ck * 64;
        const uint32_t sb = sbase + st * STG;
        #pragma unroll
        for (int i = 0; i < 4; i++) {            // A: 128 rows x 128B
            int c = tid + i * 256;
            int row = c >> 3, cc = c & 7;
            cp_async16(sb + SWZ128((uint32_t)(row * BKB + cc * 16)),
                       A + (size_t)(o0 + row) * CC + k0 + cc * 8);
        }
        #pragma unroll
        for (int i = 0; i < 4; i++) {            // B: 128 rows x 128B
            int c = tid + i * 256;
            int row = c >> 3, cc = c & 7;
            cp_async16(sb + B_OFF + SWZ128((uint32_t)(row * BKB + cc * 16)),
                       Bb + (size_t)(n0 + row) * CC + k0 + cc * 8);
        }
        CP_COMMIT();
    };

    float acc[4][4][4];
    #pragma unroll
    for (int mf = 0; mf < 4; mf++)
        #pragma unroll
        for (int nf = 0; nf < 4; nf++)
            #pragma unroll
            for (int e = 0; e < 4; e++) acc[mf][nf][e] = 0.f;

    load_stage(0, 0);
    load_stage(1, 1);
    CP_WAIT(1);
    __syncthreads();

    const int a_row  = wm * 64 + (lane & 15);
    const int a_coff = (lane >> 4) * 16;
    const int b_row  = wn * 32 + ((lane >> 4) << 3) + (lane & 7);
    const int b_coff = ((lane >> 3) & 1) * 16;

    for (int it = 0; it < 8; it++) {
        const uint32_t sb = sbase + (it % 3) * STG;
        #pragma unroll
        for (int kk = 0; kk < 4; kk++) {
            uint32_t a[4][4], b[4][2];
            #pragma unroll
            for (int mf = 0; mf < 4; mf++)
                ldmatrix_x4(a[mf], sb +
                            SWZ128((uint32_t)((a_row + mf * 16) * BKB + kk * 32 + a_coff)));
            #pragma unroll
            for (int np = 0; np < 2; np++) {
                uint32_t r[4];
                ldmatrix_x4(r, sb + B_OFF +
                            SWZ128((uint32_t)((b_row + np * 16) * BKB + kk * 32 + b_coff)));
                b[np * 2][0] = r[0];  b[np * 2][1] = r[1];
                b[np * 2 + 1][0] = r[2];  b[np * 2 + 1][1] = r[3];
            }
            #pragma unroll
            for (int mf = 0; mf < 4; mf++)
                #pragma unroll
                for (int nf = 0; nf < 4; nf++)
                    mma_f16(acc[mf][nf], a[mf], b[nf]);
        }
        if (it + 2 < 8) {
            load_stage(it + 2, (it + 2) % 3);
            CP_WAIT(1);
        } else {
            CP_WAIT(0);
        }
        __syncthreads();
    }

    const int er = lane >> 2;
    const int ec = (lane & 3) * 2;
    #pragma unroll
    for (int mf = 0; mf < 4; mf++) {
        #pragma unroll
        for (int nf = 0; nf < 4; nf++) {
            const int orow = o0 + wm * 64 + mf * 16 + er;
            const int ocol = n0 + wn * 32 + nf * 8 + ec;
            float v0x = acc[mf][nf][0], v0y = acc[mf][nf][1];
            float v1x = acc[mf][nf][2], v1y = acc[mf][nf][3];
            if (RELU) {
                v0x = fmaxf(v0x, 0.f); v0y = fmaxf(v0y, 0.f);
                v1x = fmaxf(v1x, 0.f); v1y = fmaxf(v1y, 0.f);
            }
            if (HOUT) {
                __half* Yb = (__half*)Yv + (size_t)bz * O * NN;
                *(__half2*)&Yb[(size_t)orow * NN + ocol] = __floats2half2_rn(v0x, v0y);
                *(__half2*)&Yb[(size_t)(orow + 8) * NN + ocol] = __floats2half2_rn(v1x, v1y);
            } else {
                float* Yb = (float*)Yv + (size_t)bz * O * NN;
                *(float2*)&Yb[(size_t)orow * NN + ocol]       = make_float2(v0x, v0y);
                *(float2*)&Yb[(size_t)(orow + 8) * NN + ocol] = make_float2(v1x, v1y);
            }
        }
    }
}

// ---------------------------------------------------------------------------
// Fused v-GEMM + kv: v tile [128 o][128 n] stays in SMEM (same fp16 rounding);
// k tile loaded; kv split-K partials written (chunk = n-tile, 32 chunks).
// ---------------------------------------------------------------------------
#define VP 136                 // v/k smem pitch in halves (272 B)
#define KV_KOFF 34816          // k tile base (128*272)

__global__ __launch_bounds__(256, 2) void gemm_v_kv(
    const __half* __restrict__ A, const __half* __restrict__ Bx,
    const __half* __restrict__ qk, float* __restrict__ kvp)
{
    extern __shared__ __align__(1024) char smem[];
    const uint32_t sbase = smem_u32(smem);
    const int tid  = threadIdx.x;
    const int wid  = tid >> 5;
    const int lane = tid & 31;
    const int wm   = wid & 1;
    const int wn   = wid >> 1;

    const int n0 = blockIdx.x * 128;
    const int o0 = blockIdx.y * 128;
    const int bz = blockIdx.z;

    const __half* Bb = Bx + (size_t)bz * NN * CC;

    auto load_stage = [&](int ck, int st) {
        const int k0 = ck * 64;
        const uint32_t sb = sbase + st * STG;
        #pragma unroll
        for (int i = 0; i < 4; i++) {
            int c = tid + i * 256;
            int row = c >> 3, cc = c & 7;
            cp_async16(sb + SWZ128((uint32_t)(row * BKB + cc * 16)),
                       A + (size_t)(o0 + row) * CC + k0 + cc * 8);
        }
        #pragma unroll
        for (int i = 0; i < 4; i++) {
            int c = tid + i * 256;
            int row = c >> 3, cc = c & 7;
            cp_async16(sb + B_OFF + SWZ128((uint32_t)(row * BKB + cc * 16)),
                       Bb + (size_t)(n0 + row) * CC + k0 + cc * 8);
        }
        CP_COMMIT();
    };

    float acc[4][4][4];
    #pragma unroll
    for (int mf = 0; mf < 4; mf++)
        #pragma unroll
        for (int nf = 0; nf < 4; nf++)
            #pragma unroll
            for (int e = 0; e < 4; e++) acc[mf][nf][e] = 0.f;

    load_stage(0, 0);
    load_stage(1, 1);
    CP_WAIT(1);
    __syncthreads();

    const int a_row  = wm * 64 + (lane & 15);
    const int a_coff = (lane >> 4) * 16;
    const int b_row  = wn * 32 + ((lane >> 4) << 3) + (lane & 7);
    const int b_coff = ((lane >> 3) & 1) * 16;

    for (int it = 0; it < 8; it++) {
        const uint32_t sb = sbase + (it % 3) * STG;
        #pragma unroll
        for (int kk = 0; kk < 4; kk++) {
            uint32_t a[4][4], b[4][2];
            #pragma unroll
            for (int mf = 0; mf < 4; mf++)
                ldmatrix_x4(a[mf], sb +
                            SWZ128((uint32_t)((a_row + mf * 16) * BKB + kk * 32 + a_coff)));
            #pragma unroll
            for (int np = 0; np < 2; np++) {
                uint32_t r[4];
                ldmatrix_x4(r, sb + B_OFF +
                            SWZ128((uint32_t)((b_row + np * 16) * BKB + kk * 32 + b_coff)));
                b[np * 2][0] = r[0];  b[np * 2][1] = r[1];
                b[np * 2 + 1][0] = r[2];  b[np * 2 + 1][1] = r[3];
            }
            #pragma unroll
            for (int mf = 0; mf < 4; mf++)
                #pragma unroll
                for (int nf = 0; nf < 4; nf++)
                    mma_f16(acc[mf][nf], a[mf], b[nf]);
        }
        if (it + 2 < 8) {
            load_stage(it + 2, (it + 2) % 3);
            CP_WAIT(1);
        } else {
            CP_WAIT(0);
        }
        __syncthreads();
    }

    // ---- epilogue: v tile (fp16) -> smem [128][VP]; k tile -> smem ----
    __half* sv = (__half*)smem;
    const int er = lane >> 2;
    const int ec = (lane & 3) * 2;
    #pragma unroll
    for (int mf = 0; mf < 4; mf++) {
        #pragma unroll
        for (int nf = 0; nf < 4; nf++) {
            const int lr = wm * 64 + mf * 16 + er;
            const int lc = wn * 32 + nf * 8 + ec;
            *(__half2*)&sv[lr * VP + lc] =
                __floats2half2_rn(acc[mf][nf][0], acc[mf][nf][1]);
            *(__half2*)&sv[(lr + 8) * VP + lc] =
                __floats2half2_rn(acc[mf][nf][2], acc[mf][nf][3]);
        }
    }
    // k tile: 128 channel rows (CC + o0 + r), 128 n cols (256B data), pitch 272B
    const __half* kb = qk + ((size_t)bz * 2 * CC + CC + o0) * NN + n0;
    #pragma unroll
    for (int i = 0; i < 8; i++) {
        int idx = tid + i * 256;
        int r = idx >> 4, c = idx & 15;
        cp_async16(sbase + KV_KOFF + (uint32_t)(r * 272 + c * 16),
                   kb + (size_t)r * NN + c * 8);
    }
    CP_COMMIT();
    CP_WAIT(0);
    __syncthreads();

    // ---- kv mma: 8 warps = head(2) x dgrp(4, 16 d each); K = 128 n ----
    const int head = wid >> 2;          // 0..1
    const int dgrp = wid & 3;           // 0..3

    float kacc[5][2][4];
    #pragma unroll
    for (int m = 0; m < 5; m++)
        #pragma unroll
        for (int nt = 0; nt < 2; nt++)
            #pragma unroll
            for (int e = 0; e < 4; e++) kacc[m][nt][e] = 0.f;

    const uint32_t sva = sbase;
    const uint32_t ska = sbase + KV_KOFF;
    const int arow2 = lane & 15;
    const int acoff2 = (lane >> 4) * 16;
    const int brow2 = head * 64 + dgrp * 16 + ((lane >> 4) << 3) + (lane & 7);
    const int bcoff2 = ((lane >> 3) & 1) * 16;
    const uint32_t ones[4] = {ONES2, ONES2, ONES2, ONES2};

    #pragma unroll
    for (int ks = 0; ks < 8; ks++) {
        uint32_t bf[4];
        ldmatrix_x4(bf, ska + (uint32_t)(brow2 * 272 + ks * 32 + bcoff2));
        uint32_t b0[2] = {bf[0], bf[1]}, b1[2] = {bf[2], bf[3]};
        #pragma unroll
        for (int m = 0; m < 4; m++) {
            uint32_t a[4];
            ldmatrix_x4(a, sva +
                        (uint32_t)((head * 64 + m * 16 + arow2) * 272 + ks * 32 + acoff2));
            mma_f16(kacc[m][0], a, b0);
            mma_f16(kacc[m][1], a, b1);
        }
        mma_f16(kacc[4][0], ones, b0);
        mma_f16(kacc[4][1], ones, b1);
    }

    // partials: chunk = blockIdx.x (n-tile), bh = bz*8 + blockIdx.y*2 + head
    const int chunk = blockIdx.x;
    const int bh    = bz * 8 + blockIdx.y * 2 + head;
    float* outb = kvp + (size_t)chunk * (128 * 4160) + (size_t)bh * 4160;
    #pragma unroll
    for (int m = 0; m < 4; m++)
        #pragma unroll
        for (int nt = 0; nt < 2; nt++) {
            const int e = m * 16 + (lane >> 2);
            const int d = dgrp * 16 + nt * 8 + 2 * (lane & 3);
            *(float2*)&outb[e * 64 + d]       = make_float2(kacc[m][nt][0], kacc[m][nt][1]);
            *(float2*)&outb[(e + 8) * 64 + d] = make_float2(kacc[m][nt][2], kacc[m][nt][3]);
        }
    if (lane < 4) {
        #pragma unroll
        for (int nt = 0; nt < 2; nt++) {
            const int d = dgrp * 16 + nt * 8 + 2 * lane;
            *(float2*)&outb[4096 + d] = make_float2(kacc[4][nt][0], kacc[4][nt][1]);
        }
    }
}

// ---------------------------------------------------------------------------
// Weight convert (all three in one launch)
// ---------------------------------------------------------------------------
__global__ void conv_w_all(const float* __restrict__ wqk, const float* __restrict__ wv,
                           const float* __restrict__ wo,
                           __half* __restrict__ oq, __half* __restrict__ ov,
                           __half* __restrict__ oo)
{
    int i = blockIdx.x * 256 + threadIdx.x;
    if (i < 524288) {
        oq[i] = __float2half_rn(wqk[i]);
    } else if (i < 786432) {
        int j = i - 524288; ov[j] = __float2half_rn(wv[j]);
    } else if (i < 1048576) {
        int j = i - 786432; oo[j] = __float2half_rn(wo[j]);
    }
}

// ---------------------------------------------------------------------------
// Transpose + fp16 convert: x, pos [B][C][N] fp32 -> xq=(x+pos), xv=x  [B][N][C]
// ---------------------------------------------------------------------------
__global__ __launch_bounds__(256) void conv_xt_kernel(
    const float* __restrict__ x, const float* __restrict__ pos,
    __half* __restrict__ xq, __half* __restrict__ xv)
{
    __shared__ float sA[64][65];
    __shared__ float sB[64][65];

    const int tid = threadIdx.x;
    const int n0 = blockIdx.x * 64;
    const int c0 = blockIdx.y * 64;
    const int bz = blockIdx.z;

    const float* i0 = x   + (size_t)bz * CC * NN;
    const float* i1 = pos + (size_t)bz * CC * NN;

    #pragma unroll
    for (int i = 0; i < 4; i++) {
        int idx = i * 256 + tid;
        int rc = idx >> 4, cn = (idx & 15) * 4;
        float4 xv4 = *(const float4*)&i0[(size_t)(c0 + rc) * NN + n0 + cn];
        float4 pv4 = *(const float4*)&i1[(size_t)(c0 + rc) * NN + n0 + cn];
        sA[rc][cn]     = xv4.x + pv4.x;
        sA[rc][cn + 1] = xv4.y + pv4.y;
        sA[rc][cn + 2] = xv4.z + pv4.z;
        sA[rc][cn + 3] = xv4.w + pv4.w;
        sB[rc][cn]     = xv4.x;
        sB[rc][cn + 1] = xv4.y;
        sB[rc][cn + 2] = xv4.z;
        sB[rc][cn + 3] = xv4.w;
    }
    __syncthreads();

    const size_t obase = ((size_t)bz * NN + n0) * CC + c0;
    #pragma unroll
    for (int i = 0; i < 8; i++) {
        int idx = i * 256 + tid;
        int nr = idx >> 5, cp = idx & 31;
        size_t oa = obase + (size_t)nr * CC + cp * 2;
        __half2 hq, hv;
        hq.x = __float2half_rn(sA[cp * 2][nr]);
        hq.y = __float2half_rn(sA[cp * 2 + 1][nr]);
        hv.x = __float2half_rn(sB[cp * 2][nr]);
        hv.y = __float2half_rn(sB[cp * 2 + 1][nr]);
        *(__half2*)(xq + oa) = hq;
        *(__half2*)(xv + oa) = hv;
    }
}

// ---------------------------------------------------------------------------
__global__ void kv_reduce(const float* __restrict__ kvp, float* __restrict__ kvout)
{
    int i = blockIdx.x * 256 + threadIdx.x;
    if (i < 128 * 4160) {
        float s = 0.f;
        #pragma unroll
        for (int c = 0; c < 32; c++) s += kvp[(size_t)c * (128 * 4160) + i];
        kvout[i] = s;
    }
}

// ---------------------------------------------------------------------------
// attn (tensor cores): out[e,n] = (kv @ q)[e,n] / (ksum@q[n] + EPS)
// ---------------------------------------------------------------------------
#define AT_AH 0
#define AT_AL 10240
#define AT_B  20480
#define AT_SCR 36864
#define ATTN_SMEM 55296

__global__ __launch_bounds__(128) void attn_tc_kernel(
    const __half* __restrict__ qk, const float* __restrict__ kv,
    __half* __restrict__ ao)
{
    extern __shared__ __align__(1024) char smem[];
    const uint32_t sbase = smem_u32(smem);
    __half* S1   = (__half*)(smem + AT_SCR);
    __half* sOut = (__half*)(smem + AT_SCR);

    const int tid  = threadIdx.x;
    const int wid  = tid >> 5;
    const int lane = tid & 31;
    const int bh   = blockIdx.y;
    const int b = bh >> 3, h = bh & 7;
    const int n0 = blockIdx.x * 128;

    const __half* qbase = qk + ((size_t)b * 2 * CC + h * HD) * NN + n0;
    #pragma unroll
    for (int i = 0; i < 8; i++) {
        int idx = tid + i * 128;
        int d = idx >> 4, j = idx & 15;
        cp_async16(sbase + AT_SCR + (uint32_t)(d * 288 + j * 16),
                   qbase + (size_t)d * NN + j * 8);
    }
    CP_COMMIT();

    {
        uint4 z = {0, 0, 0, 0};
        for (int i = tid; i < 1280; i += 128)
            *(uint4*)(smem + AT_AH + i * 16) = z;
    }
    __syncthreads();
    const float* kvb = kv + (size_t)bh * 4160;
    for (int i = tid; i < 4160; i += 128) {
        int e = i >> 6, d = i & 63;
        float f = kvb[i];
        __half hi = __float2half_rn(f);
        __half lo = __float2half_rn(f - __half2float(hi));
        uint32_t off = SWZ128((uint32_t)(e * 128 + d * 2));
        *(__half*)(smem + AT_AH + off) = hi;
        *(__half*)(smem + AT_AL + off) = lo;
    }
    CP_WAIT(0);
    __syncthreads();

    {
        union { __half hh[8]; uint4 u; } pk;
        const int n = tid;
        #pragma unroll
        for (int j = 0; j < 8; j++) {
            #pragma unroll
            for (int d2 = 0; d2 < 8; d2++)
                pk.hh[d2] = S1[(j * 8 + d2) * 144 + n];
            *(uint4*)(smem + AT_B + SWZ128((uint32_t)(n * 128 + j * 16))) = pk.u;
        }
    }
    __syncthreads();

    float acc[5][4][4];
    #pragma unroll
    for (int m = 0; m < 5; m++)
        #pragma unroll
        for (int nt = 0; nt < 4; nt++)
            #pragma unroll
            for (int e = 0; e < 4; e++) acc[m][nt][e] = 0.f;

    const int a_row  = lane & 15;
    const int a_coff = (lane >> 4) * 16;
    const int b_coff = ((lane >> 3) & 1) * 16;

    #pragma unroll
    for (int ks = 0; ks < 4; ks++) {
        uint32_t ah[5][4], al[5][4], bfr[4][2];
        #pragma unroll
        for (int m = 0; m < 5; m++) {
            const uint32_t so = SWZ128((uint32_t)((m * 16 + a_row) * 128 + ks * 32 + a_coff));
            ldmatrix_x4(ah[m], sbase + AT_AH + so);
            ldmatrix_x4(al[m], sbase + AT_AL + so);
        }
        #pragma unroll
        for (int g = 0; g < 2; g++) {
            const int brow = wid * 32 + g * 16 + ((lane >> 4) << 3) + (lane & 7);
            uint32_t r[4];
            ldmatrix_x4(r, sbase + AT_B + SWZ128((uint32_t)(brow * 128 + ks * 32 + b_coff)));
            bfr[g * 2][0] = r[0];  bfr[g * 2][1] = r[1];
            bfr[g * 2 + 1][0] = r[2];  bfr[g * 2 + 1][1] = r[3];
        }
        #pragma unroll
        for (int m = 0; m < 5; m++)
            #pragma unroll
            for (int nt = 0; nt < 4; nt++) {
                mma_f16(acc[m][nt], ah[m], bfr[nt]);
                mma_f16(acc[m][nt], al[m], bfr[nt]);
            }
    }

    #pragma unroll
    for (int nt = 0; nt < 4; nt++) {
        float den0 = __shfl_sync(0xffffffffu, acc[4][nt][0], lane & 3);
        float den1 = __shfl_sync(0xffffffffu, acc[4][nt][1], lane & 3);
        float inv0 = 1.f / (den0 + EPS);
        float inv1 = 1.f / (den1 + EPS);
        const int n = wid * 32 + nt * 8 + 2 * (lane & 3);
        #pragma unroll
        for (int m = 0; m < 4; m++) {
            const int e = m * 16 + (lane >> 2);
            sOut[n * 72 + e]           = __float2half_rn(acc[m][nt][0] * inv0);
            sOut[(n + 1) * 72 + e]     = __float2half_rn(acc[m][nt][1] * inv1);
            sOut[n * 72 + e + 8]       = __float2half_rn(acc[m][nt][2] * inv0);
            sOut[(n + 1) * 72 + e + 8] = __float2half_rn(acc[m][nt][3] * inv1);
        }
    }
    __syncthreads();

    {
        const int n = tid;
        __half* dst = ao + ((size_t)b * NN + n0 + n) * CC + h * HD;
        #pragma unroll
        for (int j = 0; j < 8; j++)
            *(uint4*)(dst + j * 8) = *(uint4*)(sOut + n * 72 + j * 8);
    }
}

// ---------------------------------------------------------------------------
extern "C" void kernel_launch(void* const* d_in, const int* in_sizes, int n_in,
                              void* d_out, int out_size)
{
    const float* x    = (const float*)d_in[0];
    const float* pos  = (const float*)d_in[1];
    const float* w_qk = (const float*)d_in[2];
    const float* w_v  = (const float*)d_in[3];
    const float* w_o  = (const float*)d_in[4];
    float* out = (float*)d_out;

    __half *qk;
    float *kvp, *kvr;
    cudaGetSymbolAddress((void**)&qk,  g_qkh);
    cudaGetSymbolAddress((void**)&kvp, g_kvp);
    cudaGetSymbolAddress((void**)&kvr, g_kv);
    __half *xq, *xv, *ao, *wq, *wv, *wo;
    cudaGetSymbolAddress((void**)&xq, g_xq);
    cudaGetSymbolAddress((void**)&xv, g_xv);
    cudaGetSymbolAddress((void**)&ao, g_ao);
    cudaGetSymbolAddress((void**)&wq, g_wqk);
    cudaGetSymbolAddress((void**)&wv, g_wv);
    cudaGetSymbolAddress((void**)&wo, g_wo);

    cudaFuncSetAttribute(gemm_tc<true, true>,
                         cudaFuncAttributeMaxDynamicSharedMemorySize, GEMM_SMEM);
    cudaFuncSetAttribute(gemm_tc<false, false>,
                         cudaFuncAttributeMaxDynamicSharedMemorySize, GEMM_SMEM);
    cudaFuncSetAttribute(gemm_v_kv,
                         cudaFuncAttributeMaxDynamicSharedMemorySize, GEMM_SMEM);
    cudaFuncSetAttribute(attn_tc_kernel,
                         cudaFuncAttributeMaxDynamicSharedMemorySize, ATTN_SMEM);

    // 0) weight converts (fp16), single launch
    conv_w_all<<<4096, 256>>>(w_qk, w_v, w_o, wq, wv, wo);

    // 1) x / x+pos -> transposed fp16
    conv_xt_kernel<<<dim3(NN / 64, CC / 64, BB), 256>>>(x, pos, xq, xv);

    // 2) qk = relu(w_qk @ (x+pos)) -> fp16
    gemm_tc<true, true><<<dim3(NN / 128, 1024 / 128, BB), 256, GEMM_SMEM>>>(
        wq, xq, qk, 1024);

    // 3+4) v GEMM fused with kv partials
    gemm_v_kv<<<dim3(NN / 128, 512 / 128, BB), 256, GEMM_SMEM>>>(
        wv, xv, qk, kvp);
    kv_reduce<<<(128 * 4160 + 255) / 256, 256>>>(kvp, kvr);

    // 5) attn (tensor) -> fp16 transposed [B][N][C]
    attn_tc_kernel<<<dim3(NN / 128, 128), 128, ATTN_SMEM>>>(qk, kvr, ao);

    // 6) out = w_o @ attn -> fp32 (d_out)
    gemm_tc<false, false><<<dim3(NN / 128, 512 / 128, BB), 256, GEMM_SMEM>>>(
        wo, ao, out, 512);
}

// round 9
// speedup vs baseline: 6.7024x; 1.0177x over previous
#include <cuda_runtime.h>
#include <cuda_fp16.h>
#include <cstdint>
#include <cstddef>

// Problem constants
#define BB   16
#define CC   512
#define NN   4096
#define NH   8
#define HD   64
#define EPS  1e-6f

// ---------------------------------------------------------------------------
// Scratch (device globals: allocation-free rule)
// ---------------------------------------------------------------------------
__device__ __half g_qkh[(size_t)BB * 2 * CC * NN]; // [B][1024][4096] relu(qk) fp16
__device__ float g_kvp[(size_t)32 * 128 * 65 * 64];// split-K partials (32 chunks)
__device__ float g_kv [(size_t)128 * 65 * 64];     // [B*nh][65][64] fp32

// fp16 activations, [B][N][C] K-major
__device__ __half g_xq[(size_t)BB * NN * CC];      // x + pos
__device__ __half g_xv[(size_t)BB * NN * CC];      // x
__device__ __half g_ao[(size_t)BB * NN * CC];      // attn output (transposed)
// weights fp16, [O][C] K-major
__device__ __half g_wqk[1024 * 512];
__device__ __half g_wv [512 * 512];
__device__ __half g_wo [512 * 512];

// ---------------------------------------------------------------------------
// Helpers
// ---------------------------------------------------------------------------
__device__ __forceinline__ uint32_t smem_u32(const void* p) {
    uint32_t a;
    asm("{ .reg .u64 t; cvta.to.shared.u64 t, %1; cvt.u32.u64 %0, t; }" : "=r"(a) : "l"(p));
    return a;
}
#define SWZ128(off) ((off) ^ (((off) >> 3) & 0x70))
#define ONES2 0x3C003C00u

__device__ __forceinline__ void cp_async16(uint32_t s, const void* g) {
    asm volatile("cp.async.cg.shared.global [%0], [%1], 16;" :: "r"(s), "l"(g));
}
#define CP_COMMIT() asm volatile("cp.async.commit_group;" ::: "memory")
#define CP_WAIT(n)  asm volatile("cp.async.wait_group %0;" :: "n"(n) : "memory")

__device__ __forceinline__ void ldmatrix_x4(uint32_t* r, uint32_t addr) {
    asm volatile("ldmatrix.sync.aligned.m8n8.x4.shared.b16 {%0,%1,%2,%3}, [%4];"
                 : "=r"(r[0]), "=r"(r[1]), "=r"(r[2]), "=r"(r[3]) : "r"(addr));
}
__device__ __forceinline__ void mma_f16(float* d, const uint32_t* a, const uint32_t* b) {
    asm volatile(
        "mma.sync.aligned.m16n8k16.row.col.f32.f16.f16.f32 "
        "{%0,%1,%2,%3}, {%4,%5,%6,%7}, {%8,%9}, {%0,%1,%2,%3};"
        : "+f"(d[0]), "+f"(d[1]), "+f"(d[2]), "+f"(d[3])
        : "r"(a[0]), "r"(a[1]), "r"(a[2]), "r"(a[3]), "r"(b[0]), "r"(b[1]));
}

// 128-thread GEMM config: BM=128, BN=128, BK=64, warp tile 64x64, 3 stages.
#define BKB 128
#define B_OFF  16384
#define STG    32768
#define GEMM_SMEM (3 * STG)

// ---------------------------------------------------------------------------
// qk / o projection GEMM:  Y[O,N] = W[O,C] @ X[C,N]
// ---------------------------------------------------------------------------
template<bool RELU, bool HOUT>
__global__ __launch_bounds__(128, 2) void gemm_tc(
    const __half* __restrict__ A, const __half* __restrict__ Bx,
    void* __restrict__ Yv, int O)
{
    extern __shared__ __align__(1024) char smem[];
    const uint32_t sbase = smem_u32(smem);
    const int tid  = threadIdx.x;
    const int wid  = tid >> 5;
    const int lane = tid & 31;
    const int wm   = wid & 1;        // 2 m-warps
    const int wn   = wid >> 1;       // 2 n-warps

    const int n0 = blockIdx.x * 128;
    const int o0 = blockIdx.y * 128;
    const int bz = blockIdx.z;

    const __half* Bb = Bx + (size_t)bz * NN * CC;

    auto load_stage = [&](int ck, int st) {
        const int k0 = ck * 64;
        const uint32_t sb = sbase + st * STG;
        #pragma unroll
        for (int i = 0; i < 8; i++) {            // A: 128 rows x 128B
            int c = tid + i * 128;
            int row = c >> 3, cc = c & 7;
            cp_async16(sb + SWZ128((uint32_t)(row * BKB + cc * 16)),
                       A + (size_t)(o0 + row) * CC + k0 + cc * 8);
        }
        #pragma unroll
        for (int i = 0; i < 8; i++) {            // B: 128 rows x 128B
            int c = tid + i * 128;
            int row = c >> 3, cc = c & 7;
            cp_async16(sb + B_OFF + SWZ128((uint32_t)(row * BKB + cc * 16)),
                       Bb + (size_t)(n0 + row) * CC + k0 + cc * 8);
        }
        CP_COMMIT();
    };

    float acc[4][8][4];
    #pragma unroll
    for (int mf = 0; mf < 4; mf++)
        #pragma unroll
        for (int nf = 0; nf < 8; nf++)
            #pragma unroll
            for (int e = 0; e < 4; e++) acc[mf][nf][e] = 0.f;

    load_stage(0, 0);
    load_stage(1, 1);
    CP_WAIT(1);
    __syncthreads();

    const int a_row  = wm * 64 + (lane & 15);
    const int a_coff = (lane >> 4) * 16;
    const int b_row  = wn * 64 + ((lane >> 4) << 3) + (lane & 7);
    const int b_coff = ((lane >> 3) & 1) * 16;

    for (int it = 0; it < 8; it++) {
        const uint32_t sb = sbase + (it % 3) * STG;
        #pragma unroll
        for (int kk = 0; kk < 4; kk++) {
            uint32_t a[4][4], b[8][2];
            #pragma unroll
            for (int mf = 0; mf < 4; mf++)
                ldmatrix_x4(a[mf], sb +
                            SWZ128((uint32_t)((a_row + mf * 16) * BKB + kk * 32 + a_coff)));
            #pragma unroll
            for (int ng = 0; ng < 4; ng++) {
                uint32_t r[4];
                ldmatrix_x4(r, sb + B_OFF +
                            SWZ128((uint32_t)((b_row + ng * 16) * BKB + kk * 32 + b_coff)));
                b[ng * 2][0] = r[0];  b[ng * 2][1] = r[1];
                b[ng * 2 + 1][0] = r[2];  b[ng * 2 + 1][1] = r[3];
            }
            #pragma unroll
            for (int mf = 0; mf < 4; mf++)
                #pragma unroll
                for (int nf = 0; nf < 8; nf++)
                    mma_f16(acc[mf][nf], a[mf], b[nf]);
        }
        if (it + 2 < 8) {
            load_stage(it + 2, (it + 2) % 3);
            CP_WAIT(1);
        } else {
            CP_WAIT(0);
        }
        __syncthreads();
    }

    const int er = lane >> 2;
    const int ec = (lane & 3) * 2;
    #pragma unroll
    for (int mf = 0; mf < 4; mf++) {
        #pragma unroll
        for (int nf = 0; nf < 8; nf++) {
            const int orow = o0 + wm * 64 + mf * 16 + er;
            const int ocol = n0 + wn * 64 + nf * 8 + ec;
            float v0x = acc[mf][nf][0], v0y = acc[mf][nf][1];
            float v1x = acc[mf][nf][2], v1y = acc[mf][nf][3];
            if (RELU) {
                v0x = fmaxf(v0x, 0.f); v0y = fmaxf(v0y, 0.f);
                v1x = fmaxf(v1x, 0.f); v1y = fmaxf(v1y, 0.f);
            }
            if (HOUT) {
                __half* Yb = (__half*)Yv + (size_t)bz * O * NN;
                *(__half2*)&Yb[(size_t)orow * NN + ocol] = __floats2half2_rn(v0x, v0y);
                *(__half2*)&Yb[(size_t)(orow + 8) * NN + ocol] = __floats2half2_rn(v1x, v1y);
            } else {
                float* Yb = (float*)Yv + (size_t)bz * O * NN;
                *(float2*)&Yb[(size_t)orow * NN + ocol]       = make_float2(v0x, v0y);
                *(float2*)&Yb[(size_t)(orow + 8) * NN + ocol] = make_float2(v1x, v1y);
            }
        }
    }
}

// ---------------------------------------------------------------------------
// Fused v-GEMM + kv: v tile [128 o][128 n] stays in SMEM (same fp16 rounding);
// k tile loaded; kv split-K partials written (chunk = n-tile, 32 chunks).
// ---------------------------------------------------------------------------
#define VP 136                 // v/k smem pitch in halves (272 B)
#define KV_KOFF 34816          // k tile base (128*272)

__global__ __launch_bounds__(128, 2) void gemm_v_kv(
    const __half* __restrict__ A, const __half* __restrict__ Bx,
    const __half* __restrict__ qk, float* __restrict__ kvp)
{
    extern __shared__ __align__(1024) char smem[];
    const uint32_t sbase = smem_u32(smem);
    const int tid  = threadIdx.x;
    const int wid  = tid >> 5;
    const int lane = tid & 31;
    const int wm   = wid & 1;
    const int wn   = wid >> 1;

    const int n0 = blockIdx.x * 128;
    const int o0 = blockIdx.y * 128;
    const int bz = blockIdx.z;

    const __half* Bb = Bx + (size_t)bz * NN * CC;

    auto load_stage = [&](int ck, int st) {
        const int k0 = ck * 64;
        const uint32_t sb = sbase + st * STG;
        #pragma unroll
        for (int i = 0; i < 8; i++) {
            int c = tid + i * 128;
            int row = c >> 3, cc = c & 7;
            cp_async16(sb + SWZ128((uint32_t)(row * BKB + cc * 16)),
                       A + (size_t)(o0 + row) * CC + k0 + cc * 8);
        }
        #pragma unroll
        for (int i = 0; i < 8; i++) {
            int c = tid + i * 128;
            int row = c >> 3, cc = c & 7;
            cp_async16(sb + B_OFF + SWZ128((uint32_t)(row * BKB + cc * 16)),
                       Bb + (size_t)(n0 + row) * CC + k0 + cc * 8);
        }
        CP_COMMIT();
    };

    float acc[4][8][4];
    #pragma unroll
    for (int mf = 0; mf < 4; mf++)
        #pragma unroll
        for (int nf = 0; nf < 8; nf++)
            #pragma unroll
            for (int e = 0; e < 4; e++) acc[mf][nf][e] = 0.f;

    load_stage(0, 0);
    load_stage(1, 1);
    CP_WAIT(1);
    __syncthreads();

    const int a_row  = wm * 64 + (lane & 15);
    const int a_coff = (lane >> 4) * 16;
    const int b_row  = wn * 64 + ((lane >> 4) << 3) + (lane & 7);
    const int b_coff = ((lane >> 3) & 1) * 16;

    for (int it = 0; it < 8; it++) {
        const uint32_t sb = sbase + (it % 3) * STG;
        #pragma unroll
        for (int kk = 0; kk < 4; kk++) {
            uint32_t a[4][4], b[8][2];
            #pragma unroll
            for (int mf = 0; mf < 4; mf++)
                ldmatrix_x4(a[mf], sb +
                            SWZ128((uint32_t)((a_row + mf * 16) * BKB + kk * 32 + a_coff)));
            #pragma unroll
            for (int ng = 0; ng < 4; ng++) {
                uint32_t r[4];
                ldmatrix_x4(r, sb + B_OFF +
                            SWZ128((uint32_t)((b_row + ng * 16) * BKB + kk * 32 + b_coff)));
                b[ng * 2][0] = r[0];  b[ng * 2][1] = r[1];
                b[ng * 2 + 1][0] = r[2];  b[ng * 2 + 1][1] = r[3];
            }
            #pragma unroll
            for (int mf = 0; mf < 4; mf++)
                #pragma unroll
                for (int nf = 0; nf < 8; nf++)
                    mma_f16(acc[mf][nf], a[mf], b[nf]);
        }
        if (it + 2 < 8) {
            load_stage(it + 2, (it + 2) % 3);
            CP_WAIT(1);
        } else {
            CP_WAIT(0);
        }
        __syncthreads();
    }

    // ---- epilogue: v tile (fp16) -> smem [128][VP]; k tile -> smem ----
    __half* sv = (__half*)smem;
    const int er = lane >> 2;
    const int ec = (lane & 3) * 2;
    #pragma unroll
    for (int mf = 0; mf < 4; mf++) {
        #pragma unroll
        for (int nf = 0; nf < 8; nf++) {
            const int lr = wm * 64 + mf * 16 + er;
            const int lc = wn * 64 + nf * 8 + ec;
            *(__half2*)&sv[lr * VP + lc] =
                __floats2half2_rn(acc[mf][nf][0], acc[mf][nf][1]);
            *(__half2*)&sv[(lr + 8) * VP + lc] =
                __floats2half2_rn(acc[mf][nf][2], acc[mf][nf][3]);
        }
    }
    // k tile: 128 channel rows (CC + o0 + r), 128 n cols (256B data), pitch 272B
    const __half* kb = qk + ((size_t)bz * 2 * CC + CC + o0) * NN + n0;
    #pragma unroll
    for (int i = 0; i < 16; i++) {
        int idx = tid + i * 128;
        int r = idx >> 4, c = idx & 15;
        cp_async16(sbase + KV_KOFF + (uint32_t)(r * 272 + c * 16),
                   kb + (size_t)r * NN + c * 8);
    }
    CP_COMMIT();
    CP_WAIT(0);
    __syncthreads();

    // ---- kv mma: 4 warps = dgrp (16 d each); loop over heads; K = 128 n ----
    const int dgrp = wid;               // 0..3
    const int arow2 = lane & 15;
    const int acoff2 = (lane >> 4) * 16;
    const int bcoff2 = ((lane >> 3) & 1) * 16;
    const uint32_t ones[4] = {ONES2, ONES2, ONES2, ONES2};

    for (int head = 0; head < 2; head++) {
        float kacc[5][2][4];
        #pragma unroll
        for (int m = 0; m < 5; m++)
            #pragma unroll
            for (int nt = 0; nt < 2; nt++)
                #pragma unroll
                for (int e = 0; e < 4; e++) kacc[m][nt][e] = 0.f;

        const int brow2 = head * 64 + dgrp * 16 + ((lane >> 4) << 3) + (lane & 7);
        #pragma unroll
        for (int ks = 0; ks < 8; ks++) {
            uint32_t bf[4];
            ldmatrix_x4(bf, sbase + KV_KOFF + (uint32_t)(brow2 * 272 + ks * 32 + bcoff2));
            uint32_t b0[2] = {bf[0], bf[1]}, b1[2] = {bf[2], bf[3]};
            #pragma unroll
            for (int m = 0; m < 4; m++) {
                uint32_t a[4];
                ldmatrix_x4(a, sbase +
                            (uint32_t)((head * 64 + m * 16 + arow2) * 272 + ks * 32 + acoff2));
                mma_f16(kacc[m][0], a, b0);
                mma_f16(kacc[m][1], a, b1);
            }
            mma_f16(kacc[4][0], ones, b0);
            mma_f16(kacc[4][1], ones, b1);
        }

        // partials: chunk = blockIdx.x (n-tile), bh = bz*8 + blockIdx.y*2 + head
        const int bh = bz * 8 + blockIdx.y * 2 + head;
        float* outb = kvp + (size_t)blockIdx.x * (128 * 4160) + (size_t)bh * 4160;
        #pragma unroll
        for (int m = 0; m < 4; m++)
            #pragma unroll
            for (int nt = 0; nt < 2; nt++) {
                const int e = m * 16 + (lane >> 2);
                const int d = dgrp * 16 + nt * 8 + 2 * (lane & 3);
                *(float2*)&outb[e * 64 + d]       = make_float2(kacc[m][nt][0], kacc[m][nt][1]);
                *(float2*)&outb[(e + 8) * 64 + d] = make_float2(kacc[m][nt][2], kacc[m][nt][3]);
            }
        if (lane < 4) {
            #pragma unroll
            for (int nt = 0; nt < 2; nt++) {
                const int d = dgrp * 16 + nt * 8 + 2 * lane;
                *(float2*)&outb[4096 + d] = make_float2(kacc[4][nt][0], kacc[4][nt][1]);
            }
        }
    }
}

// ---------------------------------------------------------------------------
// Weight convert (all three in one launch)
// ---------------------------------------------------------------------------
__global__ void conv_w_all(const float* __restrict__ wqk, const float* __restrict__ wv,
                           const float* __restrict__ wo,
                           __half* __restrict__ oq, __half* __restrict__ ov,
                           __half* __restrict__ oo)
{
    int i = blockIdx.x * 256 + threadIdx.x;
    if (i < 524288) {
        oq[i] = __float2half_rn(wqk[i]);
    } else if (i < 786432) {
        int j = i - 524288; ov[j] = __float2half_rn(wv[j]);
    } else if (i < 1048576) {
        int j = i - 786432; oo[j] = __float2half_rn(wo[j]);
    }
}

// ---------------------------------------------------------------------------
// Transpose + fp16 convert: x, pos [B][C][N] fp32 -> xq=(x+pos), xv=x  [B][N][C]
// ---------------------------------------------------------------------------
__global__ __launch_bounds__(256) void conv_xt_kernel(
    const float* __restrict__ x, const float* __restrict__ pos,
    __half* __restrict__ xq, __half* __restrict__ xv)
{
    __shared__ float sA[64][65];
    __shared__ float sB[64][65];

    const int tid = threadIdx.x;
    const int n0 = blockIdx.x * 64;
    const int c0 = blockIdx.y * 64;
    const int bz = blockIdx.z;

    const float* i0 = x   + (size_t)bz * CC * NN;
    const float* i1 = pos + (size_t)bz * CC * NN;

    #pragma unroll
    for (int i = 0; i < 4; i++) {
        int idx = i * 256 + tid;
        int rc = idx >> 4, cn = (idx & 15) * 4;
        float4 xv4 = *(const float4*)&i0[(size_t)(c0 + rc) * NN + n0 + cn];
        float4 pv4 = *(const float4*)&i1[(size_t)(c0 + rc) * NN + n0 + cn];
        sA[rc][cn]     = xv4.x + pv4.x;
        sA[rc][cn + 1] = xv4.y + pv4.y;
        sA[rc][cn + 2] = xv4.z + pv4.z;
        sA[rc][cn + 3] = xv4.w + pv4.w;
        sB[rc][cn]     = xv4.x;
        sB[rc][cn + 1] = xv4.y;
        sB[rc][cn + 2] = xv4.z;
        sB[rc][cn + 3] = xv4.w;
    }
    __syncthreads();

    const size_t obase = ((size_t)bz * NN + n0) * CC + c0;
    #pragma unroll
    for (int i = 0; i < 8; i++) {
        int idx = i * 256 + tid;
        int nr = idx >> 5, cp = idx & 31;
        size_t oa = obase + (size_t)nr * CC + cp * 2;
        __half2 hq, hv;
        hq.x = __float2half_rn(sA[cp * 2][nr]);
        hq.y = __float2half_rn(sA[cp * 2 + 1][nr]);
        hv.x = __float2half_rn(sB[cp * 2][nr]);
        hv.y = __float2half_rn(sB[cp * 2 + 1][nr]);
        *(__half2*)(xq + oa) = hq;
        *(__half2*)(xv + oa) = hv;
    }
}

// ---------------------------------------------------------------------------
__global__ void kv_reduce(const float* __restrict__ kvp, float* __restrict__ kvout)
{
    int i = blockIdx.x * 256 + threadIdx.x;
    if (i < 128 * 4160) {
        float s = 0.f;
        #pragma unroll
        for (int c = 0; c < 32; c++) s += kvp[(size_t)c * (128 * 4160) + i];
        kvout[i] = s;
    }
}

// ---------------------------------------------------------------------------
// attn (tensor cores): out[e,n] = (kv @ q)[e,n] / (ksum@q[n] + EPS)
// ---------------------------------------------------------------------------
#define AT_AH 0
#define AT_AL 10240
#define AT_B  20480
#define AT_SCR 36864
#define ATTN_SMEM 55296

__global__ __launch_bounds__(128) void attn_tc_kernel(
    const __half* __restrict__ qk, const float* __restrict__ kv,
    __half* __restrict__ ao)
{
    extern __shared__ __align__(1024) char smem[];
    const uint32_t sbase = smem_u32(smem);
    __half* S1   = (__half*)(smem + AT_SCR);
    __half* sOut = (__half*)(smem + AT_SCR);

    const int tid  = threadIdx.x;
    const int wid  = tid >> 5;
    const int lane = tid & 31;
    const int bh   = blockIdx.y;
    const int b = bh >> 3, h = bh & 7;
    const int n0 = blockIdx.x * 128;

    const __half* qbase = qk + ((size_t)b * 2 * CC + h * HD) * NN + n0;
    #pragma unroll
    for (int i = 0; i < 8; i++) {
        int idx = tid + i * 128;
        int d = idx >> 4, j = idx & 15;
        cp_async16(sbase + AT_SCR + (uint32_t)(d * 288 + j * 16),
                   qbase + (size_t)d * NN + j * 8);
    }
    CP_COMMIT();

    {
        uint4 z = {0, 0, 0, 0};
        for (int i = tid; i < 1280; i += 128)
            *(uint4*)(smem + AT_AH + i * 16) = z;
    }
    __syncthreads();
    const float* kvb = kv + (size_t)bh * 4160;
    for (int i = tid; i < 4160; i += 128) {
        int e = i >> 6, d = i & 63;
        float f = kvb[i];
        __half hi = __float2half_rn(f);
        __half lo = __float2half_rn(f - __half2float(hi));
        uint32_t off = SWZ128((uint32_t)(e * 128 + d * 2));
        *(__half*)(smem + AT_AH + off) = hi;
        *(__half*)(smem + AT_AL + off) = lo;
    }
    CP_WAIT(0);
    __syncthreads();

    {
        union { __half hh[8]; uint4 u; } pk;
        const int n = tid;
        #pragma unroll
        for (int j = 0; j < 8; j++) {
            #pragma unroll
            for (int d2 = 0; d2 < 8; d2++)
                pk.hh[d2] = S1[(j * 8 + d2) * 144 + n];
            *(uint4*)(smem + AT_B + SWZ128((uint32_t)(n * 128 + j * 16))) = pk.u;
        }
    }
    __syncthreads();

    float acc[5][4][4];
    #pragma unroll
    for (int m = 0; m < 5; m++)
        #pragma unroll
        for (int nt = 0; nt < 4; nt++)
            #pragma unroll
            for (int e = 0; e < 4; e++) acc[m][nt][e] = 0.f;

    const int a_row  = lane & 15;
    const int a_coff = (lane >> 4) * 16;
    const int b_coff = ((lane >> 3) & 1) * 16;

    #pragma unroll
    for (int ks = 0; ks < 4; ks++) {
        uint32_t ah[5][4], al[5][4], bfr[4][2];
        #pragma unroll
        for (int m = 0; m < 5; m++) {
            const uint32_t so = SWZ128((uint32_t)((m * 16 + a_row) * 128 + ks * 32 + a_coff));
            ldmatrix_x4(ah[m], sbase + AT_AH + so);
            ldmatrix_x4(al[m], sbase + AT_AL + so);
        }
        #pragma unroll
        for (int g = 0; g < 2; g++) {
            const int brow = wid * 32 + g * 16 + ((lane >> 4) << 3) + (lane & 7);
            uint32_t r[4];
            ldmatrix_x4(r, sbase + AT_B + SWZ128((uint32_t)(brow * 128 + ks * 32 + b_coff)));
            bfr[g * 2][0] = r[0];  bfr[g * 2][1] = r[1];
            bfr[g * 2 + 1][0] = r[2];  bfr[g * 2 + 1][1] = r[3];
        }
        #pragma unroll
        for (int m = 0; m < 5; m++)
            #pragma unroll
            for (int nt = 0; nt < 4; nt++) {
                mma_f16(acc[m][nt], ah[m], bfr[nt]);
                mma_f16(acc[m][nt], al[m], bfr[nt]);
            }
    }

    #pragma unroll
    for (int nt = 0; nt < 4; nt++) {
        float den0 = __shfl_sync(0xffffffffu, acc[4][nt][0], lane & 3);
        float den1 = __shfl_sync(0xffffffffu, acc[4][nt][1], lane & 3);
        float inv0 = 1.f / (den0 + EPS);
        float inv1 = 1.f / (den1 + EPS);
        const int n = wid * 32 + nt * 8 + 2 * (lane & 3);
        #pragma unroll
        for (int m = 0; m < 4; m++) {
            const int e = m * 16 + (lane >> 2);
            sOut[n * 72 + e]           = __float2half_rn(acc[m][nt][0] * inv0);
            sOut[(n + 1) * 72 + e]     = __float2half_rn(acc[m][nt][1] * inv1);
            sOut[n * 72 + e + 8]       = __float2half_rn(acc[m][nt][2] * inv0);
            sOut[(n + 1) * 72 + e + 8] = __float2half_rn(acc[m][nt][3] * inv1);
        }
    }
    __syncthreads();

    {
        const int n = tid;
        __half* dst = ao + ((size_t)b * NN + n0 + n) * CC + h * HD;
        #pragma unroll
        for (int j = 0; j < 8; j++)
            *(uint4*)(dst + j * 8) = *(uint4*)(sOut + n * 72 + j * 8);
    }
}

// ---------------------------------------------------------------------------
extern "C" void kernel_launch(void* const* d_in, const int* in_sizes, int n_in,
                              void* d_out, int out_size)
{
    const float* x    = (const float*)d_in[0];
    const float* pos  = (const float*)d_in[1];
    const float* w_qk = (const float*)d_in[2];
    const float* w_v  = (const float*)d_in[3];
    const float* w_o  = (const float*)d_in[4];
    float* out = (float*)d_out;

    __half *qk;
    float *kvp, *kvr;
    cudaGetSymbolAddress((void**)&qk,  g_qkh);
    cudaGetSymbolAddress((void**)&kvp, g_kvp);
    cudaGetSymbolAddress((void**)&kvr, g_kv);
    __half *xq, *xv, *ao, *wq, *wv, *wo;
    cudaGetSymbolAddress((void**)&xq, g_xq);
    cudaGetSymbolAddress((void**)&xv, g_xv);
    cudaGetSymbolAddress((void**)&ao, g_ao);
    cudaGetSymbolAddress((void**)&wq, g_wqk);
    cudaGetSymbolAddress((void**)&wv, g_wv);
    cudaGetSymbolAddress((void**)&wo, g_wo);

    cudaFuncSetAttribute(gemm_tc<true, true>,
                         cudaFuncAttributeMaxDynamicSharedMemorySize, GEMM_SMEM);
    cudaFuncSetAttribute(gemm_tc<false, false>,
                         cudaFuncAttributeMaxDynamicSharedMemorySize, GEMM_SMEM);
    cudaFuncSetAttribute(gemm_v_kv,
                         cudaFuncAttributeMaxDynamicSharedMemorySize, GEMM_SMEM);
    cudaFuncSetAttribute(attn_tc_kernel,
                         cudaFuncAttributeMaxDynamicSharedMemorySize, ATTN_SMEM);

    // 0) weight converts (fp16), single launch
    conv_w_all<<<4096, 256>>>(w_qk, w_v, w_o, wq, wv, wo);

    // 1) x / x+pos -> transposed fp16
    conv_xt_kernel<<<dim3(NN / 64, CC / 64, BB), 256>>>(x, pos, xq, xv);

    // 2) qk = relu(w_qk @ (x+pos)) -> fp16
    gemm_tc<true, true><<<dim3(NN / 128, 1024 / 128, BB), 128, GEMM_SMEM>>>(
        wq, xq, qk, 1024);

    // 3+4) v GEMM fused with kv partials
    gemm_v_kv<<<dim3(NN / 128, 512 / 128, BB), 128, GEMM_SMEM>>>(
        wv, xv, qk, kvp);
    kv_reduce<<<(128 * 4160 + 255) / 256, 256>>>(kvp, kvr);

    // 5) attn (tensor) -> fp16 transposed [B][N][C]
    attn_tc_kernel<<<dim3(NN / 128, 128), 128, ATTN_SMEM>>>(qk, kvr, ao);

    // 6) out = w_o @ attn -> fp32 (d_out)
    gemm_tc<false, false><<<dim3(NN / 128, 512 / 128, BB), 128, GEMM_SMEM>>>(
        wo, ao, out, 512);
}

// round 11
// speedup vs baseline: 7.0466x; 1.0514x over previous
#include <cuda_runtime.h>
#include <cuda_fp16.h>
#include <cstdint>
#include <cstddef>

// Problem constants
#define BB   16
#define CC   512
#define NN   4096
#define NH   8
#define HD   64
#define EPS  1e-6f
#define NGRP 4
#define GB   (BB / NGRP)   // batches per group = 4

// ---------------------------------------------------------------------------
// Scratch (device globals: allocation-free rule)
// ---------------------------------------------------------------------------
__device__ __half g_qkh[(size_t)BB * 2 * CC * NN]; // [B][1024][4096] relu(qk) fp16
__device__ float g_kvp[(size_t)32 * 128 * 65 * 64];// split-K partials (32 chunks)
__device__ float g_kv [(size_t)128 * 65 * 64];     // [B*nh][65][64] fp32

// fp16 activations, [B][N][C] K-major
__device__ __half g_xq[(size_t)BB * NN * CC];      // x + pos
__device__ __half g_xv[(size_t)BB * NN * CC];      // x
__device__ __half g_ao[(size_t)BB * NN * CC];      // attn output (transposed)
// weights fp16, [O][C] K-major
__device__ __half g_wqk[1024 * 512];
__device__ __half g_wv [512 * 512];
__device__ __half g_wo [512 * 512];

// ---------------------------------------------------------------------------
// Helpers
// ---------------------------------------------------------------------------
__device__ __forceinline__ uint32_t smem_u32(const void* p) {
    uint32_t a;
    asm("{ .reg .u64 t; cvta.to.shared.u64 t, %1; cvt.u32.u64 %0, t; }" : "=r"(a) : "l"(p));
    return a;
}
#define SWZ128(off) ((off) ^ (((off) >> 3) & 0x70))
#define ONES2 0x3C003C00u

__device__ __forceinline__ void cp_async16(uint32_t s, const void* g) {
    asm volatile("cp.async.cg.shared.global [%0], [%1], 16;" :: "r"(s), "l"(g));
}
#define CP_COMMIT() asm volatile("cp.async.commit_group;" ::: "memory")
#define CP_WAIT(n)  asm volatile("cp.async.wait_group %0;" :: "n"(n) : "memory")

__device__ __forceinline__ void ldmatrix_x4(uint32_t* r, uint32_t addr) {
    asm volatile("ldmatrix.sync.aligned.m8n8.x4.shared.b16 {%0,%1,%2,%3}, [%4];"
                 : "=r"(r[0]), "=r"(r[1]), "=r"(r[2]), "=r"(r[3]) : "r"(addr));
}
__device__ __forceinline__ void mma_f16(float* d, const uint32_t* a, const uint32_t* b) {
    asm volatile(
        "mma.sync.aligned.m16n8k16.row.col.f32.f16.f16.f32 "
        "{%0,%1,%2,%3}, {%4,%5,%6,%7}, {%8,%9}, {%0,%1,%2,%3};"
        : "+f"(d[0]), "+f"(d[1]), "+f"(d[2]), "+f"(d[3])
        : "r"(a[0]), "r"(a[1]), "r"(a[2]), "r"(a[3]), "r"(b[0]), "r"(b[1]));
}

// 128-thread GEMM config: BM=128, BN=128, BK=64, warp tile 64x64, 3 stages.
#define BKB 128
#define B_OFF  16384
#define STG    32768
#define GEMM_SMEM (3 * STG)

// ---------------------------------------------------------------------------
// qk / o projection GEMM:  Y[O,N] = W[O,C] @ X[C,N]  (batches bz0 + blockIdx.z)
// ---------------------------------------------------------------------------
template<bool RELU, bool HOUT>
__global__ __launch_bounds__(128, 2) void gemm_tc(
    const __half* __restrict__ A, const __half* __restrict__ Bx,
    void* __restrict__ Yv, int O, int bz0)
{
    extern __shared__ __align__(1024) char smem[];
    const uint32_t sbase = smem_u32(smem);
    const int tid  = threadIdx.x;
    const int wid  = tid >> 5;
    const int lane = tid & 31;
    const int wm   = wid & 1;
    const int wn   = wid >> 1;

    const int n0 = blockIdx.x * 128;
    const int o0 = blockIdx.y * 128;
    const int bz = bz0 + blockIdx.z;

    const __half* Bb = Bx + (size_t)bz * NN * CC;

    auto load_stage = [&](int ck, int st) {
        const int k0 = ck * 64;
        const uint32_t sb = sbase + st * STG;
        #pragma unroll
        for (int i = 0; i < 8; i++) {
            int c = tid + i * 128;
            int row = c >> 3, cc = c & 7;
            cp_async16(sb + SWZ128((uint32_t)(row * BKB + cc * 16)),
                       A + (size_t)(o0 + row) * CC + k0 + cc * 8);
        }
        #pragma unroll
        for (int i = 0; i < 8; i++) {
            int c = tid + i * 128;
            int row = c >> 3, cc = c & 7;
            cp_async16(sb + B_OFF + SWZ128((uint32_t)(row * BKB + cc * 16)),
                       Bb + (size_t)(n0 + row) * CC + k0 + cc * 8);
        }
        CP_COMMIT();
    };

    float acc[4][8][4];
    #pragma unroll
    for (int mf = 0; mf < 4; mf++)
        #pragma unroll
        for (int nf = 0; nf < 8; nf++)
            #pragma unroll
            for (int e = 0; e < 4; e++) acc[mf][nf][e] = 0.f;

    load_stage(0, 0);
    load_stage(1, 1);
    CP_WAIT(1);
    __syncthreads();

    const int a_row  = wm * 64 + (lane & 15);
    const int a_coff = (lane >> 4) * 16;
    const int b_row  = wn * 64 + ((lane >> 4) << 3) + (lane & 7);
    const int b_coff = ((lane >> 3) & 1) * 16;

    for (int it = 0; it < 8; it++) {
        const uint32_t sb = sbase + (it % 3) * STG;
        #pragma unroll
        for (int kk = 0; kk < 4; kk++) {
            uint32_t a[4][4], b[8][2];
            #pragma unroll
            for (int mf = 0; mf < 4; mf++)
                ldmatrix_x4(a[mf], sb +
                            SWZ128((uint32_t)((a_row + mf * 16) * BKB + kk * 32 + a_coff)));
            #pragma unroll
            for (int ng = 0; ng < 4; ng++) {
                uint32_t r[4];
                ldmatrix_x4(r, sb + B_OFF +
                            SWZ128((uint32_t)((b_row + ng * 16) * BKB + kk * 32 + b_coff)));
                b[ng * 2][0] = r[0];  b[ng * 2][1] = r[1];
                b[ng * 2 + 1][0] = r[2];  b[ng * 2 + 1][1] = r[3];
            }
            #pragma unroll
            for (int mf = 0; mf < 4; mf++)
                #pragma unroll
                for (int nf = 0; nf < 8; nf++)
                    mma_f16(acc[mf][nf], a[mf], b[nf]);
        }
        if (it + 2 < 8) {
            load_stage(it + 2, (it + 2) % 3);
            CP_WAIT(1);
        } else {
            CP_WAIT(0);
        }
        __syncthreads();
    }

    const int er = lane >> 2;
    const int ec = (lane & 3) * 2;
    #pragma unroll
    for (int mf = 0; mf < 4; mf++) {
        #pragma unroll
        for (int nf = 0; nf < 8; nf++) {
            const int orow = o0 + wm * 64 + mf * 16 + er;
            const int ocol = n0 + wn * 64 + nf * 8 + ec;
            float v0x = acc[mf][nf][0], v0y = acc[mf][nf][1];
            float v1x = acc[mf][nf][2], v1y = acc[mf][nf][3];
            if (RELU) {
                v0x = fmaxf(v0x, 0.f); v0y = fmaxf(v0y, 0.f);
                v1x = fmaxf(v1x, 0.f); v1y = fmaxf(v1y, 0.f);
            }
            if (HOUT) {
                __half* Yb = (__half*)Yv + (size_t)bz * O * NN;
                *(__half2*)&Yb[(size_t)orow * NN + ocol] = __floats2half2_rn(v0x, v0y);
                *(__half2*)&Yb[(size_t)(orow + 8) * NN + ocol] = __floats2half2_rn(v1x, v1y);
            } else {
                float* Yb = (float*)Yv + (size_t)bz * O * NN;
                *(float2*)&Yb[(size_t)orow * NN + ocol]       = make_float2(v0x, v0y);
                *(float2*)&Yb[(size_t)(orow + 8) * NN + ocol] = make_float2(v1x, v1y);
            }
        }
    }
}

// ---------------------------------------------------------------------------
// Fused v-GEMM + kv (batches bz0 + blockIdx.z)
// ---------------------------------------------------------------------------
#define VP 136
#define KV_KOFF 34816

__global__ __launch_bounds__(128, 2) void gemm_v_kv(
    const __half* __restrict__ A, const __half* __restrict__ Bx,
    const __half* __restrict__ qk, float* __restrict__ kvp, int bz0)
{
    extern __shared__ __align__(1024) char smem[];
    const uint32_t sbase = smem_u32(smem);
    const int tid  = threadIdx.x;
    const int wid  = tid >> 5;
    const int lane = tid & 31;
    const int wm   = wid & 1;
    const int wn   = wid >> 1;

    const int n0 = blockIdx.x * 128;
    const int o0 = blockIdx.y * 128;
    const int bz = bz0 + blockIdx.z;

    const __half* Bb = Bx + (size_t)bz * NN * CC;

    auto load_stage = [&](int ck, int st) {
        const int k0 = ck * 64;
        const uint32_t sb = sbase + st * STG;
        #pragma unroll
        for (int i = 0; i < 8; i++) {
            int c = tid + i * 128;
            int row = c >> 3, cc = c & 7;
            cp_async16(sb + SWZ128((uint32_t)(row * BKB + cc * 16)),
                       A + (size_t)(o0 + row) * CC + k0 + cc * 8);
        }
        #pragma unroll
        for (int i = 0; i < 8; i++) {
            int c = tid + i * 128;
            int row = c >> 3, cc = c & 7;
            cp_async16(sb + B_OFF + SWZ128((uint32_t)(row * BKB + cc * 16)),
                       Bb + (size_t)(n0 + row) * CC + k0 + cc * 8);
        }
        CP_COMMIT();
    };

    float acc[4][8][4];
    #pragma unroll
    for (int mf = 0; mf < 4; mf++)
        #pragma unroll
        for (int nf = 0; nf < 8; nf++)
            #pragma unroll
            for (int e = 0; e < 4; e++) acc[mf][nf][e] = 0.f;

    load_stage(0, 0);
    load_stage(1, 1);
    CP_WAIT(1);
    __syncthreads();

    const int a_row  = wm * 64 + (lane & 15);
    const int a_coff = (lane >> 4) * 16;
    const int b_row  = wn * 64 + ((lane >> 4) << 3) + (lane & 7);
    const int b_coff = ((lane >> 3) & 1) * 16;

    for (int it = 0; it < 8; it++) {
        const uint32_t sb = sbase + (it % 3) * STG;
        #pragma unroll
        for (int kk = 0; kk < 4; kk++) {
            uint32_t a[4][4], b[8][2];
            #pragma unroll
            for (int mf = 0; mf < 4; mf++)
                ldmatrix_x4(a[mf], sb +
                            SWZ128((uint32_t)((a_row + mf * 16) * BKB + kk * 32 + a_coff)));
            #pragma unroll
            for (int ng = 0; ng < 4; ng++) {
                uint32_t r[4];
                ldmatrix_x4(r, sb + B_OFF +
                            SWZ128((uint32_t)((b_row + ng * 16) * BKB + kk * 32 + b_coff)));
                b[ng * 2][0] = r[0];  b[ng * 2][1] = r[1];
                b[ng * 2 + 1][0] = r[2];  b[ng * 2 + 1][1] = r[3];
            }
            #pragma unroll
            for (int mf = 0; mf < 4; mf++)
                #pragma unroll
                for (int nf = 0; nf < 8; nf++)
                    mma_f16(acc[mf][nf], a[mf], b[nf]);
        }
        if (it + 2 < 8) {
            load_stage(it + 2, (it + 2) % 3);
            CP_WAIT(1);
        } else {
            CP_WAIT(0);
        }
        __syncthreads();
    }

    // ---- epilogue: v tile (fp16) -> smem [128][VP]; k tile -> smem ----
    __half* sv = (__half*)smem;
    const int er = lane >> 2;
    const int ec = (lane & 3) * 2;
    #pragma unroll
    for (int mf = 0; mf < 4; mf++) {
        #pragma unroll
        for (int nf = 0; nf < 8; nf++) {
            const int lr = wm * 64 + mf * 16 + er;
            const int lc = wn * 64 + nf * 8 + ec;
            *(__half2*)&sv[lr * VP + lc] =
                __floats2half2_rn(acc[mf][nf][0], acc[mf][nf][1]);
            *(__half2*)&sv[(lr + 8) * VP + lc] =
                __floats2half2_rn(acc[mf][nf][2], acc[mf][nf][3]);
        }
    }
    const __half* kb = qk + ((size_t)bz * 2 * CC + CC + o0) * NN + n0;
    #pragma unroll
    for (int i = 0; i < 16; i++) {
        int idx = tid + i * 128;
        int r = idx >> 4, c = idx & 15;
        cp_async16(sbase + KV_KOFF + (uint32_t)(r * 272 + c * 16),
                   kb + (size_t)r * NN + c * 8);
    }
    CP_COMMIT();
    CP_WAIT(0);
    __syncthreads();

    const int dgrp = wid;
    const int arow2 = lane & 15;
    const int acoff2 = (lane >> 4) * 16;
    const int bcoff2 = ((lane >> 3) & 1) * 16;
    const uint32_t ones[4] = {ONES2, ONES2, ONES2, ONES2};

    for (int head = 0; head < 2; head++) {
        float kacc[5][2][4];
        #pragma unroll
        for (int m = 0; m < 5; m++)
            #pragma unroll
            for (int nt = 0; nt < 2; nt++)
                #pragma unroll
                for (int e = 0; e < 4; e++) kacc[m][nt][e] = 0.f;

        const int brow2 = head * 64 + dgrp * 16 + ((lane >> 4) << 3) + (lane & 7);
        #pragma unroll
        for (int ks = 0; ks < 8; ks++) {
            uint32_t bf[4];
            ldmatrix_x4(bf, sbase + KV_KOFF + (uint32_t)(brow2 * 272 + ks * 32 + bcoff2));
            uint32_t b0[2] = {bf[0], bf[1]}, b1[2] = {bf[2], bf[3]};
            #pragma unroll
            for (int m = 0; m < 4; m++) {
                uint32_t a[4];
                ldmatrix_x4(a, sbase +
                            (uint32_t)((head * 64 + m * 16 + arow2) * 272 + ks * 32 + acoff2));
                mma_f16(kacc[m][0], a, b0);
                mma_f16(kacc[m][1], a, b1);
            }
            mma_f16(kacc[4][0], ones, b0);
            mma_f16(kacc[4][1], ones, b1);
        }

        const int bh = bz * 8 + blockIdx.y * 2 + head;
        float* outb = kvp + (size_t)blockIdx.x * (128 * 4160) + (size_t)bh * 4160;
        #pragma unroll
        for (int m = 0; m < 4; m++)
            #pragma unroll
            for (int nt = 0; nt < 2; nt++) {
                const int e = m * 16 + (lane >> 2);
                const int d = dgrp * 16 + nt * 8 + 2 * (lane & 3);
                *(float2*)&outb[e * 64 + d]       = make_float2(kacc[m][nt][0], kacc[m][nt][1]);
                *(float2*)&outb[(e + 8) * 64 + d] = make_float2(kacc[m][nt][2], kacc[m][nt][3]);
            }
        if (lane < 4) {
            #pragma unroll
            for (int nt = 0; nt < 2; nt++) {
                const int d = dgrp * 16 + nt * 8 + 2 * lane;
                *(float2*)&outb[4096 + d] = make_float2(kacc[4][nt][0], kacc[4][nt][1]);
            }
        }
    }
}

// ---------------------------------------------------------------------------
// Weight convert (all three in one launch)
// ---------------------------------------------------------------------------
__global__ void conv_w_all(const float* __restrict__ wqk, const float* __restrict__ wv,
                           const float* __restrict__ wo,
                           __half* __restrict__ oq, __half* __restrict__ ov,
                           __half* __restrict__ oo)
{
    int i = blockIdx.x * 256 + threadIdx.x;
    if (i < 524288) {
        oq[i] = __float2half_rn(wqk[i]);
    } else if (i < 786432) {
        int j = i - 524288; ov[j] = __float2half_rn(wv[j]);
    } else if (i < 1048576) {
        int j = i - 786432; oo[j] = __float2half_rn(wo[j]);
    }
}

// ---------------------------------------------------------------------------
// Transpose + fp16 convert (batches bz0 + blockIdx.z)
// ---------------------------------------------------------------------------
__global__ __launch_bounds__(256) void conv_xt_kernel(
    const float* __restrict__ x, const float* __restrict__ pos,
    __half* __restrict__ xq, __half* __restrict__ xv, int bz0)
{
    __shared__ float sA[64][65];
    __shared__ float sB[64][65];

    const int tid = threadIdx.x;
    const int n0 = blockIdx.x * 64;
    const int c0 = blockIdx.y * 64;
    const int bz = bz0 + blockIdx.z;

    const float* i0 = x   + (size_t)bz * CC * NN;
    const float* i1 = pos + (size_t)bz * CC * NN;

    #pragma unroll
    for (int i = 0; i < 4; i++) {
        int idx = i * 256 + tid;
        int rc = idx >> 4, cn = (idx & 15) * 4;
        float4 xv4 = *(const float4*)&i0[(size_t)(c0 + rc) * NN + n0 + cn];
        float4 pv4 = *(const float4*)&i1[(size_t)(c0 + rc) * NN + n0 + cn];
        sA[rc][cn]     = xv4.x + pv4.x;
        sA[rc][cn + 1] = xv4.y + pv4.y;
        sA[rc][cn + 2] = xv4.z + pv4.z;
        sA[rc][cn + 3] = xv4.w + pv4.w;
        sB[rc][cn]     = xv4.x;
        sB[rc][cn + 1] = xv4.y;
        sB[rc][cn + 2] = xv4.z;
        sB[rc][cn + 3] = xv4.w;
    }
    __syncthreads();

    const size_t obase = ((size_t)bz * NN + n0) * CC + c0;
    #pragma unroll
    for (int i = 0; i < 8; i++) {
        int idx = i * 256 + tid;
        int nr = idx >> 5, cp = idx & 31;
        size_t oa = obase + (size_t)nr * CC + cp * 2;
        __half2 hq, hv;
        hq.x = __float2half_rn(sA[cp * 2][nr]);
        hq.y = __float2half_rn(sA[cp * 2 + 1][nr]);
        hv.x = __float2half_rn(sB[cp * 2][nr]);
        hv.y = __float2half_rn(sB[cp * 2 + 1][nr]);
        *(__half2*)(xq + oa) = hq;
        *(__half2*)(xv + oa) = hv;
    }
}

// ---------------------------------------------------------------------------
// kv reduce for one group of bh (32 bh per group)
// ---------------------------------------------------------------------------
__global__ void kv_reduce(const float* __restrict__ kvp, float* __restrict__ kvout,
                          int bh0)
{
    int i = blockIdx.x * 256 + threadIdx.x;
    if (i < GB * 8 * 4160) {
        size_t j = (size_t)bh0 * 4160 + i;
        float s = 0.f;
        #pragma unroll
        for (int c = 0; c < 32; c++) s += kvp[(size_t)c * (128 * 4160) + j];
        kvout[j] = s;
    }
}

// ---------------------------------------------------------------------------
// attn (tensor cores): out[e,n] = (kv @ q)[e,n] / (ksum@q[n] + EPS)
// ---------------------------------------------------------------------------
#define AT_AH 0
#define AT_AL 10240
#define AT_B  20480
#define AT_SCR 36864
#define ATTN_SMEM 55296

__global__ __launch_bounds__(128) void attn_tc_kernel(
    const __half* __restrict__ qk, const float* __restrict__ kv,
    __half* __restrict__ ao, int bh0)
{
    extern __shared__ __align__(1024) char smem[];
    const uint32_t sbase = smem_u32(smem);
    __half* S1   = (__half*)(smem + AT_SCR);
    __half* sOut = (__half*)(smem + AT_SCR);

    const int tid  = threadIdx.x;
    const int wid  = tid >> 5;
    const int lane = tid & 31;
    const int bh   = bh0 + blockIdx.y;
    const int b = bh >> 3, h = bh & 7;
    const int n0 = blockIdx.x * 128;

    const __half* qbase = qk + ((size_t)b * 2 * CC + h * HD) * NN + n0;
    #pragma unroll
    for (int i = 0; i < 8; i++) {
        int idx = tid + i * 128;
        int d = idx >> 4, j = idx & 15;
        cp_async16(sbase + AT_SCR + (uint32_t)(d * 288 + j * 16),
                   qbase + (size_t)d * NN + j * 8);
    }
    CP_COMMIT();

    {
        uint4 z = {0, 0, 0, 0};
        for (int i = tid; i < 1280; i += 128)
            *(uint4*)(smem + AT_AH + i * 16) = z;
    }
    __syncthreads();
    const float* kvb = kv + (size_t)bh * 4160;
    for (int i = tid; i < 4160; i += 128) {
        int e = i >> 6, d = i & 63;
        float f = kvb[i];
        __half hi = __float2half_rn(f);
        __half lo = __float2half_rn(f - __half2float(hi));
        uint32_t off = SWZ128((uint32_t)(e * 128 + d * 2));
        *(__half*)(smem + AT_AH + off) = hi;
        *(__half*)(smem + AT_AL + off) = lo;
    }
    CP_WAIT(0);
    __syncthreads();

    {
        union { __half hh[8]; uint4 u; } pk;
        const int n = tid;
        #pragma unroll
        for (int j = 0; j < 8; j++) {
            #pragma unroll
            for (int d2 = 0; d2 < 8; d2++)
                pk.hh[d2] = S1[(j * 8 + d2) * 144 + n];
            *(uint4*)(smem + AT_B + SWZ128((uint32_t)(n * 128 + j * 16))) = pk.u;
        }
    }
    __syncthreads();

    float acc[5][4][4];
    #pragma unroll
    for (int m = 0; m < 5; m++)
        #pragma unroll
        for (int nt = 0; nt < 4; nt++)
            #pragma unroll
            for (int e = 0; e < 4; e++) acc[m][nt][e] = 0.f;

    const int a_row  = lane & 15;
    const int a_coff = (lane >> 4) * 16;
    const int b_coff = ((lane >> 3) & 1) * 16;

    #pragma unroll
    for (int ks = 0; ks < 4; ks++) {
        uint32_t ah[5][4], al[5][4], bfr[4][2];
        #pragma unroll
        for (int m = 0; m < 5; m++) {
            const uint32_t so = SWZ128((uint32_t)((m * 16 + a_row) * 128 + ks * 32 + a_coff));
            ldmatrix_x4(ah[m], sbase + AT_AH + so);
            ldmatrix_x4(al[m], sbase + AT_AL + so);
        }
        #pragma unroll
        for (int g = 0; g < 2; g++) {
            const int brow = wid * 32 + g * 16 + ((lane >> 4) << 3) + (lane & 7);
            uint32_t r[4];
            ldmatrix_x4(r, sbase + AT_B + SWZ128((uint32_t)(brow * 128 + ks * 32 + b_coff)));
            bfr[g * 2][0] = r[0];  bfr[g * 2][1] = r[1];
            bfr[g * 2 + 1][0] = r[2];  bfr[g * 2 + 1][1] = r[3];
        }
        #pragma unroll
        for (int m = 0; m < 5; m++)
            #pragma unroll
            for (int nt = 0; nt < 4; nt++) {
                mma_f16(acc[m][nt], ah[m], bfr[nt]);
                mma_f16(acc[m][nt], al[m], bfr[nt]);
            }
    }

    #pragma unroll
    for (int nt = 0; nt < 4; nt++) {
        float den0 = __shfl_sync(0xffffffffu, acc[4][nt][0], lane & 3);
        float den1 = __shfl_sync(0xffffffffu, acc[4][nt][1], lane & 3);
        float inv0 = 1.f / (den0 + EPS);
        float inv1 = 1.f / (den1 + EPS);
        const int n = wid * 32 + nt * 8 + 2 * (lane & 3);
        #pragma unroll
        for (int m = 0; m < 4; m++) {
            const int e = m * 16 + (lane >> 2);
            sOut[n * 72 + e]           = __float2half_rn(acc[m][nt][0] * inv0);
            sOut[(n + 1) * 72 + e]     = __float2half_rn(acc[m][nt][1] * inv1);
            sOut[n * 72 + e + 8]       = __float2half_rn(acc[m][nt][2] * inv0);
            sOut[(n + 1) * 72 + e + 8] = __float2half_rn(acc[m][nt][3] * inv1);
        }
    }
    __syncthreads();

    {
        const int n = tid;
        __half* dst = ao + ((size_t)b * NN + n0 + n) * CC + h * HD;
        #pragma unroll
        for (int j = 0; j < 8; j++)
            *(uint4*)(dst + j * 8) = *(uint4*)(sOut + n * 72 + j * 8);
    }
}

// ---------------------------------------------------------------------------
extern "C" void kernel_launch(void* const* d_in, const int* in_sizes, int n_in,
                              void* d_out, int out_size)
{
    const float* x    = (const float*)d_in[0];
    const float* pos  = (const float*)d_in[1];
    const float* w_qk = (const float*)d_in[2];
    const float* w_v  = (const float*)d_in[3];
    const float* w_o  = (const float*)d_in[4];
    float* out = (float*)d_out;

    __half *qk;
    float *kvp, *kvr;
    cudaGetSymbolAddress((void**)&qk,  g_qkh);
    cudaGetSymbolAddress((void**)&kvp, g_kvp);
    cudaGetSymbolAddress((void**)&kvr, g_kv);
    __half *xq, *xv, *ao, *wq, *wv, *wo;
    cudaGetSymbolAddress((void**)&xq, g_xq);
    cudaGetSymbolAddress((void**)&xv, g_xv);
    cudaGetSymbolAddress((void**)&ao, g_ao);
    cudaGetSymbolAddress((void**)&wq, g_wqk);
    cudaGetSymbolAddress((void**)&wv, g_wv);
    cudaGetSymbolAddress((void**)&wo, g_wo);

    cudaFuncSetAttribute(gemm_tc<true, true>,
                         cudaFuncAttributeMaxDynamicSharedMemorySize, GEMM_SMEM);
    cudaFuncSetAttribute(gemm_tc<false, false>,
                         cudaFuncAttributeMaxDynamicSharedMemorySize, GEMM_SMEM);
    cudaFuncSetAttribute(gemm_v_kv,
                         cudaFuncAttributeMaxDynamicSharedMemorySize, GEMM_SMEM);
    cudaFuncSetAttribute(attn_tc_kernel,
                         cudaFuncAttributeMaxDynamicSharedMemorySize, ATTN_SMEM);

    // Fork-join multi-stream pipeline across 4 batch groups.
    // Streams/events are created ONCE per process (resource handles only; the
    // submitted work is identical on every call, so determinism holds). This
    // avoids growing the driver's stream pool during graph capture, which
    // tripped the allocation checkpoint when handles were created per call.
    // Group 0 runs on the origin stream; 3 forked streams serve groups 1-3.
    static cudaStream_t s_st[NGRP - 1];
    static cudaEvent_t  s_evRoot;
    static cudaEvent_t  s_evDone[NGRP - 1];
    static bool s_init = false;
    if (!s_init) {
        for (int g = 0; g < NGRP - 1; g++)
            cudaStreamCreateWithFlags(&s_st[g], cudaStreamNonBlocking);
        cudaEventCreateWithFlags(&s_evRoot, cudaEventDisableTiming);
        for (int g = 0; g < NGRP - 1; g++)
            cudaEventCreateWithFlags(&s_evDone[g], cudaEventDisableTiming);
        s_init = true;
    }

    // 0) weight converts on origin stream
    conv_w_all<<<4096, 256>>>(w_qk, w_v, w_o, wq, wv, wo);
    cudaEventRecord(s_evRoot, 0);

    auto chain = [&](int g, cudaStream_t stm) {
        const int bz0 = g * GB;
        const int bh0 = bz0 * NH;

        conv_xt_kernel<<<dim3(NN / 64, CC / 64, GB), 256, 0, stm>>>(
            x, pos, xq, xv, bz0);
        gemm_tc<true, true><<<dim3(NN / 128, 1024 / 128, GB), 128, GEMM_SMEM, stm>>>(
            wq, xq, qk, 1024, bz0);
        gemm_v_kv<<<dim3(NN / 128, 512 / 128, GB), 128, GEMM_SMEM, stm>>>(
            wv, xv, qk, kvp, bz0);
        kv_reduce<<<(GB * 8 * 4160 + 255) / 256, 256, 0, stm>>>(kvp, kvr, bh0);
        attn_tc_kernel<<<dim3(NN / 128, GB * 8), 128, ATTN_SMEM, stm>>>(
            qk, kvr, ao, bh0);
        gemm_tc<false, false><<<dim3(NN / 128, 512 / 128, GB), 128, GEMM_SMEM, stm>>>(
            wo, ao, out, 512, bz0);
    };

    // group 0 on the origin stream (ordered after conv_w_all implicitly)
    chain(0, (cudaStream_t)0);

    // groups 1..3 on forked streams
    for (int g = 1; g < NGRP; g++) {
        cudaStreamWaitEvent(s_st[g - 1], s_evRoot, 0);
        chain(g, s_st[g - 1]);
        cudaEventRecord(s_evDone[g - 1], s_st[g - 1]);
    }

    // join all branches back to the origin stream
    for (int g = 0; g < NGRP - 1; g++)
        cudaStreamWaitEvent(0, s_evDone[g], 0);
}